// round 1
// baseline (speedup 1.0000x reference)
#include <cuda_runtime.h>
#include <math.h>

// ---------------------------------------------------------------------------
// Problem constants
//   x:(8,32,32,768)  qkv_w:(2304,768)  qkv_b:(2304)
//   proj_w:(768,768) proj_b:(768)  rel_pos_h/w:(63,64)
//   NH=12 HD=64 S=1024 B*NH=96, out:(8,32,32,768) fp32
// ---------------------------------------------------------------------------
namespace {
constexpr int kHD = 64;
constexpr int kS  = 1024;
constexpr int kBH = 96;     // B*NH
}

// Scratch (static __device__ arrays: allocation-free per harness rules)
__device__ float g_q[kBH * kS * kHD];
__device__ float g_k[kBH * kS * kHD];
__device__ float g_v[kBH * kS * kHD];
__device__ float g_relh[kBH * 32 * 32 * 32];
__device__ float g_relw[kBH * 32 * 32 * 32];
__device__ float g_o[kBH * kS * kHD];

// ---------------------------------------------------------------------------
// Kernel 1: qkv = x @ qkv_w^T + qkv_b, scattered into q/k/v  (M=8192,N=2304,K=768)
// 128x128 block tile, 16 k-slice, 8x8 per thread, 256 threads.
// ---------------------------------------------------------------------------
__global__ __launch_bounds__(256) void qkv_gemm_kernel(
    const float* __restrict__ X, const float* __restrict__ W,
    const float* __restrict__ bias) {
  __shared__ float As[16][128];
  __shared__ float Bs[16][128];
  const int bn = blockIdx.x;          // 0..17
  const int bm = blockIdx.y;          // 0..63
  const int tid = threadIdx.x;
  const int tx = tid & 15, ty = tid >> 4;
  const int lrow = tid >> 2;          // 0..63
  const int lcol = (tid & 3) << 2;    // 0,4,8,12

  const float* Abase = X + (size_t)(bm * 128 + lrow) * 768 + lcol;
  const float* Bbase = W + (size_t)(bn * 128 + lrow) * 768 + lcol;

  float acc[8][8];
#pragma unroll
  for (int i = 0; i < 8; i++)
#pragma unroll
    for (int j = 0; j < 8; j++) acc[i][j] = 0.f;

  for (int kt = 0; kt < 768; kt += 16) {
    float4 a0 = *(const float4*)(Abase + kt);
    float4 a1 = *(const float4*)(Abase + kt + (size_t)64 * 768);
    float4 b0 = *(const float4*)(Bbase + kt);
    float4 b1 = *(const float4*)(Bbase + kt + (size_t)64 * 768);
    __syncthreads();
    As[lcol + 0][lrow] = a0.x; As[lcol + 1][lrow] = a0.y;
    As[lcol + 2][lrow] = a0.z; As[lcol + 3][lrow] = a0.w;
    As[lcol + 0][lrow + 64] = a1.x; As[lcol + 1][lrow + 64] = a1.y;
    As[lcol + 2][lrow + 64] = a1.z; As[lcol + 3][lrow + 64] = a1.w;
    Bs[lcol + 0][lrow] = b0.x; Bs[lcol + 1][lrow] = b0.y;
    Bs[lcol + 2][lrow] = b0.z; Bs[lcol + 3][lrow] = b0.w;
    Bs[lcol + 0][lrow + 64] = b1.x; Bs[lcol + 1][lrow + 64] = b1.y;
    Bs[lcol + 2][lrow + 64] = b1.z; Bs[lcol + 3][lrow + 64] = b1.w;
    __syncthreads();
#pragma unroll
    for (int kk = 0; kk < 16; kk++) {
      float4 aA = *(const float4*)&As[kk][ty * 4];
      float4 aB = *(const float4*)&As[kk][ty * 4 + 64];
      float4 bA = *(const float4*)&Bs[kk][tx * 4];
      float4 bB = *(const float4*)&Bs[kk][tx * 4 + 64];
      float am[8] = {aA.x, aA.y, aA.z, aA.w, aB.x, aB.y, aB.z, aB.w};
      float bb[8] = {bA.x, bA.y, bA.z, bA.w, bB.x, bB.y, bB.z, bB.w};
#pragma unroll
      for (int i = 0; i < 8; i++)
#pragma unroll
        for (int j = 0; j < 8; j++) acc[i][j] += am[i] * bb[j];
    }
  }

  // Epilogue: n = part*768 + head*64 + d ; m = b*1024 + s
#pragma unroll
  for (int i = 0; i < 8; i++) {
    int m = bm * 128 + ((i < 4) ? (ty * 4 + i) : (64 + ty * 4 + i - 4));
    int b = m >> 10, s = m & 1023;
#pragma unroll
    for (int jg = 0; jg < 2; jg++) {
      int n0 = bn * 128 + jg * 64 + tx * 4;
      int part = n0 / 768;
      int rem = n0 - part * 768;
      int head = rem >> 6;
      int d = rem & 63;
      float* dst = (part == 0) ? g_q : ((part == 1) ? g_k : g_v);
      size_t off = ((size_t)(b * 12 + head) * 1024 + s) * 64 + d;
      float4 bv = *(const float4*)&bias[n0];
      float4 v;
      v.x = acc[i][jg * 4 + 0] + bv.x;
      v.y = acc[i][jg * 4 + 1] + bv.y;
      v.z = acc[i][jg * 4 + 2] + bv.z;
      v.w = acc[i][jg * 4 + 3] + bv.w;
      *(float4*)(dst + off) = v;
    }
  }
}

// ---------------------------------------------------------------------------
// Kernel 2: decomposed rel-pos bias tables.
//   relh[bh,h,w,kh] = q[bh,h,w,:] . rel_pos_h[h-kh+31]
//   relw[bh,h,w,kw] = q[bh,h,w,:] . rel_pos_w[w-kw+31]
// One block per (h, bh). 256 threads.
// ---------------------------------------------------------------------------
__global__ __launch_bounds__(256) void relbias_kernel(
    const float* __restrict__ rph, const float* __restrict__ rpw) {
  __shared__ float Qs[32][64];
  __shared__ float Rhs[32][64];   // rows h..h+31 of rel_pos_h
  __shared__ float Rws[63][64];   // full rel_pos_w
  const int h = blockIdx.x;   // 0..31
  const int bh = blockIdx.y;  // 0..95
  const int tid = threadIdx.x;

  for (int idx = tid; idx < 32 * 16; idx += 256) {
    int w = idx >> 4, c4 = (idx & 15) << 2;
    *(float4*)&Qs[w][c4] =
        *(const float4*)&g_q[((size_t)bh * 1024 + h * 32 + w) * 64 + c4];
    *(float4*)&Rhs[w][c4] = *(const float4*)&rph[(h + w) * 64 + c4];
  }
  for (int idx = tid; idx < 63 * 16; idx += 256) {
    int r = idx >> 4, c4 = (idx & 15) << 2;
    *(float4*)&Rws[r][c4] = *(const float4*)&rpw[r * 64 + c4];
  }
  __syncthreads();

  const int w = tid >> 3;            // 0..31
  const int k0 = (tid & 7) << 2;     // 0,4,...,28
  float ah[4] = {0, 0, 0, 0}, aw[4] = {0, 0, 0, 0};
#pragma unroll
  for (int d4 = 0; d4 < 64; d4 += 4) {
    float4 qv = *(const float4*)&Qs[w][d4];
#pragma unroll
    for (int j = 0; j < 4; j++) {
      float4 rh = *(const float4*)&Rhs[31 - (k0 + j)][d4];
      ah[j] += qv.x * rh.x + qv.y * rh.y + qv.z * rh.z + qv.w * rh.w;
      float4 rw = *(const float4*)&Rws[w - (k0 + j) + 31][d4];
      aw[j] += qv.x * rw.x + qv.y * rw.y + qv.z * rw.z + qv.w * rw.w;
    }
  }
  size_t ob = (((size_t)bh * 32 + h) * 32 + w) * 32 + k0;
#pragma unroll
  for (int j = 0; j < 4; j++) {
    g_relh[ob + j] = ah[j];
    g_relw[ob + j] = aw[j];
  }
}

// ---------------------------------------------------------------------------
// Kernel 3: flash attention, 64x64 tiles, online softmax.
// Grid (16 q-tiles, 96 heads), 256 threads (16x16), 4x4 scores/thread.
// P tile reuses the K smem buffer. rel_w bias lives in registers.
// ---------------------------------------------------------------------------
#define ATT_SMEM_FLOATS (3 * 64 * 68 + 64 * 32)
#define ATT_SMEM_BYTES (ATT_SMEM_FLOATS * 4)

__global__ __launch_bounds__(256) void attn_kernel() {
  extern __shared__ float sm[];
  float* Qs  = sm;                  // [64][68]
  float* KPs = Qs + 64 * 68;        // [64][68] (K, then reused for P)
  float* Vs  = KPs + 64 * 68;       // [64][68]
  float* Bhs = Vs + 64 * 68;        // [64][32]

  const int bh = blockIdx.y;
  const int q0 = blockIdx.x * 64;
  const int tid = threadIdx.x;
  const int tx = tid & 15, ty = tid >> 4;
  const float scale = 0.125f;       // 64^-0.5

  for (int idx = tid; idx < 64 * 16; idx += 256) {
    int r = idx >> 4, c4 = (idx & 15) << 2;
    *(float4*)&Qs[r * 68 + c4] =
        *(const float4*)&g_q[((size_t)bh * 1024 + q0 + r) * 64 + c4];
  }
  for (int idx = tid; idx < 64 * 8; idx += 256) {
    int r = idx >> 3, k4 = (idx & 7) << 2;
    int s = q0 + r;
    *(float4*)&Bhs[r * 32 + k4] = *(const float4*)
        &g_relh[(((size_t)bh * 32 + (s >> 5)) * 32 + (s & 31)) * 32 + k4];
  }
  float bw[4][2];
#pragma unroll
  for (int i = 0; i < 4; i++) {
    int s = q0 + ty + 16 * i;
    const float* src =
        &g_relw[(((size_t)bh * 32 + (s >> 5)) * 32 + (s & 31)) * 32];
    bw[i][0] = src[tx];
    bw[i][1] = src[tx + 16];
  }

  float mrow[4], lrow[4], o[4][4];
#pragma unroll
  for (int i = 0; i < 4; i++) {
    mrow[i] = -INFINITY;
    lrow[i] = 0.f;
#pragma unroll
    for (int j = 0; j < 4; j++) o[i][j] = 0.f;
  }

  for (int n = 0; n < 16; n++) {
    __syncthreads();
    for (int idx = tid; idx < 64 * 16; idx += 256) {
      int r = idx >> 4, c4 = (idx & 15) << 2;
      size_t g = ((size_t)bh * 1024 + n * 64 + r) * 64 + c4;
      *(float4*)&KPs[r * 68 + c4] = *(const float4*)&g_k[g];
      *(float4*)&Vs[r * 68 + c4] = *(const float4*)&g_v[g];
    }
    __syncthreads();

    float sc[4][4];
#pragma unroll
    for (int i = 0; i < 4; i++)
#pragma unroll
      for (int j = 0; j < 4; j++) sc[i][j] = 0.f;

#pragma unroll
    for (int d4 = 0; d4 < 64; d4 += 4) {
      float4 qf[4], kf[4];
#pragma unroll
      for (int i = 0; i < 4; i++)
        qf[i] = *(const float4*)&Qs[(ty + 16 * i) * 68 + d4];
#pragma unroll
      for (int j = 0; j < 4; j++)
        kf[j] = *(const float4*)&KPs[(tx + 16 * j) * 68 + d4];
#pragma unroll
      for (int i = 0; i < 4; i++)
#pragma unroll
        for (int j = 0; j < 4; j++)
          sc[i][j] += qf[i].x * kf[j].x + qf[i].y * kf[j].y +
                      qf[i].z * kf[j].z + qf[i].w * kf[j].w;
    }

    // logits + bias + online softmax (rows = ty+16i; reduce across tx half-warp)
    float p[4][4];
#pragma unroll
    for (int i = 0; i < 4; i++) {
      int r = ty + 16 * i;
      float bh0 = Bhs[r * 32 + 2 * n];
      float bh1 = Bhs[r * 32 + 2 * n + 1];
      float mx = -INFINITY;
#pragma unroll
      for (int j = 0; j < 4; j++) {
        float l = sc[i][j] * scale + ((j < 2) ? bh0 : bh1) + bw[i][j & 1];
        sc[i][j] = l;
        mx = fmaxf(mx, l);
      }
#pragma unroll
      for (int msk = 1; msk < 16; msk <<= 1)
        mx = fmaxf(mx, __shfl_xor_sync(0xffffffffu, mx, msk));
      float mnew = fmaxf(mrow[i], mx);
      float alpha = __expf(mrow[i] - mnew);
      float sum = 0.f;
#pragma unroll
      for (int j = 0; j < 4; j++) {
        p[i][j] = __expf(sc[i][j] - mnew);
        sum += p[i][j];
      }
#pragma unroll
      for (int msk = 1; msk < 16; msk <<= 1)
        sum += __shfl_xor_sync(0xffffffffu, sum, msk);
      lrow[i] = lrow[i] * alpha + sum;
      mrow[i] = mnew;
#pragma unroll
      for (int j = 0; j < 4; j++) o[i][j] *= alpha;
    }

    __syncthreads();  // everyone finished reading K
#pragma unroll
    for (int i = 0; i < 4; i++)
#pragma unroll
      for (int j = 0; j < 4; j++)
        KPs[(ty + 16 * i) * 68 + tx + 16 * j] = p[i][j];
    __syncthreads();

    // O += P @ V  (d column = tx + 16j)
#pragma unroll
    for (int c4 = 0; c4 < 64; c4 += 4) {
      float4 pf[4];
#pragma unroll
      for (int i = 0; i < 4; i++)
        pf[i] = *(const float4*)&KPs[(ty + 16 * i) * 68 + c4];
#pragma unroll
      for (int cc = 0; cc < 4; cc++) {
        float vv[4];
#pragma unroll
        for (int j = 0; j < 4; j++)
          vv[j] = Vs[(c4 + cc) * 68 + tx + 16 * j];
        const float pr[4] = {pf[0].x, pf[1].x, pf[2].x, pf[3].x};
        const float pg[4] = {pf[0].y, pf[1].y, pf[2].y, pf[3].y};
        const float pb[4] = {pf[0].z, pf[1].z, pf[2].z, pf[3].z};
        const float pa[4] = {pf[0].w, pf[1].w, pf[2].w, pf[3].w};
        const float* psel = (cc == 0) ? pr : (cc == 1) ? pg : (cc == 2) ? pb : pa;
#pragma unroll
        for (int i = 0; i < 4; i++)
#pragma unroll
          for (int j = 0; j < 4; j++) o[i][j] += psel[i] * vv[j];
      }
    }
  }

#pragma unroll
  for (int i = 0; i < 4; i++) {
    float inv = 1.f / lrow[i];
    int r = ty + 16 * i;
#pragma unroll
    for (int j = 0; j < 4; j++)
      g_o[((size_t)bh * 1024 + q0 + r) * 64 + tx + 16 * j] = o[i][j] * inv;
  }
}

// ---------------------------------------------------------------------------
// Kernel 4: out = attn_out(head-interleaved) @ proj_w^T + proj_b
// M=8192, N=768, K=768. Same tiling as kernel 1; A remapped from g_o.
// ---------------------------------------------------------------------------
__global__ __launch_bounds__(256) void proj_gemm_kernel(
    const float* __restrict__ W, const float* __restrict__ bias,
    float* __restrict__ out) {
  __shared__ float As[16][128];
  __shared__ float Bs[16][128];
  const int bn = blockIdx.x;          // 0..5
  const int bm = blockIdx.y;          // 0..63
  const int tid = threadIdx.x;
  const int tx = tid & 15, ty = tid >> 4;
  const int lrow = tid >> 2;
  const int lcol = (tid & 3) << 2;

  const int m0 = bm * 128 + lrow;
  const int m1 = m0 + 64;
  const int b0 = m0 >> 10, s0 = m0 & 1023;
  const int b1 = m1 >> 10, s1 = m1 & 1023;
  const float* Bbase = W + (size_t)(bn * 128 + lrow) * 768 + lcol;

  float acc[8][8];
#pragma unroll
  for (int i = 0; i < 8; i++)
#pragma unroll
    for (int j = 0; j < 8; j++) acc[i][j] = 0.f;

  for (int kt = 0; kt < 768; kt += 16) {
    int k0 = kt + lcol;
    int head = k0 >> 6, d = k0 & 63;
    float4 a0 = *(const float4*)
        &g_o[((size_t)(b0 * 12 + head) * 1024 + s0) * 64 + d];
    float4 a1 = *(const float4*)
        &g_o[((size_t)(b1 * 12 + head) * 1024 + s1) * 64 + d];
    float4 bb0 = *(const float4*)(Bbase + kt);
    float4 bb1 = *(const float4*)(Bbase + kt + (size_t)64 * 768);
    __syncthreads();
    As[lcol + 0][lrow] = a0.x; As[lcol + 1][lrow] = a0.y;
    As[lcol + 2][lrow] = a0.z; As[lcol + 3][lrow] = a0.w;
    As[lcol + 0][lrow + 64] = a1.x; As[lcol + 1][lrow + 64] = a1.y;
    As[lcol + 2][lrow + 64] = a1.z; As[lcol + 3][lrow + 64] = a1.w;
    Bs[lcol + 0][lrow] = bb0.x; Bs[lcol + 1][lrow] = bb0.y;
    Bs[lcol + 2][lrow] = bb0.z; Bs[lcol + 3][lrow] = bb0.w;
    Bs[lcol + 0][lrow + 64] = bb1.x; Bs[lcol + 1][lrow + 64] = bb1.y;
    Bs[lcol + 2][lrow + 64] = bb1.z; Bs[lcol + 3][lrow + 64] = bb1.w;
    __syncthreads();
#pragma unroll
    for (int kk = 0; kk < 16; kk++) {
      float4 aA = *(const float4*)&As[kk][ty * 4];
      float4 aB = *(const float4*)&As[kk][ty * 4 + 64];
      float4 bA = *(const float4*)&Bs[kk][tx * 4];
      float4 bB = *(const float4*)&Bs[kk][tx * 4 + 64];
      float am[8] = {aA.x, aA.y, aA.z, aA.w, aB.x, aB.y, aB.z, aB.w};
      float bb[8] = {bA.x, bA.y, bA.z, bA.w, bB.x, bB.y, bB.z, bB.w};
#pragma unroll
      for (int i = 0; i < 8; i++)
#pragma unroll
        for (int j = 0; j < 8; j++) acc[i][j] += am[i] * bb[j];
    }
  }

#pragma unroll
  for (int i = 0; i < 8; i++) {
    int m = bm * 128 + ((i < 4) ? (ty * 4 + i) : (64 + ty * 4 + i - 4));
#pragma unroll
    for (int jg = 0; jg < 2; jg++) {
      int n0 = bn * 128 + jg * 64 + tx * 4;
      float4 bv = *(const float4*)&bias[n0];
      float4 v;
      v.x = acc[i][jg * 4 + 0] + bv.x;
      v.y = acc[i][jg * 4 + 1] + bv.y;
      v.z = acc[i][jg * 4 + 2] + bv.z;
      v.w = acc[i][jg * 4 + 3] + bv.w;
      *(float4*)&out[(size_t)m * 768 + n0] = v;
    }
  }
}

// ---------------------------------------------------------------------------
extern "C" void kernel_launch(void* const* d_in, const int* in_sizes, int n_in,
                              void* d_out, int out_size) {
  const float* x      = (const float*)d_in[0];
  const float* qkv_w  = (const float*)d_in[1];
  const float* qkv_b  = (const float*)d_in[2];
  const float* proj_w = (const float*)d_in[3];
  const float* proj_b = (const float*)d_in[4];
  const float* rph    = (const float*)d_in[5];
  const float* rpw    = (const float*)d_in[6];
  float* out = (float*)d_out;

  cudaFuncSetAttribute(attn_kernel, cudaFuncAttributeMaxDynamicSharedMemorySize,
                       ATT_SMEM_BYTES);

  qkv_gemm_kernel<<<dim3(18, 64), 256>>>(x, qkv_w, qkv_b);
  relbias_kernel<<<dim3(32, 96), 256>>>(rph, rpw);
  attn_kernel<<<dim3(16, 96), 256, ATT_SMEM_BYTES>>>();
  proj_gemm_kernel<<<dim3(6, 64), 256>>>(proj_w, proj_b, out);
}

// round 3
// speedup vs baseline: 1.3093x; 1.3093x over previous
#include <cuda_runtime.h>
#include <cuda_bf16.h>
#include <math.h>
#include <cstdint>

// ---------------------------------------------------------------------------
// Problem constants
//   x:(8,32,32,768)  qkv_w:(2304,768)  qkv_b:(2304)
//   proj_w:(768,768) proj_b:(768)  rel_pos_h/w:(63,64)
//   NH=12 HD=64 S=1024 B*NH=96, out:(8,32,32,768) fp32
// ---------------------------------------------------------------------------
namespace {
constexpr int kHD = 64;
constexpr int kS  = 1024;
constexpr int kBH = 96;
}

// Scratch (__device__ globals: allocation-free per harness rules)
__device__ float g_q[kBH * kS * kHD];
__device__ float g_k[kBH * kS * kHD];
__device__ float g_v[kBH * kS * kHD];
__device__ float g_relh[kBH * 32 * 32 * 32];
__device__ float g_relw[kBH * 32 * 32 * 32];
__device__ float g_o[kBH * kS * kHD];

// bf16 split operands for tensor-core GEMMs
__device__ __nv_bfloat16 g_xhi[8192 * 768];
__device__ __nv_bfloat16 g_xlo[8192 * 768];
__device__ __nv_bfloat16 g_wqkv_hi[2304 * 768];
__device__ __nv_bfloat16 g_wqkv_lo[2304 * 768];
__device__ __nv_bfloat16 g_ohi[8192 * 768];
__device__ __nv_bfloat16 g_olo[8192 * 768];
__device__ __nv_bfloat16 g_wproj_hi[768 * 768];
__device__ __nv_bfloat16 g_wproj_lo[768 * 768];

// ---------------------------------------------------------------------------
// mma.sync helper: D(16x8,f32) += A(16x16,bf16,row) * B(16x8,bf16,col)
// ---------------------------------------------------------------------------
__device__ __forceinline__ void mma16816(float* c, const uint32_t* a,
                                         const uint32_t* b) {
  asm volatile(
      "mma.sync.aligned.m16n8k16.row.col.f32.bf16.bf16.f32 "
      "{%0,%1,%2,%3}, {%4,%5,%6,%7}, {%8,%9}, {%0,%1,%2,%3};"
      : "+f"(c[0]), "+f"(c[1]), "+f"(c[2]), "+f"(c[3])
      : "r"(a[0]), "r"(a[1]), "r"(a[2]), "r"(a[3]), "r"(b[0]), "r"(b[1]));
}

// ---------------------------------------------------------------------------
// fp32 -> bf16 hi/lo split (contiguous)
// ---------------------------------------------------------------------------
__global__ __launch_bounds__(256) void split2_kernel(
    const float* __restrict__ src, __nv_bfloat16* __restrict__ hi,
    __nv_bfloat16* __restrict__ lo, int n4) {
  int i = blockIdx.x * 256 + threadIdx.x;
  if (i >= n4) return;
  float4 f = ((const float4*)src)[i];
  __nv_bfloat16 h0 = __float2bfloat16(f.x), h1 = __float2bfloat16(f.y);
  __nv_bfloat16 h2 = __float2bfloat16(f.z), h3 = __float2bfloat16(f.w);
  __nv_bfloat16 l0 = __float2bfloat16(f.x - __bfloat162float(h0));
  __nv_bfloat16 l1 = __float2bfloat16(f.y - __bfloat162float(h1));
  __nv_bfloat16 l2 = __float2bfloat16(f.z - __bfloat162float(h2));
  __nv_bfloat16 l3 = __float2bfloat16(f.w - __bfloat162float(h3));
  __nv_bfloat162 ha(h0, h1), hb(h2, h3), la(l0, l1), lb(l2, l3);
  uint2 uh, ul;
  uh.x = *(uint32_t*)&ha; uh.y = *(uint32_t*)&hb;
  ul.x = *(uint32_t*)&la; ul.y = *(uint32_t*)&lb;
  ((uint2*)hi)[i] = uh;
  ((uint2*)lo)[i] = ul;
}

// g_o (head-interleaved) -> row-major [8192,768] bf16 hi/lo for proj GEMM
__global__ __launch_bounds__(256) void split_o_kernel(
    __nv_bfloat16* __restrict__ hi, __nv_bfloat16* __restrict__ lo) {
  int e = blockIdx.x * 256 + threadIdx.x;  // over 8192*192
  if (e >= 8192 * 192) return;
  int m = e / 192, kq = (e - m * 192) * 4;
  int head = kq >> 6, d = kq & 63;
  int b = m >> 10, s = m & 1023;
  float4 f = *(const float4*)&g_o[((size_t)(b * 12 + head) * 1024 + s) * 64 + d];
  __nv_bfloat16 h0 = __float2bfloat16(f.x), h1 = __float2bfloat16(f.y);
  __nv_bfloat16 h2 = __float2bfloat16(f.z), h3 = __float2bfloat16(f.w);
  __nv_bfloat16 l0 = __float2bfloat16(f.x - __bfloat162float(h0));
  __nv_bfloat16 l1 = __float2bfloat16(f.y - __bfloat162float(h1));
  __nv_bfloat16 l2 = __float2bfloat16(f.z - __bfloat162float(h2));
  __nv_bfloat16 l3 = __float2bfloat16(f.w - __bfloat162float(h3));
  __nv_bfloat162 ha(h0, h1), hb(h2, h3), la(l0, l1), lb(l2, l3);
  uint2 uh, ul;
  uh.x = *(uint32_t*)&ha; uh.y = *(uint32_t*)&hb;
  ul.x = *(uint32_t*)&la; ul.y = *(uint32_t*)&lb;
  *(uint2*)(hi + (size_t)m * 768 + kq) = uh;
  *(uint2*)(lo + (size_t)m * 768 + kq) = ul;
}

// ---------------------------------------------------------------------------
// HMMA GEMM: C[128,128] = Ahi*Bhi + Ahi*Blo + Alo*Bhi  (K=768, fp32 acc)
// A row-major [M,768], B n-major [N,768] (i.e. W[n][k]) -> C = A * W^T.
// 256 threads = 8 warps (2 m x 4 n), warp tile 64x32, BK=32.
// All fragments are plain 4B LDS loads (consecutive-k pairs); smem stride
// 40 bf16 (80B) makes fragment loads bank-conflict-free.
// MODE 0: qkv epilogue (scatter into g_q/g_k/g_v + bias)
// MODE 1: proj epilogue (row-major out + bias)
// ---------------------------------------------------------------------------
#define SSTR 40  // smem k-stride in bf16 units

template <int MODE>
__global__ __launch_bounds__(256) void hmma_gemm_kernel(
    const __nv_bfloat16* __restrict__ Ahi, const __nv_bfloat16* __restrict__ Alo,
    const __nv_bfloat16* __restrict__ Bhi, const __nv_bfloat16* __restrict__ Blo,
    const float* __restrict__ bias, float* __restrict__ out) {
  __shared__ __nv_bfloat16 sAhi[128 * SSTR];
  __shared__ __nv_bfloat16 sAlo[128 * SSTR];
  __shared__ __nv_bfloat16 sBhi[128 * SSTR];
  __shared__ __nv_bfloat16 sBlo[128 * SSTR];

  const int tid = threadIdx.x;
  const int wid = tid >> 5, lane = tid & 31;
  const int wm = wid & 1;    // m half  (0..1) -> rows wm*64..+64
  const int wn = wid >> 1;   // n quarter (0..3) -> cols wn*32..+32
  const int g = lane >> 2, t = lane & 3;
  const int bn = blockIdx.x, bm = blockIdx.y;
  const int arow0 = bm * 128, brow0 = bn * 128;

  float acc[4][4][4];
#pragma unroll
  for (int mi = 0; mi < 4; mi++)
#pragma unroll
    for (int ni = 0; ni < 4; ni++)
#pragma unroll
      for (int r = 0; r < 4; r++) acc[mi][ni][r] = 0.f;

  for (int kt = 0; kt < 768; kt += 32) {
    __syncthreads();
    // load 4 tiles of [128 rows x 32 bf16]; 16B chunks, 512 per tile
    for (int c = tid; c < 512; c += 256) {
      int row = c >> 2, q = c & 3;  // q*8 bf16 within row
      size_t ga = (size_t)(arow0 + row) * 768 + kt + q * 8;
      size_t gb = (size_t)(brow0 + row) * 768 + kt + q * 8;
      int so = row * SSTR + q * 8;
      *(uint4*)&sAhi[so] = *(const uint4*)(Ahi + ga);
      *(uint4*)&sAlo[so] = *(const uint4*)(Alo + ga);
      *(uint4*)&sBhi[so] = *(const uint4*)(Bhi + gb);
      *(uint4*)&sBlo[so] = *(const uint4*)(Blo + gb);
    }
    __syncthreads();

#pragma unroll
    for (int ks = 0; ks < 32; ks += 16) {
      uint32_t a[4][4], b[4][2];
      const int acol = ks + 2 * t;   // fragment k pair base
      // --- load A-hi fragments ---
#pragma unroll
      for (int mi = 0; mi < 4; mi++) {
        int r0 = (wm * 64 + mi * 16 + g) * SSTR;
        a[mi][0] = *(const uint32_t*)&sAhi[r0 + acol];
        a[mi][1] = *(const uint32_t*)&sAhi[r0 + 8 * SSTR + acol];
        a[mi][2] = *(const uint32_t*)&sAhi[r0 + acol + 8];
        a[mi][3] = *(const uint32_t*)&sAhi[r0 + 8 * SSTR + acol + 8];
      }
      // --- load B-hi fragments ---
#pragma unroll
      for (int ni = 0; ni < 4; ni++) {
        int r0 = (wn * 32 + ni * 8 + g) * SSTR;
        b[ni][0] = *(const uint32_t*)&sBhi[r0 + acol];
        b[ni][1] = *(const uint32_t*)&sBhi[r0 + acol + 8];
      }
#pragma unroll
      for (int mi = 0; mi < 4; mi++)
#pragma unroll
        for (int ni = 0; ni < 4; ni++) mma16816(acc[mi][ni], a[mi], b[ni]);
      // --- B-lo (reuse A-hi) ---
#pragma unroll
      for (int ni = 0; ni < 4; ni++) {
        int r0 = (wn * 32 + ni * 8 + g) * SSTR;
        b[ni][0] = *(const uint32_t*)&sBlo[r0 + acol];
        b[ni][1] = *(const uint32_t*)&sBlo[r0 + acol + 8];
      }
#pragma unroll
      for (int mi = 0; mi < 4; mi++)
#pragma unroll
        for (int ni = 0; ni < 4; ni++) mma16816(acc[mi][ni], a[mi], b[ni]);
      // --- A-lo x B-hi ---
#pragma unroll
      for (int mi = 0; mi < 4; mi++) {
        int r0 = (wm * 64 + mi * 16 + g) * SSTR;
        a[mi][0] = *(const uint32_t*)&sAlo[r0 + acol];
        a[mi][1] = *(const uint32_t*)&sAlo[r0 + 8 * SSTR + acol];
        a[mi][2] = *(const uint32_t*)&sAlo[r0 + acol + 8];
        a[mi][3] = *(const uint32_t*)&sAlo[r0 + 8 * SSTR + acol + 8];
      }
#pragma unroll
      for (int ni = 0; ni < 4; ni++) {
        int r0 = (wn * 32 + ni * 8 + g) * SSTR;
        b[ni][0] = *(const uint32_t*)&sBhi[r0 + acol];
        b[ni][1] = *(const uint32_t*)&sBhi[r0 + acol + 8];
      }
#pragma unroll
      for (int mi = 0; mi < 4; mi++)
#pragma unroll
        for (int ni = 0; ni < 4; ni++) mma16816(acc[mi][ni], a[mi], b[ni]);
    }
  }

  // Epilogue. C frag: c0,c1 -> (row g, cols 2t,2t+1); c2,c3 -> row g+8.
#pragma unroll
  for (int mi = 0; mi < 4; mi++) {
#pragma unroll
    for (int ni = 0; ni < 4; ni++) {
      int n = bn * 128 + wn * 32 + ni * 8 + 2 * t;
      float b0 = bias[n], b1 = bias[n + 1];
#pragma unroll
      for (int half = 0; half < 2; half++) {
        int m = bm * 128 + wm * 64 + mi * 16 + g + half * 8;
        float2 v;
        v.x = acc[mi][ni][half * 2 + 0] + b0;
        v.y = acc[mi][ni][half * 2 + 1] + b1;
        if (MODE == 0) {
          int part = n / 768;
          int rem = n - part * 768;
          int head = rem >> 6, d = rem & 63;
          int bb = m >> 10, s = m & 1023;
          float* dst = (part == 0) ? g_q : (part == 1) ? g_k : g_v;
          *(float2*)(dst + ((size_t)(bb * 12 + head) * 1024 + s) * 64 + d) = v;
        } else {
          *(float2*)(out + (size_t)m * 768 + n) = v;
        }
      }
    }
  }
}

// ---------------------------------------------------------------------------
// Kernel 2: decomposed rel-pos bias tables (unchanged from R1)
// ---------------------------------------------------------------------------
__global__ __launch_bounds__(256) void relbias_kernel(
    const float* __restrict__ rph, const float* __restrict__ rpw) {
  __shared__ float Qs[32][64];
  __shared__ float Rhs[32][64];
  __shared__ float Rws[63][64];
  const int h = blockIdx.x;
  const int bh = blockIdx.y;
  const int tid = threadIdx.x;

  for (int idx = tid; idx < 32 * 16; idx += 256) {
    int w = idx >> 4, c4 = (idx & 15) << 2;
    *(float4*)&Qs[w][c4] =
        *(const float4*)&g_q[((size_t)bh * 1024 + h * 32 + w) * 64 + c4];
    *(float4*)&Rhs[w][c4] = *(const float4*)&rph[(h + w) * 64 + c4];
  }
  for (int idx = tid; idx < 63 * 16; idx += 256) {
    int r = idx >> 4, c4 = (idx & 15) << 2;
    *(float4*)&Rws[r][c4] = *(const float4*)&rpw[r * 64 + c4];
  }
  __syncthreads();

  const int w = tid >> 3;
  const int k0 = (tid & 7) << 2;
  float ah[4] = {0, 0, 0, 0}, aw[4] = {0, 0, 0, 0};
#pragma unroll
  for (int d4 = 0; d4 < 64; d4 += 4) {
    float4 qv = *(const float4*)&Qs[w][d4];
#pragma unroll
    for (int j = 0; j < 4; j++) {
      float4 rh = *(const float4*)&Rhs[31 - (k0 + j)][d4];
      ah[j] += qv.x * rh.x + qv.y * rh.y + qv.z * rh.z + qv.w * rh.w;
      float4 rw = *(const float4*)&Rws[w - (k0 + j) + 31][d4];
      aw[j] += qv.x * rw.x + qv.y * rw.y + qv.z * rw.z + qv.w * rw.w;
    }
  }
  size_t ob = (((size_t)bh * 32 + h) * 32 + w) * 32 + k0;
#pragma unroll
  for (int j = 0; j < 4; j++) {
    g_relh[ob + j] = ah[j];
    g_relw[ob + j] = aw[j];
  }
}

// ---------------------------------------------------------------------------
// Kernel 3: flash attention (unchanged from R1)
// ---------------------------------------------------------------------------
#define ATT_SMEM_FLOATS (3 * 64 * 68 + 64 * 32)
#define ATT_SMEM_BYTES (ATT_SMEM_FLOATS * 4)

__global__ __launch_bounds__(256) void attn_kernel() {
  extern __shared__ float smf[];
  float* Qs  = smf;
  float* KPs = Qs + 64 * 68;
  float* Vs  = KPs + 64 * 68;
  float* Bhs = Vs + 64 * 68;

  const int bh = blockIdx.y;
  const int q0 = blockIdx.x * 64;
  const int tid = threadIdx.x;
  const int tx = tid & 15, ty = tid >> 4;
  const float scale = 0.125f;

  for (int idx = tid; idx < 64 * 16; idx += 256) {
    int r = idx >> 4, c4 = (idx & 15) << 2;
    *(float4*)&Qs[r * 68 + c4] =
        *(const float4*)&g_q[((size_t)bh * 1024 + q0 + r) * 64 + c4];
  }
  for (int idx = tid; idx < 64 * 8; idx += 256) {
    int r = idx >> 3, k4 = (idx & 7) << 2;
    int s = q0 + r;
    *(float4*)&Bhs[r * 32 + k4] = *(const float4*)
        &g_relh[(((size_t)bh * 32 + (s >> 5)) * 32 + (s & 31)) * 32 + k4];
  }
  float bw[4][2];
#pragma unroll
  for (int i = 0; i < 4; i++) {
    int s = q0 + ty + 16 * i;
    const float* src =
        &g_relw[(((size_t)bh * 32 + (s >> 5)) * 32 + (s & 31)) * 32];
    bw[i][0] = src[tx];
    bw[i][1] = src[tx + 16];
  }

  float mrow[4], lrow[4], o[4][4];
#pragma unroll
  for (int i = 0; i < 4; i++) {
    mrow[i] = -INFINITY;
    lrow[i] = 0.f;
#pragma unroll
    for (int j = 0; j < 4; j++) o[i][j] = 0.f;
  }

  for (int n = 0; n < 16; n++) {
    __syncthreads();
    for (int idx = tid; idx < 64 * 16; idx += 256) {
      int r = idx >> 4, c4 = (idx & 15) << 2;
      size_t g = ((size_t)bh * 1024 + n * 64 + r) * 64 + c4;
      *(float4*)&KPs[r * 68 + c4] = *(const float4*)&g_k[g];
      *(float4*)&Vs[r * 68 + c4] = *(const float4*)&g_v[g];
    }
    __syncthreads();

    float sc[4][4];
#pragma unroll
    for (int i = 0; i < 4; i++)
#pragma unroll
      for (int j = 0; j < 4; j++) sc[i][j] = 0.f;

#pragma unroll
    for (int d4 = 0; d4 < 64; d4 += 4) {
      float4 qf[4], kf[4];
#pragma unroll
      for (int i = 0; i < 4; i++)
        qf[i] = *(const float4*)&Qs[(ty + 16 * i) * 68 + d4];
#pragma unroll
      for (int j = 0; j < 4; j++)
        kf[j] = *(const float4*)&KPs[(tx + 16 * j) * 68 + d4];
#pragma unroll
      for (int i = 0; i < 4; i++)
#pragma unroll
        for (int j = 0; j < 4; j++)
          sc[i][j] += qf[i].x * kf[j].x + qf[i].y * kf[j].y +
                      qf[i].z * kf[j].z + qf[i].w * kf[j].w;
    }

    float p[4][4];
#pragma unroll
    for (int i = 0; i < 4; i++) {
      int r = ty + 16 * i;
      float bh0 = Bhs[r * 32 + 2 * n];
      float bh1 = Bhs[r * 32 + 2 * n + 1];
      float mx = -INFINITY;
#pragma unroll
      for (int j = 0; j < 4; j++) {
        float l = sc[i][j] * scale + ((j < 2) ? bh0 : bh1) + bw[i][j & 1];
        sc[i][j] = l;
        mx = fmaxf(mx, l);
      }
#pragma unroll
      for (int msk = 1; msk < 16; msk <<= 1)
        mx = fmaxf(mx, __shfl_xor_sync(0xffffffffu, mx, msk));
      float mnew = fmaxf(mrow[i], mx);
      float alpha = __expf(mrow[i] - mnew);
      float sum = 0.f;
#pragma unroll
      for (int j = 0; j < 4; j++) {
        p[i][j] = __expf(sc[i][j] - mnew);
        sum += p[i][j];
      }
#pragma unroll
      for (int msk = 1; msk < 16; msk <<= 1)
        sum += __shfl_xor_sync(0xffffffffu, sum, msk);
      lrow[i] = lrow[i] * alpha + sum;
      mrow[i] = mnew;
#pragma unroll
      for (int j = 0; j < 4; j++) o[i][j] *= alpha;
    }

    __syncthreads();
#pragma unroll
    for (int i = 0; i < 4; i++)
#pragma unroll
      for (int j = 0; j < 4; j++)
        KPs[(ty + 16 * i) * 68 + tx + 16 * j] = p[i][j];
    __syncthreads();

#pragma unroll
    for (int c4 = 0; c4 < 64; c4 += 4) {
      float4 pf[4];
#pragma unroll
      for (int i = 0; i < 4; i++)
        pf[i] = *(const float4*)&KPs[(ty + 16 * i) * 68 + c4];
#pragma unroll
      for (int cc = 0; cc < 4; cc++) {
        float vv[4];
#pragma unroll
        for (int j = 0; j < 4; j++)
          vv[j] = Vs[(c4 + cc) * 68 + tx + 16 * j];
        const float pr[4] = {pf[0].x, pf[1].x, pf[2].x, pf[3].x};
        const float pg[4] = {pf[0].y, pf[1].y, pf[2].y, pf[3].y};
        const float pb[4] = {pf[0].z, pf[1].z, pf[2].z, pf[3].z};
        const float pa[4] = {pf[0].w, pf[1].w, pf[2].w, pf[3].w};
        const float* psel = (cc == 0) ? pr : (cc == 1) ? pg : (cc == 2) ? pb : pa;
#pragma unroll
        for (int i = 0; i < 4; i++)
#pragma unroll
          for (int j = 0; j < 4; j++) o[i][j] += psel[i] * vv[j];
      }
    }
  }

#pragma unroll
  for (int i = 0; i < 4; i++) {
    float inv = 1.f / lrow[i];
    int r = ty + 16 * i;
#pragma unroll
    for (int j = 0; j < 4; j++)
      g_o[((size_t)bh * 1024 + q0 + r) * 64 + tx + 16 * j] = o[i][j] * inv;
  }
}

// ---------------------------------------------------------------------------
extern "C" void kernel_launch(void* const* d_in, const int* in_sizes, int n_in,
                              void* d_out, int out_size) {
  const float* x      = (const float*)d_in[0];
  const float* qkv_w  = (const float*)d_in[1];
  const float* qkv_b  = (const float*)d_in[2];
  const float* proj_w = (const float*)d_in[3];
  const float* proj_b = (const float*)d_in[4];
  const float* rph    = (const float*)d_in[5];
  const float* rpw    = (const float*)d_in[6];
  float* out = (float*)d_out;

  cudaFuncSetAttribute(attn_kernel, cudaFuncAttributeMaxDynamicSharedMemorySize,
                       ATT_SMEM_BYTES);

  __nv_bfloat16 *xhi, *xlo, *whi, *wlo, *ohi, *olo, *phi, *plo;
  cudaGetSymbolAddress((void**)&xhi, g_xhi);
  cudaGetSymbolAddress((void**)&xlo, g_xlo);
  cudaGetSymbolAddress((void**)&whi, g_wqkv_hi);
  cudaGetSymbolAddress((void**)&wlo, g_wqkv_lo);
  cudaGetSymbolAddress((void**)&ohi, g_ohi);
  cudaGetSymbolAddress((void**)&olo, g_olo);
  cudaGetSymbolAddress((void**)&phi, g_wproj_hi);
  cudaGetSymbolAddress((void**)&plo, g_wproj_lo);

  split2_kernel<<<8192 * 768 / 4 / 256, 256>>>(x, xhi, xlo, 8192 * 768 / 4);
  split2_kernel<<<2304 * 768 / 4 / 256, 256>>>(qkv_w, whi, wlo, 2304 * 768 / 4);
  hmma_gemm_kernel<0><<<dim3(18, 64), 256>>>(xhi, xlo, whi, wlo, qkv_b,
                                             nullptr);
  relbias_kernel<<<dim3(32, 96), 256>>>(rph, rpw);
  attn_kernel<<<dim3(16, 96), 256, ATT_SMEM_BYTES>>>();
  split_o_kernel<<<(8192 * 192 + 255) / 256, 256>>>(ohi, olo);
  split2_kernel<<<768 * 768 / 4 / 256, 256>>>(proj_w, phi, plo, 768 * 768 / 4);
  hmma_gemm_kernel<1><<<dim3(6, 64), 256>>>(ohi, olo, phi, plo, proj_b, out);
}

// round 4
// speedup vs baseline: 2.5248x; 1.9283x over previous
#include <cuda_runtime.h>
#include <cuda_bf16.h>
#include <math.h>
#include <cstdint>

// ---------------------------------------------------------------------------
// Problem constants
//   x:(8,32,32,768)  qkv_w:(2304,768)  qkv_b:(2304)
//   proj_w:(768,768) proj_b:(768)  rel_pos_h/w:(63,64)
//   NH=12 HD=64 S=1024 B*NH=96, out:(8,32,32,768) fp32
// ---------------------------------------------------------------------------
namespace {
constexpr int kHD = 64;
constexpr int kS  = 1024;
constexpr int kBH = 96;
}

// Scratch (__device__ globals: allocation-free per harness rules)
__device__ float g_q[kBH * kS * kHD];          // fp32 q (relbias input)
__device__ float g_relh[kBH * 32 * 32 * 32];
__device__ float g_relw[kBH * 32 * 32 * 32];

// bf16 split operands
__device__ __nv_bfloat16 g_xhi[8192 * 768];
__device__ __nv_bfloat16 g_xlo[8192 * 768];
__device__ __nv_bfloat16 g_wqkv_hi[2304 * 768];
__device__ __nv_bfloat16 g_wqkv_lo[2304 * 768];
__device__ __nv_bfloat16 g_ohi[8192 * 768];
__device__ __nv_bfloat16 g_olo[8192 * 768];
__device__ __nv_bfloat16 g_wproj_hi[768 * 768];
__device__ __nv_bfloat16 g_wproj_lo[768 * 768];
// attention operands (written by qkv epilogue)
__device__ __nv_bfloat16 g_qhi[kBH * kS * kHD];  // pre-scaled by 0.125
__device__ __nv_bfloat16 g_qlo[kBH * kS * kHD];
__device__ __nv_bfloat16 g_khi[kBH * kS * kHD];
__device__ __nv_bfloat16 g_klo[kBH * kS * kHD];
__device__ __nv_bfloat16 g_vthi[kBH * kHD * kS];  // [bh][d][seq] transposed
__device__ __nv_bfloat16 g_vtlo[kBH * kHD * kS];

// ---------------------------------------------------------------------------
// mma.sync helper: D(16x8,f32) += A(16x16,bf16,row) * B(16x8,bf16,col)
// ---------------------------------------------------------------------------
__device__ __forceinline__ void mma16816(float* c, const uint32_t* a,
                                         const uint32_t* b) {
  asm volatile(
      "mma.sync.aligned.m16n8k16.row.col.f32.bf16.bf16.f32 "
      "{%0,%1,%2,%3}, {%4,%5,%6,%7}, {%8,%9}, {%0,%1,%2,%3};"
      : "+f"(c[0]), "+f"(c[1]), "+f"(c[2]), "+f"(c[3])
      : "r"(a[0]), "r"(a[1]), "r"(a[2]), "r"(a[3]), "r"(b[0]), "r"(b[1]));
}

__device__ __forceinline__ void split_pack(float x0, float x1, uint32_t& hi,
                                           uint32_t& lo) {
  __nv_bfloat16 h0 = __float2bfloat16(x0), h1 = __float2bfloat16(x1);
  __nv_bfloat162 hp(h0, h1);
  hi = *(uint32_t*)&hp;
  __nv_bfloat16 l0 = __float2bfloat16(x0 - __bfloat162float(h0));
  __nv_bfloat16 l1 = __float2bfloat16(x1 - __bfloat162float(h1));
  __nv_bfloat162 lp(l0, l1);
  lo = *(uint32_t*)&lp;
}

// ---------------------------------------------------------------------------
// fp32 -> bf16 hi/lo split (contiguous)
// ---------------------------------------------------------------------------
__global__ __launch_bounds__(256) void split2_kernel(
    const float* __restrict__ src, __nv_bfloat16* __restrict__ hi,
    __nv_bfloat16* __restrict__ lo, int n4) {
  int i = blockIdx.x * 256 + threadIdx.x;
  if (i >= n4) return;
  float4 f = ((const float4*)src)[i];
  uint2 uh, ul;
  split_pack(f.x, f.y, uh.x, ul.x);
  split_pack(f.z, f.w, uh.y, ul.y);
  ((uint2*)hi)[i] = uh;
  ((uint2*)lo)[i] = ul;
}

// ---------------------------------------------------------------------------
// HMMA GEMM: C[128,128] = Ahi*Bhi + Ahi*Blo + Alo*Bhi  (K=768, fp32 acc)
// 256 threads = 8 warps (2 m x 4 n), warp tile 64x32, BK=32.
// MODE 0: qkv epilogue (scatter q fp32 + q/k/v bf16 hi/lo, V transposed)
// MODE 1: proj epilogue (row-major fp32 out + bias)
// ---------------------------------------------------------------------------
#define SSTR 40  // smem k-stride in bf16 units

template <int MODE>
__global__ __launch_bounds__(256) void hmma_gemm_kernel(
    const __nv_bfloat16* __restrict__ Ahi, const __nv_bfloat16* __restrict__ Alo,
    const __nv_bfloat16* __restrict__ Bhi, const __nv_bfloat16* __restrict__ Blo,
    const float* __restrict__ bias, float* __restrict__ out) {
  __shared__ __nv_bfloat16 sAhi[128 * SSTR];
  __shared__ __nv_bfloat16 sAlo[128 * SSTR];
  __shared__ __nv_bfloat16 sBhi[128 * SSTR];
  __shared__ __nv_bfloat16 sBlo[128 * SSTR];

  const int tid = threadIdx.x;
  const int wid = tid >> 5, lane = tid & 31;
  const int wm = wid & 1;
  const int wn = wid >> 1;
  const int g = lane >> 2, t = lane & 3;
  const int bn = blockIdx.x, bm = blockIdx.y;
  const int arow0 = bm * 128, brow0 = bn * 128;

  float acc[4][4][4];
#pragma unroll
  for (int mi = 0; mi < 4; mi++)
#pragma unroll
    for (int ni = 0; ni < 4; ni++)
#pragma unroll
      for (int r = 0; r < 4; r++) acc[mi][ni][r] = 0.f;

  for (int kt = 0; kt < 768; kt += 32) {
    __syncthreads();
    for (int c = tid; c < 512; c += 256) {
      int row = c >> 2, q = c & 3;
      size_t ga = (size_t)(arow0 + row) * 768 + kt + q * 8;
      size_t gb = (size_t)(brow0 + row) * 768 + kt + q * 8;
      int so = row * SSTR + q * 8;
      *(uint4*)&sAhi[so] = *(const uint4*)(Ahi + ga);
      *(uint4*)&sAlo[so] = *(const uint4*)(Alo + ga);
      *(uint4*)&sBhi[so] = *(const uint4*)(Bhi + gb);
      *(uint4*)&sBlo[so] = *(const uint4*)(Blo + gb);
    }
    __syncthreads();

#pragma unroll
    for (int ks = 0; ks < 32; ks += 16) {
      uint32_t a[4][4], b[4][2];
      const int acol = ks + 2 * t;
#pragma unroll
      for (int mi = 0; mi < 4; mi++) {
        int r0 = (wm * 64 + mi * 16 + g) * SSTR;
        a[mi][0] = *(const uint32_t*)&sAhi[r0 + acol];
        a[mi][1] = *(const uint32_t*)&sAhi[r0 + 8 * SSTR + acol];
        a[mi][2] = *(const uint32_t*)&sAhi[r0 + acol + 8];
        a[mi][3] = *(const uint32_t*)&sAhi[r0 + 8 * SSTR + acol + 8];
      }
#pragma unroll
      for (int ni = 0; ni < 4; ni++) {
        int r0 = (wn * 32 + ni * 8 + g) * SSTR;
        b[ni][0] = *(const uint32_t*)&sBhi[r0 + acol];
        b[ni][1] = *(const uint32_t*)&sBhi[r0 + acol + 8];
      }
#pragma unroll
      for (int mi = 0; mi < 4; mi++)
#pragma unroll
        for (int ni = 0; ni < 4; ni++) mma16816(acc[mi][ni], a[mi], b[ni]);
#pragma unroll
      for (int ni = 0; ni < 4; ni++) {
        int r0 = (wn * 32 + ni * 8 + g) * SSTR;
        b[ni][0] = *(const uint32_t*)&sBlo[r0 + acol];
        b[ni][1] = *(const uint32_t*)&sBlo[r0 + acol + 8];
      }
#pragma unroll
      for (int mi = 0; mi < 4; mi++)
#pragma unroll
        for (int ni = 0; ni < 4; ni++) mma16816(acc[mi][ni], a[mi], b[ni]);
#pragma unroll
      for (int mi = 0; mi < 4; mi++) {
        int r0 = (wm * 64 + mi * 16 + g) * SSTR;
        a[mi][0] = *(const uint32_t*)&sAlo[r0 + acol];
        a[mi][1] = *(const uint32_t*)&sAlo[r0 + 8 * SSTR + acol];
        a[mi][2] = *(const uint32_t*)&sAlo[r0 + acol + 8];
        a[mi][3] = *(const uint32_t*)&sAlo[r0 + 8 * SSTR + acol + 8];
      }
#pragma unroll
      for (int ni = 0; ni < 4; ni++) {
        int r0 = (wn * 32 + ni * 8 + g) * SSTR;
        b[ni][0] = *(const uint32_t*)&sBhi[r0 + acol];
        b[ni][1] = *(const uint32_t*)&sBhi[r0 + acol + 8];
      }
#pragma unroll
      for (int mi = 0; mi < 4; mi++)
#pragma unroll
        for (int ni = 0; ni < 4; ni++) mma16816(acc[mi][ni], a[mi], b[ni]);
    }
  }

  // Epilogue. c0,c1 -> (row g, cols 2t,2t+1); c2,c3 -> row g+8.
#pragma unroll
  for (int mi = 0; mi < 4; mi++) {
#pragma unroll
    for (int ni = 0; ni < 4; ni++) {
      int n = bn * 128 + wn * 32 + ni * 8 + 2 * t;
      float b0 = bias[n], b1 = bias[n + 1];
#pragma unroll
      for (int half = 0; half < 2; half++) {
        int m = bm * 128 + wm * 64 + mi * 16 + g + half * 8;
        float2 v;
        v.x = acc[mi][ni][half * 2 + 0] + b0;
        v.y = acc[mi][ni][half * 2 + 1] + b1;
        if (MODE == 0) {
          int part = n / 768;
          int rem = n - part * 768;
          int head = rem >> 6, d = rem & 63;
          int bb = m >> 10, s = m & 1023;
          int bh = bb * 12 + head;
          size_t off = ((size_t)bh * 1024 + s) * 64 + d;
          uint32_t hi, lo;
          if (part == 0) {
            *(float2*)(g_q + off) = v;
            split_pack(0.125f * v.x, 0.125f * v.y, hi, lo);
            *(uint32_t*)&g_qhi[off] = hi;
            *(uint32_t*)&g_qlo[off] = lo;
          } else if (part == 1) {
            split_pack(v.x, v.y, hi, lo);
            *(uint32_t*)&g_khi[off] = hi;
            *(uint32_t*)&g_klo[off] = lo;
          } else {
            __nv_bfloat16 h0 = __float2bfloat16(v.x);
            __nv_bfloat16 h1 = __float2bfloat16(v.y);
            size_t vt0 = ((size_t)bh * 64 + d) * 1024 + s;
            size_t vt1 = ((size_t)bh * 64 + d + 1) * 1024 + s;
            g_vthi[vt0] = h0;
            g_vthi[vt1] = h1;
            g_vtlo[vt0] = __float2bfloat16(v.x - __bfloat162float(h0));
            g_vtlo[vt1] = __float2bfloat16(v.y - __bfloat162float(h1));
          }
        } else {
          *(float2*)(out + (size_t)m * 768 + n) = v;
        }
      }
    }
  }
}

// ---------------------------------------------------------------------------
// Kernel 2: decomposed rel-pos bias tables.  Bank-conflict fix: XOR swizzle
// on Rhs/Rws columns (phase rows are spaced by 4 -> use bits [2:4] of row).
// ---------------------------------------------------------------------------
#define RSWZ(r, c4) ((c4) ^ ((((r) >> 2) & 7) << 2))

__global__ __launch_bounds__(256) void relbias_kernel(
    const float* __restrict__ rph, const float* __restrict__ rpw) {
  __shared__ float Qs[32][64];
  __shared__ float Rhs[32][64];
  __shared__ float Rws[63][64];
  const int h = blockIdx.x;
  const int bh = blockIdx.y;
  const int tid = threadIdx.x;

  for (int idx = tid; idx < 32 * 16; idx += 256) {
    int w = idx >> 4, c4 = (idx & 15) << 2;
    *(float4*)&Qs[w][c4] =
        *(const float4*)&g_q[((size_t)bh * 1024 + h * 32 + w) * 64 + c4];
    *(float4*)&Rhs[w][RSWZ(w, c4)] = *(const float4*)&rph[(h + w) * 64 + c4];
  }
  for (int idx = tid; idx < 63 * 16; idx += 256) {
    int r = idx >> 4, c4 = (idx & 15) << 2;
    *(float4*)&Rws[r][RSWZ(r, c4)] = *(const float4*)&rpw[r * 64 + c4];
  }
  __syncthreads();

  const int w = tid >> 3;
  const int k0 = (tid & 7) << 2;
  float ah[4] = {0, 0, 0, 0}, aw[4] = {0, 0, 0, 0};
#pragma unroll
  for (int d4 = 0; d4 < 64; d4 += 4) {
    float4 qv = *(const float4*)&Qs[w][d4];
#pragma unroll
    for (int j = 0; j < 4; j++) {
      int rh_r = 31 - (k0 + j);
      float4 rh = *(const float4*)&Rhs[rh_r][RSWZ(rh_r, d4)];
      ah[j] += qv.x * rh.x + qv.y * rh.y + qv.z * rh.z + qv.w * rh.w;
      int rw_r = w - (k0 + j) + 31;
      float4 rw = *(const float4*)&Rws[rw_r][RSWZ(rw_r, d4)];
      aw[j] += qv.x * rw.x + qv.y * rw.y + qv.z * rw.z + qv.w * rw.w;
    }
  }
  size_t ob = (((size_t)bh * 32 + h) * 32 + w) * 32 + k0;
#pragma unroll
  for (int j = 0; j < 4; j++) {
    g_relh[ob + j] = ah[j];
    g_relw[ob + j] = aw[j];
  }
}

// ---------------------------------------------------------------------------
// Kernel 3: flash attention on HMMA, hi/lo 3-product, 64x64 q-tile.
// 128 threads = 4 warps; warp owns 16 q-rows. Q frags in registers.
// K row-major smem; V pre-transposed [d][seq] smem. P reused from S C-frags.
// Writes O directly as bf16 hi/lo in proj-GEMM layout.
// ---------------------------------------------------------------------------
#define KSTR 72  // bf16 smem stride

__global__ __launch_bounds__(128, 3) void attn_mma_kernel() {
  __shared__ __nv_bfloat16 sKhi[64 * KSTR];
  __shared__ __nv_bfloat16 sKlo[64 * KSTR];
  __shared__ __nv_bfloat16 sVhi[64 * KSTR];  // [d][seq]
  __shared__ __nv_bfloat16 sVlo[64 * KSTR];
  __shared__ float sBh[64 * 32];

  const int bh = blockIdx.y;
  const int q0 = blockIdx.x * 64;
  const int tid = threadIdx.x;
  const int w = tid >> 5, lane = tid & 31;
  const int g = lane >> 2, t = lane & 3;
  const int b = bh / 12, head = bh - b * 12;

  // rel_h table for this q-tile
  for (int idx = tid; idx < 64 * 8; idx += 128) {
    int r = idx >> 3, c4 = (idx & 7) << 2;
    int s = q0 + r;
    *(float4*)&sBh[r * 32 + c4] = *(const float4*)
        &g_relh[(((size_t)bh * 32 + (s >> 5)) * 32 + (s & 31)) * 32 + c4];
  }

  // Q fragments in registers (rows w*16+g, w*16+g+8), pre-scaled
  uint32_t qhi[4][4], qlo[4][4];
  {
    const size_t base = ((size_t)bh * 1024 + q0 + w * 16) * 64;
#pragma unroll
    for (int kc = 0; kc < 4; kc++) {
      int col = kc * 16 + 2 * t;
      qhi[kc][0] = *(const uint32_t*)&g_qhi[base + (size_t)g * 64 + col];
      qhi[kc][1] = *(const uint32_t*)&g_qhi[base + (size_t)(g + 8) * 64 + col];
      qhi[kc][2] = *(const uint32_t*)&g_qhi[base + (size_t)g * 64 + col + 8];
      qhi[kc][3] =
          *(const uint32_t*)&g_qhi[base + (size_t)(g + 8) * 64 + col + 8];
      qlo[kc][0] = *(const uint32_t*)&g_qlo[base + (size_t)g * 64 + col];
      qlo[kc][1] = *(const uint32_t*)&g_qlo[base + (size_t)(g + 8) * 64 + col];
      qlo[kc][2] = *(const uint32_t*)&g_qlo[base + (size_t)g * 64 + col + 8];
      qlo[kc][3] =
          *(const uint32_t*)&g_qlo[base + (size_t)(g + 8) * 64 + col + 8];
    }
  }

  // rel_w bias registers: bw[half][ni&3][col01]
  float bw[2][4][2];
#pragma unroll
  for (int hf = 0; hf < 2; hf++) {
    int s = q0 + w * 16 + g + hf * 8;
    const float* src =
        &g_relw[(((size_t)bh * 32 + (s >> 5)) * 32 + (s & 31)) * 32];
#pragma unroll
    for (int nm = 0; nm < 4; nm++) {
      bw[hf][nm][0] = src[nm * 8 + 2 * t];
      bw[hf][nm][1] = src[nm * 8 + 2 * t + 1];
    }
  }

  float m0 = -INFINITY, m1 = -INFINITY, l0 = 0.f, l1 = 0.f;
  float o[8][4];
#pragma unroll
  for (int ni = 0; ni < 8; ni++)
#pragma unroll
    for (int r = 0; r < 4; r++) o[ni][r] = 0.f;

  for (int kt = 0; kt < 16; kt++) {
    __syncthreads();
    for (int idx = tid; idx < 512; idx += 128) {
      int r = idx >> 3, q = idx & 7;
      size_t gk = ((size_t)bh * 1024 + kt * 64 + r) * 64 + q * 8;
      *(uint4*)&sKhi[r * KSTR + q * 8] = *(const uint4*)&g_khi[gk];
      *(uint4*)&sKlo[r * KSTR + q * 8] = *(const uint4*)&g_klo[gk];
      size_t gv = ((size_t)bh * 64 + r) * 1024 + kt * 64 + q * 8;
      *(uint4*)&sVhi[r * KSTR + q * 8] = *(const uint4*)&g_vthi[gv];
      *(uint4*)&sVlo[r * KSTR + q * 8] = *(const uint4*)&g_vtlo[gv];
    }
    __syncthreads();

    // ---- S = (scaled Q) K^T, 3 products ----
    float sc[8][4];
#pragma unroll
    for (int ni = 0; ni < 8; ni++)
#pragma unroll
      for (int r = 0; r < 4; r++) sc[ni][r] = 0.f;
#pragma unroll
    for (int kc = 0; kc < 4; kc++) {
      const int c0 = kc * 16 + 2 * t;
#pragma unroll
      for (int ni = 0; ni < 8; ni++) {
        const int rb = (ni * 8 + g) * KSTR;
        uint32_t bhv[2], blv[2];
        bhv[0] = *(const uint32_t*)&sKhi[rb + c0];
        bhv[1] = *(const uint32_t*)&sKhi[rb + c0 + 8];
        blv[0] = *(const uint32_t*)&sKlo[rb + c0];
        blv[1] = *(const uint32_t*)&sKlo[rb + c0 + 8];
        mma16816(sc[ni], qhi[kc], bhv);
        mma16816(sc[ni], qhi[kc], blv);
        mma16816(sc[ni], qlo[kc], bhv);
      }
    }

    // ---- bias + online softmax (rows g and g+8) ----
    const float bhA0 = sBh[(w * 16 + g) * 32 + 2 * kt];
    const float bhA1 = sBh[(w * 16 + g) * 32 + 2 * kt + 1];
    const float bhB0 = sBh[(w * 16 + g + 8) * 32 + 2 * kt];
    const float bhB1 = sBh[(w * 16 + g + 8) * 32 + 2 * kt + 1];
    float mx0 = -INFINITY, mx1 = -INFINITY;
#pragma unroll
    for (int ni = 0; ni < 8; ni++) {
      const float ba = (ni < 4) ? bhA0 : bhA1;
      const float bb2 = (ni < 4) ? bhB0 : bhB1;
      const int nm = ni & 3;
      sc[ni][0] += ba + bw[0][nm][0];
      sc[ni][1] += ba + bw[0][nm][1];
      sc[ni][2] += bb2 + bw[1][nm][0];
      sc[ni][3] += bb2 + bw[1][nm][1];
      mx0 = fmaxf(mx0, fmaxf(sc[ni][0], sc[ni][1]));
      mx1 = fmaxf(mx1, fmaxf(sc[ni][2], sc[ni][3]));
    }
    mx0 = fmaxf(mx0, __shfl_xor_sync(0xffffffffu, mx0, 1));
    mx0 = fmaxf(mx0, __shfl_xor_sync(0xffffffffu, mx0, 2));
    mx1 = fmaxf(mx1, __shfl_xor_sync(0xffffffffu, mx1, 1));
    mx1 = fmaxf(mx1, __shfl_xor_sync(0xffffffffu, mx1, 2));
    const float mn0 = fmaxf(m0, mx0), mn1 = fmaxf(m1, mx1);
    const float a0 = __expf(m0 - mn0), a1 = __expf(m1 - mn1);
    float sum0 = 0.f, sum1 = 0.f;
#pragma unroll
    for (int ni = 0; ni < 8; ni++) {
      sc[ni][0] = __expf(sc[ni][0] - mn0);
      sc[ni][1] = __expf(sc[ni][1] - mn0);
      sc[ni][2] = __expf(sc[ni][2] - mn1);
      sc[ni][3] = __expf(sc[ni][3] - mn1);
      sum0 += sc[ni][0] + sc[ni][1];
      sum1 += sc[ni][2] + sc[ni][3];
    }
    sum0 += __shfl_xor_sync(0xffffffffu, sum0, 1);
    sum0 += __shfl_xor_sync(0xffffffffu, sum0, 2);
    sum1 += __shfl_xor_sync(0xffffffffu, sum1, 1);
    sum1 += __shfl_xor_sync(0xffffffffu, sum1, 2);
    l0 = l0 * a0 + sum0;
    l1 = l1 * a1 + sum1;
    m0 = mn0;
    m1 = mn1;
#pragma unroll
    for (int ni = 0; ni < 8; ni++) {
      o[ni][0] *= a0;
      o[ni][1] *= a0;
      o[ni][2] *= a1;
      o[ni][3] *= a1;
    }

    // ---- pack P (A-frags reuse S C-frags) ----
    uint32_t phi[4][4], plo[4][4];
#pragma unroll
    for (int kc = 0; kc < 4; kc++) {
      const int nA = 2 * kc, nB = 2 * kc + 1;
      split_pack(sc[nA][0], sc[nA][1], phi[kc][0], plo[kc][0]);
      split_pack(sc[nA][2], sc[nA][3], phi[kc][1], plo[kc][1]);
      split_pack(sc[nB][0], sc[nB][1], phi[kc][2], plo[kc][2]);
      split_pack(sc[nB][2], sc[nB][3], phi[kc][3], plo[kc][3]);
    }

    // ---- O += P V  (B from transposed V: rows = d) ----
#pragma unroll
    for (int kc = 0; kc < 4; kc++) {
      const int c0 = kc * 16 + 2 * t;
#pragma unroll
      for (int ni = 0; ni < 8; ni++) {
        const int rb = (ni * 8 + g) * KSTR;
        uint32_t vh[2], vl[2];
        vh[0] = *(const uint32_t*)&sVhi[rb + c0];
        vh[1] = *(const uint32_t*)&sVhi[rb + c0 + 8];
        vl[0] = *(const uint32_t*)&sVlo[rb + c0];
        vl[1] = *(const uint32_t*)&sVlo[rb + c0 + 8];
        mma16816(o[ni], phi[kc], vh);
        mma16816(o[ni], phi[kc], vl);
        mma16816(o[ni], plo[kc], vh);
      }
    }
  }

  // epilogue: normalize and write bf16 hi/lo in proj layout [b*1024+s][768]
  const float inv0 = 1.f / l0, inv1 = 1.f / l1;
  const int s0 = q0 + w * 16 + g, s1 = s0 + 8;
  const size_t ob0 = ((size_t)(b * 1024 + s0)) * 768 + head * 64;
  const size_t ob1 = ((size_t)(b * 1024 + s1)) * 768 + head * 64;
#pragma unroll
  for (int ni = 0; ni < 8; ni++) {
    const int d = ni * 8 + 2 * t;
    uint32_t hi, lo;
    split_pack(o[ni][0] * inv0, o[ni][1] * inv0, hi, lo);
    *(uint32_t*)&g_ohi[ob0 + d] = hi;
    *(uint32_t*)&g_olo[ob0 + d] = lo;
    split_pack(o[ni][2] * inv1, o[ni][3] * inv1, hi, lo);
    *(uint32_t*)&g_ohi[ob1 + d] = hi;
    *(uint32_t*)&g_olo[ob1 + d] = lo;
  }
}

// ---------------------------------------------------------------------------
extern "C" void kernel_launch(void* const* d_in, const int* in_sizes, int n_in,
                              void* d_out, int out_size) {
  const float* x      = (const float*)d_in[0];
  const float* qkv_w  = (const float*)d_in[1];
  const float* qkv_b  = (const float*)d_in[2];
  const float* proj_w = (const float*)d_in[3];
  const float* proj_b = (const float*)d_in[4];
  const float* rph    = (const float*)d_in[5];
  const float* rpw    = (const float*)d_in[6];
  float* out = (float*)d_out;

  __nv_bfloat16 *xhi, *xlo, *whi, *wlo, *ohi, *olo, *phi, *plo;
  cudaGetSymbolAddress((void**)&xhi, g_xhi);
  cudaGetSymbolAddress((void**)&xlo, g_xlo);
  cudaGetSymbolAddress((void**)&whi, g_wqkv_hi);
  cudaGetSymbolAddress((void**)&wlo, g_wqkv_lo);
  cudaGetSymbolAddress((void**)&ohi, g_ohi);
  cudaGetSymbolAddress((void**)&olo, g_olo);
  cudaGetSymbolAddress((void**)&phi, g_wproj_hi);
  cudaGetSymbolAddress((void**)&plo, g_wproj_lo);

  split2_kernel<<<8192 * 768 / 4 / 256, 256>>>(x, xhi, xlo, 8192 * 768 / 4);
  split2_kernel<<<2304 * 768 / 4 / 256, 256>>>(qkv_w, whi, wlo, 2304 * 768 / 4);
  hmma_gemm_kernel<0><<<dim3(18, 64), 256>>>(xhi, xlo, whi, wlo, qkv_b,
                                             nullptr);
  relbias_kernel<<<dim3(32, 96), 256>>>(rph, rpw);
  attn_mma_kernel<<<dim3(16, 96), 128>>>();
  split2_kernel<<<768 * 768 / 4 / 256, 256>>>(proj_w, phi, plo, 768 * 768 / 4);
  hmma_gemm_kernel<1><<<dim3(6, 64), 256>>>(ohi, olo, phi, plo, proj_b, out);
}

// round 5
// speedup vs baseline: 2.5619x; 1.0147x over previous
#include <cuda_runtime.h>
#include <cuda_bf16.h>
#include <math.h>
#include <cstdint>

// ---------------------------------------------------------------------------
// Problem constants
//   x:(8,32,32,768)  qkv_w:(2304,768)  qkv_b:(2304)
//   proj_w:(768,768) proj_b:(768)  rel_pos_h/w:(63,64)
//   NH=12 HD=64 S=1024 B*NH=96, out:(8,32,32,768) fp32
// ---------------------------------------------------------------------------
namespace {
constexpr int kHD = 64;
constexpr int kS  = 1024;
constexpr int kBH = 96;
}

// Scratch (__device__ globals: allocation-free per harness rules)
__device__ float g_q[kBH * kS * kHD];          // fp32 q (relbias input)
__device__ float g_relh[kBH * 32 * 32 * 32];
__device__ float g_relw[kBH * 32 * 32 * 32];

// bf16 split operands
__device__ __nv_bfloat16 g_xhi[8192 * 768];
__device__ __nv_bfloat16 g_xlo[8192 * 768];
__device__ __nv_bfloat16 g_wqkv_hi[2304 * 768];
__device__ __nv_bfloat16 g_wqkv_lo[2304 * 768];
__device__ __nv_bfloat16 g_ohi[8192 * 768];
__device__ __nv_bfloat16 g_olo[8192 * 768];
__device__ __nv_bfloat16 g_wproj_hi[768 * 768];
__device__ __nv_bfloat16 g_wproj_lo[768 * 768];
// attention operands (written by qkv epilogue)
__device__ __nv_bfloat16 g_qhi[kBH * kS * kHD];  // pre-scaled by 0.125
__device__ __nv_bfloat16 g_qlo[kBH * kS * kHD];
__device__ __nv_bfloat16 g_khi[kBH * kS * kHD];
__device__ __nv_bfloat16 g_klo[kBH * kS * kHD];
__device__ __nv_bfloat16 g_vthi[kBH * kHD * kS];  // [bh][d][seq] transposed
__device__ __nv_bfloat16 g_vtlo[kBH * kHD * kS];

// ---------------------------------------------------------------------------
// PTX helpers
// ---------------------------------------------------------------------------
__device__ __forceinline__ void mma16816(float* c, const uint32_t* a,
                                         const uint32_t* b) {
  asm volatile(
      "mma.sync.aligned.m16n8k16.row.col.f32.bf16.bf16.f32 "
      "{%0,%1,%2,%3}, {%4,%5,%6,%7}, {%8,%9}, {%0,%1,%2,%3};"
      : "+f"(c[0]), "+f"(c[1]), "+f"(c[2]), "+f"(c[3])
      : "r"(a[0]), "r"(a[1]), "r"(a[2]), "r"(a[3]), "r"(b[0]), "r"(b[1]));
}

__device__ __forceinline__ uint32_t smem_u32(const void* p) {
  uint32_t a;
  asm("{ .reg .u64 t; cvta.to.shared.u64 t, %1; cvt.u32.u64 %0, t; }"
      : "=r"(a) : "l"(p));
  return a;
}
__device__ __forceinline__ void cp16(uint32_t s, const void* g) {
  asm volatile("cp.async.cg.shared.global [%0], [%1], 16;" ::"r"(s), "l"(g)
               : "memory");
}
#define CP_COMMIT() asm volatile("cp.async.commit_group;" ::: "memory")
#define CP_WAIT1() asm volatile("cp.async.wait_group 1;" ::: "memory")
#define CP_WAIT0() asm volatile("cp.async.wait_group 0;" ::: "memory")

__device__ __forceinline__ void split_pack(float x0, float x1, uint32_t& hi,
                                           uint32_t& lo) {
  __nv_bfloat16 h0 = __float2bfloat16(x0), h1 = __float2bfloat16(x1);
  __nv_bfloat162 hp(h0, h1);
  hi = *(uint32_t*)&hp;
  __nv_bfloat16 l0 = __float2bfloat16(x0 - __bfloat162float(h0));
  __nv_bfloat16 l1 = __float2bfloat16(x1 - __bfloat162float(h1));
  __nv_bfloat162 lp(l0, l1);
  lo = *(uint32_t*)&lp;
}

// ---------------------------------------------------------------------------
// fp32 -> bf16 hi/lo split (contiguous)
// ---------------------------------------------------------------------------
__global__ __launch_bounds__(256) void split2_kernel(
    const float* __restrict__ src, __nv_bfloat16* __restrict__ hi,
    __nv_bfloat16* __restrict__ lo, int n4) {
  int i = blockIdx.x * 256 + threadIdx.x;
  if (i >= n4) return;
  float4 f = ((const float4*)src)[i];
  uint2 uh, ul;
  split_pack(f.x, f.y, uh.x, ul.x);
  split_pack(f.z, f.w, uh.y, ul.y);
  ((uint2*)hi)[i] = uh;
  ((uint2*)lo)[i] = ul;
}

// ---------------------------------------------------------------------------
// HMMA GEMM: C[128,128] = Ahi*Bhi + Ahi*Blo + Alo*Bhi  (K=768, fp32 acc)
// 256 threads = 8 warps (2 m x 4 n), warp tile 64x32, BK=32.
// cp.async double-buffered smem.
// MODE 0: qkv epilogue (scatter q fp32 + q/k/v bf16 hi/lo, V transposed)
// MODE 1: proj epilogue (row-major fp32 out + bias)
// ---------------------------------------------------------------------------
#define SSTR 40                  // smem k-stride in bf16 units
#define GEMM_TILE 10240          // 128*SSTR*2 bytes
#define GEMM_BUF (4 * GEMM_TILE) // one stage: Ahi,Alo,Bhi,Blo
#define GEMM_SMEM (2 * GEMM_BUF)

template <int MODE>
__global__ __launch_bounds__(256) void hmma_gemm_kernel(
    const __nv_bfloat16* __restrict__ Ahi, const __nv_bfloat16* __restrict__ Alo,
    const __nv_bfloat16* __restrict__ Bhi, const __nv_bfloat16* __restrict__ Blo,
    const float* __restrict__ bias, float* __restrict__ out) {
  extern __shared__ char dsm[];
  const uint32_t smb = smem_u32(dsm);
  const int tid = threadIdx.x;
  const int wid = tid >> 5, lane = tid & 31;
  const int wm = wid & 1;
  const int wn = wid >> 1;
  const int g = lane >> 2, t = lane & 3;
  const int bn = blockIdx.x, bm = blockIdx.y;
  const int arow0 = bm * 128, brow0 = bn * 128;

  auto prefetch = [&](int kt, int bb) {
    uint32_t sb = smb + bb * GEMM_BUF;
#pragma unroll
    for (int c = tid; c < 512; c += 256) {
      int row = c >> 2, q = c & 3;
      size_t ga = (size_t)(arow0 + row) * 768 + kt * 32 + q * 8;
      size_t gb = (size_t)(brow0 + row) * 768 + kt * 32 + q * 8;
      uint32_t so = row * (SSTR * 2) + q * 16;
      cp16(sb + so, Ahi + ga);
      cp16(sb + GEMM_TILE + so, Alo + ga);
      cp16(sb + 2 * GEMM_TILE + so, Bhi + gb);
      cp16(sb + 3 * GEMM_TILE + so, Blo + gb);
    }
  };

  float acc[4][4][4];
#pragma unroll
  for (int mi = 0; mi < 4; mi++)
#pragma unroll
    for (int ni = 0; ni < 4; ni++)
#pragma unroll
      for (int r = 0; r < 4; r++) acc[mi][ni][r] = 0.f;

  prefetch(0, 0);
  CP_COMMIT();

  for (int kt = 0; kt < 24; ++kt) {
    const int bb = kt & 1;
    if (kt + 1 < 24) {
      prefetch(kt + 1, bb ^ 1);
      CP_COMMIT();
      CP_WAIT1();
    } else {
      CP_WAIT0();
    }
    __syncthreads();
    const __nv_bfloat16* sAhi = (const __nv_bfloat16*)(dsm + bb * GEMM_BUF);
    const __nv_bfloat16* sAlo =
        (const __nv_bfloat16*)(dsm + bb * GEMM_BUF + GEMM_TILE);
    const __nv_bfloat16* sBhi =
        (const __nv_bfloat16*)(dsm + bb * GEMM_BUF + 2 * GEMM_TILE);
    const __nv_bfloat16* sBlo =
        (const __nv_bfloat16*)(dsm + bb * GEMM_BUF + 3 * GEMM_TILE);

#pragma unroll
    for (int ks = 0; ks < 32; ks += 16) {
      uint32_t a[4][4], b[4][2];
      const int acol = ks + 2 * t;
#pragma unroll
      for (int mi = 0; mi < 4; mi++) {
        int r0 = (wm * 64 + mi * 16 + g) * SSTR;
        a[mi][0] = *(const uint32_t*)&sAhi[r0 + acol];
        a[mi][1] = *(const uint32_t*)&sAhi[r0 + 8 * SSTR + acol];
        a[mi][2] = *(const uint32_t*)&sAhi[r0 + acol + 8];
        a[mi][3] = *(const uint32_t*)&sAhi[r0 + 8 * SSTR + acol + 8];
      }
#pragma unroll
      for (int ni = 0; ni < 4; ni++) {
        int r0 = (wn * 32 + ni * 8 + g) * SSTR;
        b[ni][0] = *(const uint32_t*)&sBhi[r0 + acol];
        b[ni][1] = *(const uint32_t*)&sBhi[r0 + acol + 8];
      }
#pragma unroll
      for (int mi = 0; mi < 4; mi++)
#pragma unroll
        for (int ni = 0; ni < 4; ni++) mma16816(acc[mi][ni], a[mi], b[ni]);
#pragma unroll
      for (int ni = 0; ni < 4; ni++) {
        int r0 = (wn * 32 + ni * 8 + g) * SSTR;
        b[ni][0] = *(const uint32_t*)&sBlo[r0 + acol];
        b[ni][1] = *(const uint32_t*)&sBlo[r0 + acol + 8];
      }
#pragma unroll
      for (int mi = 0; mi < 4; mi++)
#pragma unroll
        for (int ni = 0; ni < 4; ni++) mma16816(acc[mi][ni], a[mi], b[ni]);
#pragma unroll
      for (int mi = 0; mi < 4; mi++) {
        int r0 = (wm * 64 + mi * 16 + g) * SSTR;
        a[mi][0] = *(const uint32_t*)&sAlo[r0 + acol];
        a[mi][1] = *(const uint32_t*)&sAlo[r0 + 8 * SSTR + acol];
        a[mi][2] = *(const uint32_t*)&sAlo[r0 + acol + 8];
        a[mi][3] = *(const uint32_t*)&sAlo[r0 + 8 * SSTR + acol + 8];
      }
#pragma unroll
      for (int ni = 0; ni < 4; ni++) {
        int r0 = (wn * 32 + ni * 8 + g) * SSTR;
        b[ni][0] = *(const uint32_t*)&sBhi[r0 + acol];
        b[ni][1] = *(const uint32_t*)&sBhi[r0 + acol + 8];
      }
#pragma unroll
      for (int mi = 0; mi < 4; mi++)
#pragma unroll
        for (int ni = 0; ni < 4; ni++) mma16816(acc[mi][ni], a[mi], b[ni]);
    }
    __syncthreads();
  }

  // Epilogue. c0,c1 -> (row g, cols 2t,2t+1); c2,c3 -> row g+8.
#pragma unroll
  for (int mi = 0; mi < 4; mi++) {
#pragma unroll
    for (int ni = 0; ni < 4; ni++) {
      int n = bn * 128 + wn * 32 + ni * 8 + 2 * t;
      float b0 = bias[n], b1 = bias[n + 1];
#pragma unroll
      for (int half = 0; half < 2; half++) {
        int m = bm * 128 + wm * 64 + mi * 16 + g + half * 8;
        float2 v;
        v.x = acc[mi][ni][half * 2 + 0] + b0;
        v.y = acc[mi][ni][half * 2 + 1] + b1;
        if (MODE == 0) {
          int part = n / 768;
          int rem = n - part * 768;
          int head = rem >> 6, d = rem & 63;
          int bb2 = m >> 10, s = m & 1023;
          int bh = bb2 * 12 + head;
          size_t off = ((size_t)bh * 1024 + s) * 64 + d;
          uint32_t hi, lo;
          if (part == 0) {
            *(float2*)(g_q + off) = v;
            split_pack(0.125f * v.x, 0.125f * v.y, hi, lo);
            *(uint32_t*)&g_qhi[off] = hi;
            *(uint32_t*)&g_qlo[off] = lo;
          } else if (part == 1) {
            split_pack(v.x, v.y, hi, lo);
            *(uint32_t*)&g_khi[off] = hi;
            *(uint32_t*)&g_klo[off] = lo;
          } else {
            __nv_bfloat16 h0 = __float2bfloat16(v.x);
            __nv_bfloat16 h1 = __float2bfloat16(v.y);
            size_t vt0 = ((size_t)bh * 64 + d) * 1024 + s;
            size_t vt1 = ((size_t)bh * 64 + d + 1) * 1024 + s;
            g_vthi[vt0] = h0;
            g_vthi[vt1] = h1;
            g_vtlo[vt0] = __float2bfloat16(v.x - __bfloat162float(h0));
            g_vtlo[vt1] = __float2bfloat16(v.y - __bfloat162float(h1));
          }
        } else {
          *(float2*)(out + (size_t)m * 768 + n) = v;
        }
      }
    }
  }
}

// ---------------------------------------------------------------------------
// Kernel 2: decomposed rel-pos bias tables.  XOR swizzle on Rhs/Rws; Qs row
// stride padded to 68 to kill the 4-way broadcast conflict.
// ---------------------------------------------------------------------------
#define RSWZ(r, c4) ((c4) ^ ((((r) >> 2) & 7) << 2))

__global__ __launch_bounds__(256) void relbias_kernel(
    const float* __restrict__ rph, const float* __restrict__ rpw) {
  __shared__ float Qs[32][68];
  __shared__ float Rhs[32][64];
  __shared__ float Rws[63][64];
  const int h = blockIdx.x;
  const int bh = blockIdx.y;
  const int tid = threadIdx.x;

  for (int idx = tid; idx < 32 * 16; idx += 256) {
    int w = idx >> 4, c4 = (idx & 15) << 2;
    *(float4*)&Qs[w][c4] =
        *(const float4*)&g_q[((size_t)bh * 1024 + h * 32 + w) * 64 + c4];
    *(float4*)&Rhs[w][RSWZ(w, c4)] = *(const float4*)&rph[(h + w) * 64 + c4];
  }
  for (int idx = tid; idx < 63 * 16; idx += 256) {
    int r = idx >> 4, c4 = (idx & 15) << 2;
    *(float4*)&Rws[r][RSWZ(r, c4)] = *(const float4*)&rpw[r * 64 + c4];
  }
  __syncthreads();

  const int w = tid >> 3;
  const int k0 = (tid & 7) << 2;
  float ah[4] = {0, 0, 0, 0}, aw[4] = {0, 0, 0, 0};
#pragma unroll
  for (int d4 = 0; d4 < 64; d4 += 4) {
    float4 qv = *(const float4*)&Qs[w][d4];
#pragma unroll
    for (int j = 0; j < 4; j++) {
      int rh_r = 31 - (k0 + j);
      float4 rh = *(const float4*)&Rhs[rh_r][RSWZ(rh_r, d4)];
      ah[j] += qv.x * rh.x + qv.y * rh.y + qv.z * rh.z + qv.w * rh.w;
      int rw_r = w - (k0 + j) + 31;
      float4 rw = *(const float4*)&Rws[rw_r][RSWZ(rw_r, d4)];
      aw[j] += qv.x * rw.x + qv.y * rw.y + qv.z * rw.z + qv.w * rw.w;
    }
  }
  size_t ob = (((size_t)bh * 32 + h) * 32 + w) * 32 + k0;
#pragma unroll
  for (int j = 0; j < 4; j++) {
    g_relh[ob + j] = ah[j];
    g_relw[ob + j] = aw[j];
  }
}

// ---------------------------------------------------------------------------
// Kernel 3: flash attention on HMMA, hi/lo 3-product, 128x64 q-tile.
// 256 threads = 8 warps; warp owns 16 q-rows. Q frags in registers.
// cp.async double-buffered K/V smem. V pre-transposed [d][seq].
// Writes O directly as bf16 hi/lo in proj-GEMM layout.
// ---------------------------------------------------------------------------
#define KSTR 72                      // bf16 smem stride
#define ATT_TILE (64 * KSTR * 2)     // 9216 B per array
#define ATT_BUF (4 * ATT_TILE)       // Khi,Klo,Vhi,Vlo one stage
#define ATT_BH_OFF (2 * ATT_BUF)
#define ATT_SMEM (2 * ATT_BUF + 128 * 32 * 4)

__global__ __launch_bounds__(256, 1) void attn_mma_kernel() {
  extern __shared__ char dsm[];
  const uint32_t smb = smem_u32(dsm);
  float* sBh = (float*)(dsm + ATT_BH_OFF);

  const int bh = blockIdx.y;
  const int q0 = blockIdx.x * 128;
  const int tid = threadIdx.x;
  const int w = tid >> 5, lane = tid & 31;
  const int g = lane >> 2, t = lane & 3;
  const int b = bh / 12, head = bh - b * 12;

  auto prefetch = [&](int kt, int bb) {
    uint32_t sb = smb + bb * ATT_BUF;
#pragma unroll
    for (int idx = tid; idx < 512; idx += 256) {
      int r = idx >> 3, qc = idx & 7;
      size_t gk = ((size_t)bh * 1024 + kt * 64 + r) * 64 + qc * 8;
      size_t gv = ((size_t)bh * 64 + r) * 1024 + kt * 64 + qc * 8;
      uint32_t so = r * (KSTR * 2) + qc * 16;
      cp16(sb + so, g_khi + gk);
      cp16(sb + ATT_TILE + so, g_klo + gk);
      cp16(sb + 2 * ATT_TILE + so, g_vthi + gv);
      cp16(sb + 3 * ATT_TILE + so, g_vtlo + gv);
    }
  };

  prefetch(0, 0);
  CP_COMMIT();

  // rel_h table for this q-tile (128 rows x 32)
  for (int idx = tid; idx < 128 * 8; idx += 256) {
    int r = idx >> 3, c4 = (idx & 7) << 2;
    int s = q0 + r;
    *(float4*)&sBh[r * 32 + c4] = *(const float4*)
        &g_relh[(((size_t)bh * 32 + (s >> 5)) * 32 + (s & 31)) * 32 + c4];
  }

  // Q fragments in registers (rows w*16+g, +8), pre-scaled
  uint32_t qhi[4][4], qlo[4][4];
  {
    const size_t base = ((size_t)bh * 1024 + q0 + w * 16) * 64;
#pragma unroll
    for (int kc = 0; kc < 4; kc++) {
      int col = kc * 16 + 2 * t;
      qhi[kc][0] = *(const uint32_t*)&g_qhi[base + (size_t)g * 64 + col];
      qhi[kc][1] = *(const uint32_t*)&g_qhi[base + (size_t)(g + 8) * 64 + col];
      qhi[kc][2] = *(const uint32_t*)&g_qhi[base + (size_t)g * 64 + col + 8];
      qhi[kc][3] =
          *(const uint32_t*)&g_qhi[base + (size_t)(g + 8) * 64 + col + 8];
      qlo[kc][0] = *(const uint32_t*)&g_qlo[base + (size_t)g * 64 + col];
      qlo[kc][1] = *(const uint32_t*)&g_qlo[base + (size_t)(g + 8) * 64 + col];
      qlo[kc][2] = *(const uint32_t*)&g_qlo[base + (size_t)g * 64 + col + 8];
      qlo[kc][3] =
          *(const uint32_t*)&g_qlo[base + (size_t)(g + 8) * 64 + col + 8];
    }
  }

  // rel_w bias registers: bw[half][ni&3][col01]
  float bw[2][4][2];
#pragma unroll
  for (int hf = 0; hf < 2; hf++) {
    int s = q0 + w * 16 + g + hf * 8;
    const float* src =
        &g_relw[(((size_t)bh * 32 + (s >> 5)) * 32 + (s & 31)) * 32];
#pragma unroll
    for (int nm = 0; nm < 4; nm++) {
      bw[hf][nm][0] = src[nm * 8 + 2 * t];
      bw[hf][nm][1] = src[nm * 8 + 2 * t + 1];
    }
  }

  float m0 = -INFINITY, m1 = -INFINITY, l0 = 0.f, l1 = 0.f;
  float o[8][4];
#pragma unroll
  for (int ni = 0; ni < 8; ni++)
#pragma unroll
    for (int r = 0; r < 4; r++) o[ni][r] = 0.f;

  for (int kt = 0; kt < 16; kt++) {
    const int bb = kt & 1;
    if (kt + 1 < 16) {
      prefetch(kt + 1, bb ^ 1);
      CP_COMMIT();
      CP_WAIT1();
    } else {
      CP_WAIT0();
    }
    __syncthreads();
    const __nv_bfloat16* sKhi = (const __nv_bfloat16*)(dsm + bb * ATT_BUF);
    const __nv_bfloat16* sKlo =
        (const __nv_bfloat16*)(dsm + bb * ATT_BUF + ATT_TILE);
    const __nv_bfloat16* sVhi =
        (const __nv_bfloat16*)(dsm + bb * ATT_BUF + 2 * ATT_TILE);
    const __nv_bfloat16* sVlo =
        (const __nv_bfloat16*)(dsm + bb * ATT_BUF + 3 * ATT_TILE);

    // ---- S = (scaled Q) K^T, 3 products ----
    float sc[8][4];
#pragma unroll
    for (int ni = 0; ni < 8; ni++)
#pragma unroll
      for (int r = 0; r < 4; r++) sc[ni][r] = 0.f;
#pragma unroll
    for (int kc = 0; kc < 4; kc++) {
      const int c0 = kc * 16 + 2 * t;
#pragma unroll
      for (int ni = 0; ni < 8; ni++) {
        const int rb = (ni * 8 + g) * KSTR;
        uint32_t bhv[2], blv[2];
        bhv[0] = *(const uint32_t*)&sKhi[rb + c0];
        bhv[1] = *(const uint32_t*)&sKhi[rb + c0 + 8];
        blv[0] = *(const uint32_t*)&sKlo[rb + c0];
        blv[1] = *(const uint32_t*)&sKlo[rb + c0 + 8];
        mma16816(sc[ni], qhi[kc], bhv);
        mma16816(sc[ni], qhi[kc], blv);
        mma16816(sc[ni], qlo[kc], bhv);
      }
    }

    // ---- bias + online softmax (rows g and g+8) ----
    const float bhA0 = sBh[(w * 16 + g) * 32 + 2 * kt];
    const float bhA1 = sBh[(w * 16 + g) * 32 + 2 * kt + 1];
    const float bhB0 = sBh[(w * 16 + g + 8) * 32 + 2 * kt];
    const float bhB1 = sBh[(w * 16 + g + 8) * 32 + 2 * kt + 1];
    float mx0 = -INFINITY, mx1 = -INFINITY;
#pragma unroll
    for (int ni = 0; ni < 8; ni++) {
      const float ba = (ni < 4) ? bhA0 : bhA1;
      const float bb2 = (ni < 4) ? bhB0 : bhB1;
      const int nm = ni & 3;
      sc[ni][0] += ba + bw[0][nm][0];
      sc[ni][1] += ba + bw[0][nm][1];
      sc[ni][2] += bb2 + bw[1][nm][0];
      sc[ni][3] += bb2 + bw[1][nm][1];
      mx0 = fmaxf(mx0, fmaxf(sc[ni][0], sc[ni][1]));
      mx1 = fmaxf(mx1, fmaxf(sc[ni][2], sc[ni][3]));
    }
    mx0 = fmaxf(mx0, __shfl_xor_sync(0xffffffffu, mx0, 1));
    mx0 = fmaxf(mx0, __shfl_xor_sync(0xffffffffu, mx0, 2));
    mx1 = fmaxf(mx1, __shfl_xor_sync(0xffffffffu, mx1, 1));
    mx1 = fmaxf(mx1, __shfl_xor_sync(0xffffffffu, mx1, 2));
    const float mn0 = fmaxf(m0, mx0), mn1 = fmaxf(m1, mx1);
    const float a0 = __expf(m0 - mn0), a1 = __expf(m1 - mn1);
    float sum0 = 0.f, sum1 = 0.f;
#pragma unroll
    for (int ni = 0; ni < 8; ni++) {
      sc[ni][0] = __expf(sc[ni][0] - mn0);
      sc[ni][1] = __expf(sc[ni][1] - mn0);
      sc[ni][2] = __expf(sc[ni][2] - mn1);
      sc[ni][3] = __expf(sc[ni][3] - mn1);
      sum0 += sc[ni][0] + sc[ni][1];
      sum1 += sc[ni][2] + sc[ni][3];
    }
    sum0 += __shfl_xor_sync(0xffffffffu, sum0, 1);
    sum0 += __shfl_xor_sync(0xffffffffu, sum0, 2);
    sum1 += __shfl_xor_sync(0xffffffffu, sum1, 1);
    sum1 += __shfl_xor_sync(0xffffffffu, sum1, 2);
    l0 = l0 * a0 + sum0;
    l1 = l1 * a1 + sum1;
    m0 = mn0;
    m1 = mn1;
#pragma unroll
    for (int ni = 0; ni < 8; ni++) {
      o[ni][0] *= a0;
      o[ni][1] *= a0;
      o[ni][2] *= a1;
      o[ni][3] *= a1;
    }

    // ---- pack P (A-frags reuse S C-frags) ----
    uint32_t phi[4][4], plo[4][4];
#pragma unroll
    for (int kc = 0; kc < 4; kc++) {
      const int nA = 2 * kc, nB = 2 * kc + 1;
      split_pack(sc[nA][0], sc[nA][1], phi[kc][0], plo[kc][0]);
      split_pack(sc[nA][2], sc[nA][3], phi[kc][1], plo[kc][1]);
      split_pack(sc[nB][0], sc[nB][1], phi[kc][2], plo[kc][2]);
      split_pack(sc[nB][2], sc[nB][3], phi[kc][3], plo[kc][3]);
    }

    // ---- O += P V  (B from transposed V: rows = d) ----
#pragma unroll
    for (int kc = 0; kc < 4; kc++) {
      const int c0 = kc * 16 + 2 * t;
#pragma unroll
      for (int ni = 0; ni < 8; ni++) {
        const int rb = (ni * 8 + g) * KSTR;
        uint32_t vh[2], vl[2];
        vh[0] = *(const uint32_t*)&sVhi[rb + c0];
        vh[1] = *(const uint32_t*)&sVhi[rb + c0 + 8];
        vl[0] = *(const uint32_t*)&sVlo[rb + c0];
        vl[1] = *(const uint32_t*)&sVlo[rb + c0 + 8];
        mma16816(o[ni], phi[kc], vh);
        mma16816(o[ni], phi[kc], vl);
        mma16816(o[ni], plo[kc], vh);
      }
    }
    __syncthreads();
  }

  // epilogue: normalize and write bf16 hi/lo in proj layout [b*1024+s][768]
  const float inv0 = 1.f / l0, inv1 = 1.f / l1;
  const int s0 = q0 + w * 16 + g, s1 = s0 + 8;
  const size_t ob0 = ((size_t)(b * 1024 + s0)) * 768 + head * 64;
  const size_t ob1 = ((size_t)(b * 1024 + s1)) * 768 + head * 64;
#pragma unroll
  for (int ni = 0; ni < 8; ni++) {
    const int d = ni * 8 + 2 * t;
    uint32_t hi, lo;
    split_pack(o[ni][0] * inv0, o[ni][1] * inv0, hi, lo);
    *(uint32_t*)&g_ohi[ob0 + d] = hi;
    *(uint32_t*)&g_olo[ob0 + d] = lo;
    split_pack(o[ni][2] * inv1, o[ni][3] * inv1, hi, lo);
    *(uint32_t*)&g_ohi[ob1 + d] = hi;
    *(uint32_t*)&g_olo[ob1 + d] = lo;
  }
}

// ---------------------------------------------------------------------------
extern "C" void kernel_launch(void* const* d_in, const int* in_sizes, int n_in,
                              void* d_out, int out_size) {
  const float* x      = (const float*)d_in[0];
  const float* qkv_w  = (const float*)d_in[1];
  const float* qkv_b  = (const float*)d_in[2];
  const float* proj_w = (const float*)d_in[3];
  const float* proj_b = (const float*)d_in[4];
  const float* rph    = (const float*)d_in[5];
  const float* rpw    = (const float*)d_in[6];
  float* out = (float*)d_out;

  cudaFuncSetAttribute(hmma_gemm_kernel<0>,
                       cudaFuncAttributeMaxDynamicSharedMemorySize, GEMM_SMEM);
  cudaFuncSetAttribute(hmma_gemm_kernel<1>,
                       cudaFuncAttributeMaxDynamicSharedMemorySize, GEMM_SMEM);
  cudaFuncSetAttribute(attn_mma_kernel,
                       cudaFuncAttributeMaxDynamicSharedMemorySize, ATT_SMEM);

  __nv_bfloat16 *xhi, *xlo, *whi, *wlo, *ohi, *olo, *phi, *plo;
  cudaGetSymbolAddress((void**)&xhi, g_xhi);
  cudaGetSymbolAddress((void**)&xlo, g_xlo);
  cudaGetSymbolAddress((void**)&whi, g_wqkv_hi);
  cudaGetSymbolAddress((void**)&wlo, g_wqkv_lo);
  cudaGetSymbolAddress((void**)&ohi, g_ohi);
  cudaGetSymbolAddress((void**)&olo, g_olo);
  cudaGetSymbolAddress((void**)&phi, g_wproj_hi);
  cudaGetSymbolAddress((void**)&plo, g_wproj_lo);

  split2_kernel<<<8192 * 768 / 4 / 256, 256>>>(x, xhi, xlo, 8192 * 768 / 4);
  split2_kernel<<<2304 * 768 / 4 / 256, 256>>>(qkv_w, whi, wlo, 2304 * 768 / 4);
  hmma_gemm_kernel<0><<<dim3(18, 64), 256, GEMM_SMEM>>>(xhi, xlo, whi, wlo,
                                                        qkv_b, nullptr);
  relbias_kernel<<<dim3(32, 96), 256>>>(rph, rpw);
  attn_mma_kernel<<<dim3(8, 96), 256, ATT_SMEM>>>();
  split2_kernel<<<768 * 768 / 4 / 256, 256>>>(proj_w, phi, plo, 768 * 768 / 4);
  hmma_gemm_kernel<1><<<dim3(6, 64), 256, GEMM_SMEM>>>(ohi, olo, phi, plo,
                                                       proj_b, out);
}

// round 6
// speedup vs baseline: 3.5975x; 1.4042x over previous
#include <cuda_runtime.h>
#include <cuda_fp16.h>
#include <math.h>
#include <cstdint>

// ---------------------------------------------------------------------------
// Problem constants
//   x:(8,32,32,768)  qkv_w:(2304,768)  qkv_b:(2304)
//   proj_w:(768,768) proj_b:(768)  rel_pos_h/w:(63,64)
//   NH=12 HD=64 S=1024 B*NH=96, out:(8,32,32,768) fp32
// ---------------------------------------------------------------------------
namespace {
constexpr int kHD = 64;
constexpr int kS  = 1024;
constexpr int kBH = 96;
}

// Scratch (__device__ globals: allocation-free per harness rules)
__device__ float g_q[kBH * kS * kHD];          // fp32 q (relbias input)
__device__ float g_relh[kBH * 32 * 32 * 32];
__device__ float g_relw[kBH * 32 * 32 * 32];

// fp16 operands. A-side carries hi/lo (2-product scheme), B-side single.
__device__ __half g_xhi[8192 * 768];
__device__ __half g_xlo[8192 * 768];
__device__ __half g_wqkv[2304 * 768];
__device__ __half g_ohi[8192 * 768];
__device__ __half g_olo[8192 * 768];
__device__ __half g_wproj[768 * 768];
// attention operands (written by qkv epilogue)
__device__ __half g_qhi[kBH * kS * kHD];  // pre-scaled by 0.125
__device__ __half g_qlo[kBH * kS * kHD];
__device__ __half g_k[kBH * kS * kHD];    // single fp16
__device__ __half g_vt[kBH * kHD * kS];   // [bh][d][seq] transposed, single

// ---------------------------------------------------------------------------
// PTX helpers
// ---------------------------------------------------------------------------
__device__ __forceinline__ void mma16816h(float* c, const uint32_t* a,
                                          const uint32_t* b) {
  asm volatile(
      "mma.sync.aligned.m16n8k16.row.col.f32.f16.f16.f32 "
      "{%0,%1,%2,%3}, {%4,%5,%6,%7}, {%8,%9}, {%0,%1,%2,%3};"
      : "+f"(c[0]), "+f"(c[1]), "+f"(c[2]), "+f"(c[3])
      : "r"(a[0]), "r"(a[1]), "r"(a[2]), "r"(a[3]), "r"(b[0]), "r"(b[1]));
}

__device__ __forceinline__ uint32_t smem_u32(const void* p) {
  uint32_t a;
  asm("{ .reg .u64 t; cvta.to.shared.u64 t, %1; cvt.u32.u64 %0, t; }"
      : "=r"(a) : "l"(p));
  return a;
}
__device__ __forceinline__ void cp16(uint32_t s, const void* g) {
  asm volatile("cp.async.cg.shared.global [%0], [%1], 16;" ::"r"(s), "l"(g)
               : "memory");
}
#define CP_COMMIT() asm volatile("cp.async.commit_group;" ::: "memory")
#define CP_WAIT1() asm volatile("cp.async.wait_group 1;" ::: "memory")
#define CP_WAIT0() asm volatile("cp.async.wait_group 0;" ::: "memory")

// fp32 pair -> packed fp16 hi + packed fp16 lo
__device__ __forceinline__ void split_pack_h(float x0, float x1, uint32_t& hi,
                                             uint32_t& lo) {
  __half h0 = __float2half_rn(x0), h1 = __float2half_rn(x1);
  __half2 hp(h0, h1);
  hi = *(uint32_t*)&hp;
  __half l0 = __float2half_rn(x0 - __half2float(h0));
  __half l1 = __float2half_rn(x1 - __half2float(h1));
  __half2 lp(l0, l1);
  lo = *(uint32_t*)&lp;
}

// ---------------------------------------------------------------------------
// fp32 -> fp16 hi/lo split (contiguous)
// ---------------------------------------------------------------------------
__global__ __launch_bounds__(256) void splith_kernel(
    const float* __restrict__ src, __half* __restrict__ hi,
    __half* __restrict__ lo, int n4) {
  int i = blockIdx.x * 256 + threadIdx.x;
  if (i >= n4) return;
  float4 f = ((const float4*)src)[i];
  uint2 uh, ul;
  split_pack_h(f.x, f.y, uh.x, ul.x);
  split_pack_h(f.z, f.w, uh.y, ul.y);
  ((uint2*)hi)[i] = uh;
  ((uint2*)lo)[i] = ul;
}

// fp32 -> fp16 single (contiguous)
__global__ __launch_bounds__(256) void convh_kernel(
    const float* __restrict__ src, __half* __restrict__ dst, int n4) {
  int i = blockIdx.x * 256 + threadIdx.x;
  if (i >= n4) return;
  float4 f = ((const float4*)src)[i];
  __half2 a(__float2half_rn(f.x), __float2half_rn(f.y));
  __half2 b(__float2half_rn(f.z), __float2half_rn(f.w));
  uint2 u;
  u.x = *(uint32_t*)&a;
  u.y = *(uint32_t*)&b;
  ((uint2*)dst)[i] = u;
}

// ---------------------------------------------------------------------------
// HMMA GEMM: C[128,128] = Ahi*B + Alo*B  (K=768, fp32 acc, fp16 operands)
// 256 threads = 8 warps (2 m x 4 n), warp tile 64x32, BK=32.
// cp.async double-buffered smem; B fragments register-cached across products.
// MODE 0: qkv epilogue (scatter q fp32 + q hi/lo + k/vt fp16)
// MODE 1: proj epilogue (row-major fp32 out + bias)
// ---------------------------------------------------------------------------
#define SSTR 40                  // smem k-stride in fp16 units
#define GEMM_TILE 10240          // 128*SSTR*2 bytes
#define GEMM_BUF (3 * GEMM_TILE) // one stage: Ahi,Alo,B
#define GEMM_SMEM (2 * GEMM_BUF)

template <int MODE>
__global__ __launch_bounds__(256) void hmma_gemm_kernel(
    const __half* __restrict__ Ahi, const __half* __restrict__ Alo,
    const __half* __restrict__ B, const float* __restrict__ bias,
    float* __restrict__ out) {
  extern __shared__ char dsm[];
  const uint32_t smb = smem_u32(dsm);
  const int tid = threadIdx.x;
  const int wid = tid >> 5, lane = tid & 31;
  const int wm = wid & 1;
  const int wn = wid >> 1;
  const int g = lane >> 2, t = lane & 3;
  const int bn = blockIdx.x, bm = blockIdx.y;
  const int arow0 = bm * 128, brow0 = bn * 128;

  auto prefetch = [&](int kt, int bb) {
    uint32_t sb = smb + bb * GEMM_BUF;
#pragma unroll
    for (int c = tid; c < 512; c += 256) {
      int row = c >> 2, q = c & 3;
      size_t ga = (size_t)(arow0 + row) * 768 + kt * 32 + q * 8;
      size_t gb = (size_t)(brow0 + row) * 768 + kt * 32 + q * 8;
      uint32_t so = row * (SSTR * 2) + q * 16;
      cp16(sb + so, Ahi + ga);
      cp16(sb + GEMM_TILE + so, Alo + ga);
      cp16(sb + 2 * GEMM_TILE + so, B + gb);
    }
  };

  float acc[4][4][4];
#pragma unroll
  for (int mi = 0; mi < 4; mi++)
#pragma unroll
    for (int ni = 0; ni < 4; ni++)
#pragma unroll
      for (int r = 0; r < 4; r++) acc[mi][ni][r] = 0.f;

  prefetch(0, 0);
  CP_COMMIT();

  for (int kt = 0; kt < 24; ++kt) {
    const int bb = kt & 1;
    if (kt + 1 < 24) {
      prefetch(kt + 1, bb ^ 1);
      CP_COMMIT();
      CP_WAIT1();
    } else {
      CP_WAIT0();
    }
    __syncthreads();
    const __half* sAhi = (const __half*)(dsm + bb * GEMM_BUF);
    const __half* sAlo = (const __half*)(dsm + bb * GEMM_BUF + GEMM_TILE);
    const __half* sB = (const __half*)(dsm + bb * GEMM_BUF + 2 * GEMM_TILE);

#pragma unroll
    for (int ks = 0; ks < 32; ks += 16) {
      uint32_t a[4][4], b[4][2];
      const int acol = ks + 2 * t;
      // B fragments once, cached for both products
#pragma unroll
      for (int ni = 0; ni < 4; ni++) {
        int r0 = (wn * 32 + ni * 8 + g) * SSTR;
        b[ni][0] = *(const uint32_t*)&sB[r0 + acol];
        b[ni][1] = *(const uint32_t*)&sB[r0 + acol + 8];
      }
#pragma unroll
      for (int mi = 0; mi < 4; mi++) {
        int r0 = (wm * 64 + mi * 16 + g) * SSTR;
        a[mi][0] = *(const uint32_t*)&sAhi[r0 + acol];
        a[mi][1] = *(const uint32_t*)&sAhi[r0 + 8 * SSTR + acol];
        a[mi][2] = *(const uint32_t*)&sAhi[r0 + acol + 8];
        a[mi][3] = *(const uint32_t*)&sAhi[r0 + 8 * SSTR + acol + 8];
      }
#pragma unroll
      for (int mi = 0; mi < 4; mi++)
#pragma unroll
        for (int ni = 0; ni < 4; ni++) mma16816h(acc[mi][ni], a[mi], b[ni]);
#pragma unroll
      for (int mi = 0; mi < 4; mi++) {
        int r0 = (wm * 64 + mi * 16 + g) * SSTR;
        a[mi][0] = *(const uint32_t*)&sAlo[r0 + acol];
        a[mi][1] = *(const uint32_t*)&sAlo[r0 + 8 * SSTR + acol];
        a[mi][2] = *(const uint32_t*)&sAlo[r0 + acol + 8];
        a[mi][3] = *(const uint32_t*)&sAlo[r0 + 8 * SSTR + acol + 8];
      }
#pragma unroll
      for (int mi = 0; mi < 4; mi++)
#pragma unroll
        for (int ni = 0; ni < 4; ni++) mma16816h(acc[mi][ni], a[mi], b[ni]);
    }
    __syncthreads();
  }

  // Epilogue. c0,c1 -> (row g, cols 2t,2t+1); c2,c3 -> row g+8.
#pragma unroll
  for (int mi = 0; mi < 4; mi++) {
#pragma unroll
    for (int ni = 0; ni < 4; ni++) {
      int n = bn * 128 + wn * 32 + ni * 8 + 2 * t;
      float b0 = bias[n], b1 = bias[n + 1];
#pragma unroll
      for (int half = 0; half < 2; half++) {
        int m = bm * 128 + wm * 64 + mi * 16 + g + half * 8;
        float2 v;
        v.x = acc[mi][ni][half * 2 + 0] + b0;
        v.y = acc[mi][ni][half * 2 + 1] + b1;
        if (MODE == 0) {
          int part = n / 768;
          int rem = n - part * 768;
          int head = rem >> 6, d = rem & 63;
          int bb2 = m >> 10, s = m & 1023;
          int bh = bb2 * 12 + head;
          size_t off = ((size_t)bh * 1024 + s) * 64 + d;
          if (part == 0) {
            *(float2*)(g_q + off) = v;
            uint32_t hi, lo;
            split_pack_h(0.125f * v.x, 0.125f * v.y, hi, lo);
            *(uint32_t*)&g_qhi[off] = hi;
            *(uint32_t*)&g_qlo[off] = lo;
          } else if (part == 1) {
            __half2 kk(__float2half_rn(v.x), __float2half_rn(v.y));
            *(__half2*)&g_k[off] = kk;
          } else {
            size_t vt0 = ((size_t)bh * 64 + d) * 1024 + s;
            size_t vt1 = ((size_t)bh * 64 + d + 1) * 1024 + s;
            g_vt[vt0] = __float2half_rn(v.x);
            g_vt[vt1] = __float2half_rn(v.y);
          }
        } else {
          *(float2*)(out + (size_t)m * 768 + n) = v;
        }
      }
    }
  }
}

// ---------------------------------------------------------------------------
// Kernel 2: decomposed rel-pos bias tables (unchanged; fp32).
// ---------------------------------------------------------------------------
#define RSWZ(r, c4) ((c4) ^ ((((r) >> 2) & 7) << 2))

__global__ __launch_bounds__(256) void relbias_kernel(
    const float* __restrict__ rph, const float* __restrict__ rpw) {
  __shared__ float Qs[32][68];
  __shared__ float Rhs[32][64];
  __shared__ float Rws[63][64];
  const int h = blockIdx.x;
  const int bh = blockIdx.y;
  const int tid = threadIdx.x;

  for (int idx = tid; idx < 32 * 16; idx += 256) {
    int w = idx >> 4, c4 = (idx & 15) << 2;
    *(float4*)&Qs[w][c4] =
        *(const float4*)&g_q[((size_t)bh * 1024 + h * 32 + w) * 64 + c4];
    *(float4*)&Rhs[w][RSWZ(w, c4)] = *(const float4*)&rph[(h + w) * 64 + c4];
  }
  for (int idx = tid; idx < 63 * 16; idx += 256) {
    int r = idx >> 4, c4 = (idx & 15) << 2;
    *(float4*)&Rws[r][RSWZ(r, c4)] = *(const float4*)&rpw[r * 64 + c4];
  }
  __syncthreads();

  const int w = tid >> 3;
  const int k0 = (tid & 7) << 2;
  float ah[4] = {0, 0, 0, 0}, aw[4] = {0, 0, 0, 0};
#pragma unroll
  for (int d4 = 0; d4 < 64; d4 += 4) {
    float4 qv = *(const float4*)&Qs[w][d4];
#pragma unroll
    for (int j = 0; j < 4; j++) {
      int rh_r = 31 - (k0 + j);
      float4 rh = *(const float4*)&Rhs[rh_r][RSWZ(rh_r, d4)];
      ah[j] += qv.x * rh.x + qv.y * rh.y + qv.z * rh.z + qv.w * rh.w;
      int rw_r = w - (k0 + j) + 31;
      float4 rw = *(const float4*)&Rws[rw_r][RSWZ(rw_r, d4)];
      aw[j] += qv.x * rw.x + qv.y * rw.y + qv.z * rw.z + qv.w * rw.w;
    }
  }
  size_t ob = (((size_t)bh * 32 + h) * 32 + w) * 32 + k0;
#pragma unroll
  for (int j = 0; j < 4; j++) {
    g_relh[ob + j] = ah[j];
    g_relw[ob + j] = aw[j];
  }
}

// ---------------------------------------------------------------------------
// Kernel 3: flash attention, fp16 2-product, 128x64 q-tile.
// 256 threads = 8 warps; warp owns 16 q-rows. Q hi/lo frags in registers,
// K/V single fp16 in cp.async double-buffered smem. V pre-transposed.
// Writes O directly as fp16 hi/lo in proj-GEMM layout.
// ---------------------------------------------------------------------------
#define KSTR 72                      // fp16 smem stride
#define ATT_TILE (64 * KSTR * 2)     // 9216 B per array
#define ATT_BUF (2 * ATT_TILE)       // K,V one stage
#define ATT_BH_OFF (2 * ATT_BUF)
#define ATT_SMEM (2 * ATT_BUF + 128 * 32 * 4)

__global__ __launch_bounds__(256, 1) void attn_mma_kernel() {
  extern __shared__ char dsm[];
  const uint32_t smb = smem_u32(dsm);
  float* sBh = (float*)(dsm + ATT_BH_OFF);

  const int bh = blockIdx.y;
  const int q0 = blockIdx.x * 128;
  const int tid = threadIdx.x;
  const int w = tid >> 5, lane = tid & 31;
  const int g = lane >> 2, t = lane & 3;
  const int b = bh / 12, head = bh - b * 12;

  auto prefetch = [&](int kt, int bb) {
    uint32_t sb = smb + bb * ATT_BUF;
#pragma unroll
    for (int idx = tid; idx < 512; idx += 256) {
      int r = idx >> 3, qc = idx & 7;
      size_t gk = ((size_t)bh * 1024 + kt * 64 + r) * 64 + qc * 8;
      size_t gv = ((size_t)bh * 64 + r) * 1024 + kt * 64 + qc * 8;
      uint32_t so = r * (KSTR * 2) + qc * 16;
      cp16(sb + so, g_k + gk);
      cp16(sb + ATT_TILE + so, g_vt + gv);
    }
  };

  prefetch(0, 0);
  CP_COMMIT();

  // rel_h table for this q-tile (128 rows x 32)
  for (int idx = tid; idx < 128 * 8; idx += 256) {
    int r = idx >> 3, c4 = (idx & 7) << 2;
    int s = q0 + r;
    *(float4*)&sBh[r * 32 + c4] = *(const float4*)
        &g_relh[(((size_t)bh * 32 + (s >> 5)) * 32 + (s & 31)) * 32 + c4];
  }

  // Q fragments in registers (rows w*16+g, +8), pre-scaled, hi/lo
  uint32_t qhi[4][4], qlo[4][4];
  {
    const size_t base = ((size_t)bh * 1024 + q0 + w * 16) * 64;
#pragma unroll
    for (int kc = 0; kc < 4; kc++) {
      int col = kc * 16 + 2 * t;
      qhi[kc][0] = *(const uint32_t*)&g_qhi[base + (size_t)g * 64 + col];
      qhi[kc][1] = *(const uint32_t*)&g_qhi[base + (size_t)(g + 8) * 64 + col];
      qhi[kc][2] = *(const uint32_t*)&g_qhi[base + (size_t)g * 64 + col + 8];
      qhi[kc][3] =
          *(const uint32_t*)&g_qhi[base + (size_t)(g + 8) * 64 + col + 8];
      qlo[kc][0] = *(const uint32_t*)&g_qlo[base + (size_t)g * 64 + col];
      qlo[kc][1] = *(const uint32_t*)&g_qlo[base + (size_t)(g + 8) * 64 + col];
      qlo[kc][2] = *(const uint32_t*)&g_qlo[base + (size_t)g * 64 + col + 8];
      qlo[kc][3] =
          *(const uint32_t*)&g_qlo[base + (size_t)(g + 8) * 64 + col + 8];
    }
  }

  // rel_w bias registers: bw[half][ni&3][col01]
  float bw[2][4][2];
#pragma unroll
  for (int hf = 0; hf < 2; hf++) {
    int s = q0 + w * 16 + g + hf * 8;
    const float* src =
        &g_relw[(((size_t)bh * 32 + (s >> 5)) * 32 + (s & 31)) * 32];
#pragma unroll
    for (int nm = 0; nm < 4; nm++) {
      bw[hf][nm][0] = src[nm * 8 + 2 * t];
      bw[hf][nm][1] = src[nm * 8 + 2 * t + 1];
    }
  }

  float m0 = -INFINITY, m1 = -INFINITY, l0 = 0.f, l1 = 0.f;
  float o[8][4];
#pragma unroll
  for (int ni = 0; ni < 8; ni++)
#pragma unroll
    for (int r = 0; r < 4; r++) o[ni][r] = 0.f;

  for (int kt = 0; kt < 16; kt++) {
    const int bb = kt & 1;
    if (kt + 1 < 16) {
      prefetch(kt + 1, bb ^ 1);
      CP_COMMIT();
      CP_WAIT1();
    } else {
      CP_WAIT0();
    }
    __syncthreads();
    const __half* sK = (const __half*)(dsm + bb * ATT_BUF);
    const __half* sV = (const __half*)(dsm + bb * ATT_BUF + ATT_TILE);

    // ---- S = (scaled Q) K^T, 2 products (K loaded once) ----
    float sc[8][4];
#pragma unroll
    for (int ni = 0; ni < 8; ni++)
#pragma unroll
      for (int r = 0; r < 4; r++) sc[ni][r] = 0.f;
#pragma unroll
    for (int kc = 0; kc < 4; kc++) {
      const int c0 = kc * 16 + 2 * t;
#pragma unroll
      for (int ni = 0; ni < 8; ni++) {
        const int rb = (ni * 8 + g) * KSTR;
        uint32_t bk[2];
        bk[0] = *(const uint32_t*)&sK[rb + c0];
        bk[1] = *(const uint32_t*)&sK[rb + c0 + 8];
        mma16816h(sc[ni], qhi[kc], bk);
        mma16816h(sc[ni], qlo[kc], bk);
      }
    }

    // ---- bias + online softmax (rows g and g+8) ----
    const float bhA0 = sBh[(w * 16 + g) * 32 + 2 * kt];
    const float bhA1 = sBh[(w * 16 + g) * 32 + 2 * kt + 1];
    const float bhB0 = sBh[(w * 16 + g + 8) * 32 + 2 * kt];
    const float bhB1 = sBh[(w * 16 + g + 8) * 32 + 2 * kt + 1];
    float mx0 = -INFINITY, mx1 = -INFINITY;
#pragma unroll
    for (int ni = 0; ni < 8; ni++) {
      const float ba = (ni < 4) ? bhA0 : bhA1;
      const float bb2 = (ni < 4) ? bhB0 : bhB1;
      const int nm = ni & 3;
      sc[ni][0] += ba + bw[0][nm][0];
      sc[ni][1] += ba + bw[0][nm][1];
      sc[ni][2] += bb2 + bw[1][nm][0];
      sc[ni][3] += bb2 + bw[1][nm][1];
      mx0 = fmaxf(mx0, fmaxf(sc[ni][0], sc[ni][1]));
      mx1 = fmaxf(mx1, fmaxf(sc[ni][2], sc[ni][3]));
    }
    mx0 = fmaxf(mx0, __shfl_xor_sync(0xffffffffu, mx0, 1));
    mx0 = fmaxf(mx0, __shfl_xor_sync(0xffffffffu, mx0, 2));
    mx1 = fmaxf(mx1, __shfl_xor_sync(0xffffffffu, mx1, 1));
    mx1 = fmaxf(mx1, __shfl_xor_sync(0xffffffffu, mx1, 2));
    const float mn0 = fmaxf(m0, mx0), mn1 = fmaxf(m1, mx1);
    const float a0 = __expf(m0 - mn0), a1 = __expf(m1 - mn1);
    float sum0 = 0.f, sum1 = 0.f;
#pragma unroll
    for (int ni = 0; ni < 8; ni++) {
      sc[ni][0] = __expf(sc[ni][0] - mn0);
      sc[ni][1] = __expf(sc[ni][1] - mn0);
      sc[ni][2] = __expf(sc[ni][2] - mn1);
      sc[ni][3] = __expf(sc[ni][3] - mn1);
      sum0 += sc[ni][0] + sc[ni][1];
      sum1 += sc[ni][2] + sc[ni][3];
    }
    sum0 += __shfl_xor_sync(0xffffffffu, sum0, 1);
    sum0 += __shfl_xor_sync(0xffffffffu, sum0, 2);
    sum1 += __shfl_xor_sync(0xffffffffu, sum1, 1);
    sum1 += __shfl_xor_sync(0xffffffffu, sum1, 2);
    l0 = l0 * a0 + sum0;
    l1 = l1 * a1 + sum1;
    m0 = mn0;
    m1 = mn1;
#pragma unroll
    for (int ni = 0; ni < 8; ni++) {
      o[ni][0] *= a0;
      o[ni][1] *= a0;
      o[ni][2] *= a1;
      o[ni][3] *= a1;
    }

    // ---- pack P hi/lo (A-frags reuse S C-frags) ----
    uint32_t phi[4][4], plo[4][4];
#pragma unroll
    for (int kc = 0; kc < 4; kc++) {
      const int nA = 2 * kc, nB = 2 * kc + 1;
      split_pack_h(sc[nA][0], sc[nA][1], phi[kc][0], plo[kc][0]);
      split_pack_h(sc[nA][2], sc[nA][3], phi[kc][1], plo[kc][1]);
      split_pack_h(sc[nB][0], sc[nB][1], phi[kc][2], plo[kc][2]);
      split_pack_h(sc[nB][2], sc[nB][3], phi[kc][3], plo[kc][3]);
    }

    // ---- O += P V  (V loaded once, 2 products) ----
#pragma unroll
    for (int kc = 0; kc < 4; kc++) {
      const int c0 = kc * 16 + 2 * t;
#pragma unroll
      for (int ni = 0; ni < 8; ni++) {
        const int rb = (ni * 8 + g) * KSTR;
        uint32_t bv[2];
        bv[0] = *(const uint32_t*)&sV[rb + c0];
        bv[1] = *(const uint32_t*)&sV[rb + c0 + 8];
        mma16816h(o[ni], phi[kc], bv);
        mma16816h(o[ni], plo[kc], bv);
      }
    }
    __syncthreads();
  }

  // epilogue: normalize and write fp16 hi/lo in proj layout [b*1024+s][768]
  const float inv0 = 1.f / l0, inv1 = 1.f / l1;
  const int s0 = q0 + w * 16 + g, s1 = s0 + 8;
  const size_t ob0 = ((size_t)(b * 1024 + s0)) * 768 + head * 64;
  const size_t ob1 = ((size_t)(b * 1024 + s1)) * 768 + head * 64;
#pragma unroll
  for (int ni = 0; ni < 8; ni++) {
    const int d = ni * 8 + 2 * t;
    uint32_t hi, lo;
    split_pack_h(o[ni][0] * inv0, o[ni][1] * inv0, hi, lo);
    *(uint32_t*)&g_ohi[ob0 + d] = hi;
    *(uint32_t*)&g_olo[ob0 + d] = lo;
    split_pack_h(o[ni][2] * inv1, o[ni][3] * inv1, hi, lo);
    *(uint32_t*)&g_ohi[ob1 + d] = hi;
    *(uint32_t*)&g_olo[ob1 + d] = lo;
  }
}

// ---------------------------------------------------------------------------
extern "C" void kernel_launch(void* const* d_in, const int* in_sizes, int n_in,
                              void* d_out, int out_size) {
  const float* x      = (const float*)d_in[0];
  const float* qkv_w  = (const float*)d_in[1];
  const float* qkv_b  = (const float*)d_in[2];
  const float* proj_w = (const float*)d_in[3];
  const float* proj_b = (const float*)d_in[4];
  const float* rph    = (const float*)d_in[5];
  const float* rpw    = (const float*)d_in[6];
  float* out = (float*)d_out;

  cudaFuncSetAttribute(hmma_gemm_kernel<0>,
                       cudaFuncAttributeMaxDynamicSharedMemorySize, GEMM_SMEM);
  cudaFuncSetAttribute(hmma_gemm_kernel<1>,
                       cudaFuncAttributeMaxDynamicSharedMemorySize, GEMM_SMEM);
  cudaFuncSetAttribute(attn_mma_kernel,
                       cudaFuncAttributeMaxDynamicSharedMemorySize, ATT_SMEM);

  __half *xhi, *xlo, *wq, *ohi, *olo, *wp;
  cudaGetSymbolAddress((void**)&xhi, g_xhi);
  cudaGetSymbolAddress((void**)&xlo, g_xlo);
  cudaGetSymbolAddress((void**)&wq, g_wqkv);
  cudaGetSymbolAddress((void**)&ohi, g_ohi);
  cudaGetSymbolAddress((void**)&olo, g_olo);
  cudaGetSymbolAddress((void**)&wp, g_wproj);

  splith_kernel<<<8192 * 768 / 4 / 256, 256>>>(x, xhi, xlo, 8192 * 768 / 4);
  convh_kernel<<<2304 * 768 / 4 / 256, 256>>>(qkv_w, wq, 2304 * 768 / 4);
  hmma_gemm_kernel<0><<<dim3(18, 64), 256, GEMM_SMEM>>>(xhi, xlo, wq, qkv_b,
                                                        nullptr);
  relbias_kernel<<<dim3(32, 96), 256>>>(rph, rpw);
  attn_mma_kernel<<<dim3(8, 96), 256, ATT_SMEM>>>();
  convh_kernel<<<768 * 768 / 4 / 256, 256>>>(proj_w, wp, 768 * 768 / 4);
  hmma_gemm_kernel<1><<<dim3(6, 64), 256, GEMM_SMEM>>>(ohi, olo, wp, proj_b,
                                                       out);
}

// round 7
// speedup vs baseline: 5.3968x; 1.5002x over previous
#include <cuda_runtime.h>
#include <cuda_fp16.h>
#include <math.h>
#include <cstdint>

// ---------------------------------------------------------------------------
// Problem constants
//   x:(8,32,32,768)  qkv_w:(2304,768)  qkv_b:(2304)
//   proj_w:(768,768) proj_b:(768)  rel_pos_h/w:(63,64)
//   NH=12 HD=64 S=1024 B*NH=96, out:(8,32,32,768) fp32
// ---------------------------------------------------------------------------
namespace {
constexpr int kHD = 64;
constexpr int kS  = 1024;
constexpr int kBH = 96;
}

// Scratch (__device__ globals: allocation-free per harness rules)
__device__ float g_q[kBH * kS * kHD];          // fp32 q (relbias input)
__device__ float g_relh[kBH * 32 * 32 * 32];
__device__ float g_relw[kBH * 32 * 32 * 32];

// fp16 operands (single precision product everywhere)
__device__ __half g_xh[8192 * 768];
__device__ __half g_wqkv[2304 * 768];
__device__ __half g_oh[8192 * 768];
__device__ __half g_wproj[768 * 768];
// attention operands (written by qkv epilogue)
__device__ __half g_qh[kBH * kS * kHD];   // pre-scaled by 0.125
__device__ __half g_k[kBH * kS * kHD];
__device__ __half g_vt[kBH * kHD * kS];   // [bh][d][seq] transposed

// ---------------------------------------------------------------------------
// PTX helpers
// ---------------------------------------------------------------------------
__device__ __forceinline__ void mma16816h(float* c, const uint32_t* a,
                                          const uint32_t* b) {
  asm volatile(
      "mma.sync.aligned.m16n8k16.row.col.f32.f16.f16.f32 "
      "{%0,%1,%2,%3}, {%4,%5,%6,%7}, {%8,%9}, {%0,%1,%2,%3};"
      : "+f"(c[0]), "+f"(c[1]), "+f"(c[2]), "+f"(c[3])
      : "r"(a[0]), "r"(a[1]), "r"(a[2]), "r"(a[3]), "r"(b[0]), "r"(b[1]));
}

__device__ __forceinline__ uint32_t smem_u32(const void* p) {
  uint32_t a;
  asm("{ .reg .u64 t; cvta.to.shared.u64 t, %1; cvt.u32.u64 %0, t; }"
      : "=r"(a) : "l"(p));
  return a;
}
__device__ __forceinline__ void cp16(uint32_t s, const void* g) {
  asm volatile("cp.async.cg.shared.global [%0], [%1], 16;" ::"r"(s), "l"(g)
               : "memory");
}
#define CP_COMMIT() asm volatile("cp.async.commit_group;" ::: "memory")
#define CP_WAIT1() asm volatile("cp.async.wait_group 1;" ::: "memory")
#define CP_WAIT0() asm volatile("cp.async.wait_group 0;" ::: "memory")

__device__ __forceinline__ uint32_t pack_h2(float x0, float x1) {
  __half2 h = __floats2half2_rn(x0, x1);
  return *(uint32_t*)&h;
}

// ---------------------------------------------------------------------------
// fp32 -> fp16 (contiguous)
// ---------------------------------------------------------------------------
__global__ __launch_bounds__(256) void convh_kernel(
    const float* __restrict__ src, __half* __restrict__ dst, int n4) {
  int i = blockIdx.x * 256 + threadIdx.x;
  if (i >= n4) return;
  float4 f = ((const float4*)src)[i];
  uint2 u;
  u.x = pack_h2(f.x, f.y);
  u.y = pack_h2(f.z, f.w);
  ((uint2*)dst)[i] = u;
}

// ---------------------------------------------------------------------------
// HMMA GEMM: C[128,128] = A*B^T  (K=768, fp32 acc, fp16 operands)
// 256 threads = 8 warps (2 m x 4 n), warp tile 64x32, BK=32.
// cp.async double-buffered smem.
// MODE 0: qkv epilogue (scatter q fp32 + q/k/vt fp16)
// MODE 1: proj epilogue (row-major fp32 out + bias)
// ---------------------------------------------------------------------------
#define SSTR 40                  // smem k-stride in fp16 units
#define GEMM_TILE 10240          // 128*SSTR*2 bytes
#define GEMM_BUF (2 * GEMM_TILE) // one stage: A,B
#define GEMM_SMEM (2 * GEMM_BUF)

template <int MODE>
__global__ __launch_bounds__(256) void hmma_gemm_kernel(
    const __half* __restrict__ A, const __half* __restrict__ B,
    const float* __restrict__ bias, float* __restrict__ out) {
  extern __shared__ char dsm[];
  const uint32_t smb = smem_u32(dsm);
  const int tid = threadIdx.x;
  const int wid = tid >> 5, lane = tid & 31;
  const int wm = wid & 1;
  const int wn = wid >> 1;
  const int g = lane >> 2, t = lane & 3;
  const int bn = blockIdx.x, bm = blockIdx.y;
  const int arow0 = bm * 128, brow0 = bn * 128;

  auto prefetch = [&](int kt, int bb) {
    uint32_t sb = smb + bb * GEMM_BUF;
#pragma unroll
    for (int c = tid; c < 512; c += 256) {
      int row = c >> 2, q = c & 3;
      size_t ga = (size_t)(arow0 + row) * 768 + kt * 32 + q * 8;
      size_t gb = (size_t)(brow0 + row) * 768 + kt * 32 + q * 8;
      uint32_t so = row * (SSTR * 2) + q * 16;
      cp16(sb + so, A + ga);
      cp16(sb + GEMM_TILE + so, B + gb);
    }
  };

  float acc[4][4][4];
#pragma unroll
  for (int mi = 0; mi < 4; mi++)
#pragma unroll
    for (int ni = 0; ni < 4; ni++)
#pragma unroll
      for (int r = 0; r < 4; r++) acc[mi][ni][r] = 0.f;

  prefetch(0, 0);
  CP_COMMIT();

  for (int kt = 0; kt < 24; ++kt) {
    const int bb = kt & 1;
    if (kt + 1 < 24) {
      prefetch(kt + 1, bb ^ 1);
      CP_COMMIT();
      CP_WAIT1();
    } else {
      CP_WAIT0();
    }
    __syncthreads();
    const __half* sA = (const __half*)(dsm + bb * GEMM_BUF);
    const __half* sB = (const __half*)(dsm + bb * GEMM_BUF + GEMM_TILE);

#pragma unroll
    for (int ks = 0; ks < 32; ks += 16) {
      uint32_t a[4][4], b[4][2];
      const int acol = ks + 2 * t;
#pragma unroll
      for (int ni = 0; ni < 4; ni++) {
        int r0 = (wn * 32 + ni * 8 + g) * SSTR;
        b[ni][0] = *(const uint32_t*)&sB[r0 + acol];
        b[ni][1] = *(const uint32_t*)&sB[r0 + acol + 8];
      }
#pragma unroll
      for (int mi = 0; mi < 4; mi++) {
        int r0 = (wm * 64 + mi * 16 + g) * SSTR;
        a[mi][0] = *(const uint32_t*)&sA[r0 + acol];
        a[mi][1] = *(const uint32_t*)&sA[r0 + 8 * SSTR + acol];
        a[mi][2] = *(const uint32_t*)&sA[r0 + acol + 8];
        a[mi][3] = *(const uint32_t*)&sA[r0 + 8 * SSTR + acol + 8];
      }
#pragma unroll
      for (int mi = 0; mi < 4; mi++)
#pragma unroll
        for (int ni = 0; ni < 4; ni++) mma16816h(acc[mi][ni], a[mi], b[ni]);
    }
    __syncthreads();
  }

  // Epilogue. c0,c1 -> (row g, cols 2t,2t+1); c2,c3 -> row g+8.
#pragma unroll
  for (int mi = 0; mi < 4; mi++) {
#pragma unroll
    for (int ni = 0; ni < 4; ni++) {
      int n = bn * 128 + wn * 32 + ni * 8 + 2 * t;
      float b0 = bias[n], b1 = bias[n + 1];
#pragma unroll
      for (int half = 0; half < 2; half++) {
        int m = bm * 128 + wm * 64 + mi * 16 + g + half * 8;
        float2 v;
        v.x = acc[mi][ni][half * 2 + 0] + b0;
        v.y = acc[mi][ni][half * 2 + 1] + b1;
        if (MODE == 0) {
          int part = n / 768;
          int rem = n - part * 768;
          int head = rem >> 6, d = rem & 63;
          int bb2 = m >> 10, s = m & 1023;
          int bh = bb2 * 12 + head;
          size_t off = ((size_t)bh * 1024 + s) * 64 + d;
          if (part == 0) {
            *(float2*)(g_q + off) = v;
            *(uint32_t*)&g_qh[off] = pack_h2(0.125f * v.x, 0.125f * v.y);
          } else if (part == 1) {
            *(uint32_t*)&g_k[off] = pack_h2(v.x, v.y);
          } else {
            size_t vt0 = ((size_t)bh * 64 + d) * 1024 + s;
            size_t vt1 = ((size_t)bh * 64 + d + 1) * 1024 + s;
            g_vt[vt0] = __float2half_rn(v.x);
            g_vt[vt1] = __float2half_rn(v.y);
          }
        } else {
          *(float2*)(out + (size_t)m * 768 + n) = v;
        }
      }
    }
  }
}

// ---------------------------------------------------------------------------
// Kernel 2: decomposed rel-pos bias tables (fp32, swizzled smem).
// ---------------------------------------------------------------------------
#define RSWZ(r, c4) ((c4) ^ ((((r) >> 2) & 7) << 2))

__global__ __launch_bounds__(256) void relbias_kernel(
    const float* __restrict__ rph, const float* __restrict__ rpw) {
  __shared__ float Qs[32][68];
  __shared__ float Rhs[32][64];
  __shared__ float Rws[63][64];
  const int h = blockIdx.x;
  const int bh = blockIdx.y;
  const int tid = threadIdx.x;

  for (int idx = tid; idx < 32 * 16; idx += 256) {
    int w = idx >> 4, c4 = (idx & 15) << 2;
    *(float4*)&Qs[w][c4] =
        *(const float4*)&g_q[((size_t)bh * 1024 + h * 32 + w) * 64 + c4];
    *(float4*)&Rhs[w][RSWZ(w, c4)] = *(const float4*)&rph[(h + w) * 64 + c4];
  }
  for (int idx = tid; idx < 63 * 16; idx += 256) {
    int r = idx >> 4, c4 = (idx & 15) << 2;
    *(float4*)&Rws[r][RSWZ(r, c4)] = *(const float4*)&rpw[r * 64 + c4];
  }
  __syncthreads();

  const int w = tid >> 3;
  const int k0 = (tid & 7) << 2;
  float ah[4] = {0, 0, 0, 0}, aw[4] = {0, 0, 0, 0};
#pragma unroll
  for (int d4 = 0; d4 < 64; d4 += 4) {
    float4 qv = *(const float4*)&Qs[w][d4];
#pragma unroll
    for (int j = 0; j < 4; j++) {
      int rh_r = 31 - (k0 + j);
      float4 rh = *(const float4*)&Rhs[rh_r][RSWZ(rh_r, d4)];
      ah[j] += qv.x * rh.x + qv.y * rh.y + qv.z * rh.z + qv.w * rh.w;
      int rw_r = w - (k0 + j) + 31;
      float4 rw = *(const float4*)&Rws[rw_r][RSWZ(rw_r, d4)];
      aw[j] += qv.x * rw.x + qv.y * rw.y + qv.z * rw.z + qv.w * rw.w;
    }
  }
  size_t ob = (((size_t)bh * 32 + h) * 32 + w) * 32 + k0;
#pragma unroll
  for (int j = 0; j < 4; j++) {
    g_relh[ob + j] = ah[j];
    g_relw[ob + j] = aw[j];
  }
}

// ---------------------------------------------------------------------------
// Kernel 3: flash attention, single fp16 product, 128x64 q-tile.
// 256 threads = 8 warps; warp owns 16 q-rows. Q frags in registers,
// K/V fp16 in cp.async double-buffered smem. V pre-transposed.
// Writes O directly as fp16 in proj-GEMM layout.
// ---------------------------------------------------------------------------
#define KSTR 72                      // fp16 smem stride
#define ATT_TILE (64 * KSTR * 2)     // 9216 B per array
#define ATT_BUF (2 * ATT_TILE)       // K,V one stage
#define ATT_BH_OFF (2 * ATT_BUF)
#define ATT_SMEM (2 * ATT_BUF + 128 * 32 * 4)

__global__ __launch_bounds__(256) void attn_mma_kernel() {
  extern __shared__ char dsm[];
  const uint32_t smb = smem_u32(dsm);
  float* sBh = (float*)(dsm + ATT_BH_OFF);

  const int bh = blockIdx.y;
  const int q0 = blockIdx.x * 128;
  const int tid = threadIdx.x;
  const int w = tid >> 5, lane = tid & 31;
  const int g = lane >> 2, t = lane & 3;
  const int b = bh / 12, head = bh - b * 12;

  auto prefetch = [&](int kt, int bb) {
    uint32_t sb = smb + bb * ATT_BUF;
#pragma unroll
    for (int idx = tid; idx < 512; idx += 256) {
      int r = idx >> 3, qc = idx & 7;
      size_t gk = ((size_t)bh * 1024 + kt * 64 + r) * 64 + qc * 8;
      size_t gv = ((size_t)bh * 64 + r) * 1024 + kt * 64 + qc * 8;
      uint32_t so = r * (KSTR * 2) + qc * 16;
      cp16(sb + so, g_k + gk);
      cp16(sb + ATT_TILE + so, g_vt + gv);
    }
  };

  prefetch(0, 0);
  CP_COMMIT();

  // rel_h table for this q-tile (128 rows x 32)
  for (int idx = tid; idx < 128 * 8; idx += 256) {
    int r = idx >> 3, c4 = (idx & 7) << 2;
    int s = q0 + r;
    *(float4*)&sBh[r * 32 + c4] = *(const float4*)
        &g_relh[(((size_t)bh * 32 + (s >> 5)) * 32 + (s & 31)) * 32 + c4];
  }

  // Q fragments in registers (rows w*16+g, +8), pre-scaled
  uint32_t qf[4][4];
  {
    const size_t base = ((size_t)bh * 1024 + q0 + w * 16) * 64;
#pragma unroll
    for (int kc = 0; kc < 4; kc++) {
      int col = kc * 16 + 2 * t;
      qf[kc][0] = *(const uint32_t*)&g_qh[base + (size_t)g * 64 + col];
      qf[kc][1] = *(const uint32_t*)&g_qh[base + (size_t)(g + 8) * 64 + col];
      qf[kc][2] = *(const uint32_t*)&g_qh[base + (size_t)g * 64 + col + 8];
      qf[kc][3] =
          *(const uint32_t*)&g_qh[base + (size_t)(g + 8) * 64 + col + 8];
    }
  }

  // rel_w bias registers: bw[half][ni&3][col01]
  float bw[2][4][2];
#pragma unroll
  for (int hf = 0; hf < 2; hf++) {
    int s = q0 + w * 16 + g + hf * 8;
    const float* src =
        &g_relw[(((size_t)bh * 32 + (s >> 5)) * 32 + (s & 31)) * 32];
#pragma unroll
    for (int nm = 0; nm < 4; nm++) {
      bw[hf][nm][0] = src[nm * 8 + 2 * t];
      bw[hf][nm][1] = src[nm * 8 + 2 * t + 1];
    }
  }

  float m0 = -INFINITY, m1 = -INFINITY, l0 = 0.f, l1 = 0.f;
  float o[8][4];
#pragma unroll
  for (int ni = 0; ni < 8; ni++)
#pragma unroll
    for (int r = 0; r < 4; r++) o[ni][r] = 0.f;

  for (int kt = 0; kt < 16; kt++) {
    const int bb = kt & 1;
    if (kt + 1 < 16) {
      prefetch(kt + 1, bb ^ 1);
      CP_COMMIT();
      CP_WAIT1();
    } else {
      CP_WAIT0();
    }
    __syncthreads();
    const __half* sK = (const __half*)(dsm + bb * ATT_BUF);
    const __half* sV = (const __half*)(dsm + bb * ATT_BUF + ATT_TILE);

    // ---- S = (scaled Q) K^T ----
    float sc[8][4];
#pragma unroll
    for (int ni = 0; ni < 8; ni++)
#pragma unroll
      for (int r = 0; r < 4; r++) sc[ni][r] = 0.f;
#pragma unroll
    for (int kc = 0; kc < 4; kc++) {
      const int c0 = kc * 16 + 2 * t;
#pragma unroll
      for (int ni = 0; ni < 8; ni++) {
        const int rb = (ni * 8 + g) * KSTR;
        uint32_t bk[2];
        bk[0] = *(const uint32_t*)&sK[rb + c0];
        bk[1] = *(const uint32_t*)&sK[rb + c0 + 8];
        mma16816h(sc[ni], qf[kc], bk);
      }
    }

    // ---- bias + online softmax (rows g and g+8) ----
    const float bhA0 = sBh[(w * 16 + g) * 32 + 2 * kt];
    const float bhA1 = sBh[(w * 16 + g) * 32 + 2 * kt + 1];
    const float bhB0 = sBh[(w * 16 + g + 8) * 32 + 2 * kt];
    const float bhB1 = sBh[(w * 16 + g + 8) * 32 + 2 * kt + 1];
    float mx0 = -INFINITY, mx1 = -INFINITY;
#pragma unroll
    for (int ni = 0; ni < 8; ni++) {
      const float ba = (ni < 4) ? bhA0 : bhA1;
      const float bb2 = (ni < 4) ? bhB0 : bhB1;
      const int nm = ni & 3;
      sc[ni][0] += ba + bw[0][nm][0];
      sc[ni][1] += ba + bw[0][nm][1];
      sc[ni][2] += bb2 + bw[1][nm][0];
      sc[ni][3] += bb2 + bw[1][nm][1];
      mx0 = fmaxf(mx0, fmaxf(sc[ni][0], sc[ni][1]));
      mx1 = fmaxf(mx1, fmaxf(sc[ni][2], sc[ni][3]));
    }
    mx0 = fmaxf(mx0, __shfl_xor_sync(0xffffffffu, mx0, 1));
    mx0 = fmaxf(mx0, __shfl_xor_sync(0xffffffffu, mx0, 2));
    mx1 = fmaxf(mx1, __shfl_xor_sync(0xffffffffu, mx1, 1));
    mx1 = fmaxf(mx1, __shfl_xor_sync(0xffffffffu, mx1, 2));
    const float mn0 = fmaxf(m0, mx0), mn1 = fmaxf(m1, mx1);
    const float a0 = __expf(m0 - mn0), a1 = __expf(m1 - mn1);
    float sum0 = 0.f, sum1 = 0.f;
#pragma unroll
    for (int ni = 0; ni < 8; ni++) {
      sc[ni][0] = __expf(sc[ni][0] - mn0);
      sc[ni][1] = __expf(sc[ni][1] - mn0);
      sc[ni][2] = __expf(sc[ni][2] - mn1);
      sc[ni][3] = __expf(sc[ni][3] - mn1);
      sum0 += sc[ni][0] + sc[ni][1];
      sum1 += sc[ni][2] + sc[ni][3];
    }
    sum0 += __shfl_xor_sync(0xffffffffu, sum0, 1);
    sum0 += __shfl_xor_sync(0xffffffffu, sum0, 2);
    sum1 += __shfl_xor_sync(0xffffffffu, sum1, 1);
    sum1 += __shfl_xor_sync(0xffffffffu, sum1, 2);
    l0 = l0 * a0 + sum0;
    l1 = l1 * a1 + sum1;
    m0 = mn0;
    m1 = mn1;
#pragma unroll
    for (int ni = 0; ni < 8; ni++) {
      o[ni][0] *= a0;
      o[ni][1] *= a0;
      o[ni][2] *= a1;
      o[ni][3] *= a1;
    }

    // ---- pack P (A-frags reuse S C-frags) ----
    uint32_t ph[4][4];
#pragma unroll
    for (int kc = 0; kc < 4; kc++) {
      const int nA = 2 * kc, nB = 2 * kc + 1;
      ph[kc][0] = pack_h2(sc[nA][0], sc[nA][1]);
      ph[kc][1] = pack_h2(sc[nA][2], sc[nA][3]);
      ph[kc][2] = pack_h2(sc[nB][0], sc[nB][1]);
      ph[kc][3] = pack_h2(sc[nB][2], sc[nB][3]);
    }

    // ---- O += P V ----
#pragma unroll
    for (int kc = 0; kc < 4; kc++) {
      const int c0 = kc * 16 + 2 * t;
#pragma unroll
      for (int ni = 0; ni < 8; ni++) {
        const int rb = (ni * 8 + g) * KSTR;
        uint32_t bv[2];
        bv[0] = *(const uint32_t*)&sV[rb + c0];
        bv[1] = *(const uint32_t*)&sV[rb + c0 + 8];
        mma16816h(o[ni], ph[kc], bv);
      }
    }
    __syncthreads();
  }

  // epilogue: normalize and write fp16 in proj layout [b*1024+s][768]
  const float inv0 = 1.f / l0, inv1 = 1.f / l1;
  const int s0 = q0 + w * 16 + g, s1 = s0 + 8;
  const size_t ob0 = ((size_t)(b * 1024 + s0)) * 768 + head * 64;
  const size_t ob1 = ((size_t)(b * 1024 + s1)) * 768 + head * 64;
#pragma unroll
  for (int ni = 0; ni < 8; ni++) {
    const int d = ni * 8 + 2 * t;
    *(uint32_t*)&g_oh[ob0 + d] = pack_h2(o[ni][0] * inv0, o[ni][1] * inv0);
    *(uint32_t*)&g_oh[ob1 + d] = pack_h2(o[ni][2] * inv1, o[ni][3] * inv1);
  }
}

// ---------------------------------------------------------------------------
extern "C" void kernel_launch(void* const* d_in, const int* in_sizes, int n_in,
                              void* d_out, int out_size) {
  const float* x      = (const float*)d_in[0];
  const float* qkv_w  = (const float*)d_in[1];
  const float* qkv_b  = (const float*)d_in[2];
  const float* proj_w = (const float*)d_in[3];
  const float* proj_b = (const float*)d_in[4];
  const float* rph    = (const float*)d_in[5];
  const float* rpw    = (const float*)d_in[6];
  float* out = (float*)d_out;

  cudaFuncSetAttribute(hmma_gemm_kernel<0>,
                       cudaFuncAttributeMaxDynamicSharedMemorySize, GEMM_SMEM);
  cudaFuncSetAttribute(hmma_gemm_kernel<1>,
                       cudaFuncAttributeMaxDynamicSharedMemorySize, GEMM_SMEM);
  cudaFuncSetAttribute(attn_mma_kernel,
                       cudaFuncAttributeMaxDynamicSharedMemorySize, ATT_SMEM);

  __half *xh, *wq, *oh, *wp;
  cudaGetSymbolAddress((void**)&xh, g_xh);
  cudaGetSymbolAddress((void**)&wq, g_wqkv);
  cudaGetSymbolAddress((void**)&oh, g_oh);
  cudaGetSymbolAddress((void**)&wp, g_wproj);

  convh_kernel<<<8192 * 768 / 4 / 256, 256>>>(x, xh, 8192 * 768 / 4);
  convh_kernel<<<2304 * 768 / 4 / 256, 256>>>(qkv_w, wq, 2304 * 768 / 4);
  convh_kernel<<<768 * 768 / 4 / 256, 256>>>(proj_w, wp, 768 * 768 / 4);
  hmma_gemm_kernel<0><<<dim3(18, 64), 256, GEMM_SMEM>>>(xh, wq, qkv_b,
                                                        nullptr);
  relbias_kernel<<<dim3(32, 96), 256>>>(rph, rpw);
  attn_mma_kernel<<<dim3(8, 96), 256, ATT_SMEM>>>();
  hmma_gemm_kernel<1><<<dim3(6, 64), 256, GEMM_SMEM>>>(oh, wp, proj_b, out);
}

// round 9
// speedup vs baseline: 5.6049x; 1.0386x over previous
#include <cuda_runtime.h>
#include <cuda_fp16.h>
#include <math.h>
#include <cstdint>

// ---------------------------------------------------------------------------
// Problem constants
//   x:(8,32,32,768)  qkv_w:(2304,768)  qkv_b:(2304)
//   proj_w:(768,768) proj_b:(768)  rel_pos_h/w:(63,64)
//   NH=12 HD=64 S=1024 B*NH=96, out:(8,32,32,768) fp32
// ---------------------------------------------------------------------------
namespace {
constexpr int kHD = 64;
constexpr int kS  = 1024;
constexpr int kBH = 96;
}

// Scratch (__device__ globals: allocation-free per harness rules)
__device__ float g_q[kBH * kS * kHD];          // fp32 q (relbias input)
__device__ float g_relh[kBH * 32 * 32 * 32];
__device__ float g_relw[kBH * 32 * 32 * 32];

// fp16 operands
__device__ __half g_xh[8192 * 768];
__device__ __half g_wqkv[2304 * 768];
__device__ __half g_oh[8192 * 768];
__device__ __half g_wproj[768 * 768];
// attention operands (written by qkv epilogue)
__device__ __half g_qh[kBH * kS * kHD];   // pre-scaled by 0.125
__device__ __half g_k[kBH * kS * kHD];
__device__ __half g_vt[kBH * kHD * kS];   // [bh][d][seq] transposed

// ---------------------------------------------------------------------------
// PTX helpers
// ---------------------------------------------------------------------------
__device__ __forceinline__ void mma16816h(float* c, const uint32_t* a,
                                          const uint32_t* b) {
  asm volatile(
      "mma.sync.aligned.m16n8k16.row.col.f32.f16.f16.f32 "
      "{%0,%1,%2,%3}, {%4,%5,%6,%7}, {%8,%9}, {%0,%1,%2,%3};"
      : "+f"(c[0]), "+f"(c[1]), "+f"(c[2]), "+f"(c[3])
      : "r"(a[0]), "r"(a[1]), "r"(a[2]), "r"(a[3]), "r"(b[0]), "r"(b[1]));
}

#define LDSM4(r, addr)                                                  \
  asm volatile(                                                         \
      "ldmatrix.sync.aligned.m8n8.x4.shared.b16 {%0,%1,%2,%3}, [%4];"   \
      : "=r"((r)[0]), "=r"((r)[1]), "=r"((r)[2]), "=r"((r)[3])          \
      : "r"(addr))

__device__ __forceinline__ uint32_t smem_u32(const void* p) {
  uint32_t a;
  asm("{ .reg .u64 t; cvta.to.shared.u64 t, %1; cvt.u32.u64 %0, t; }"
      : "=r"(a) : "l"(p));
  return a;
}
__device__ __forceinline__ void cp16(uint32_t s, const void* g) {
  asm volatile("cp.async.cg.shared.global [%0], [%1], 16;" ::"r"(s), "l"(g)
               : "memory");
}
#define CP_COMMIT() asm volatile("cp.async.commit_group;" ::: "memory")
#define CP_WAIT2() asm volatile("cp.async.wait_group 2;" ::: "memory")
#define CP_WAIT1() asm volatile("cp.async.wait_group 1;" ::: "memory")
#define CP_WAIT0() asm volatile("cp.async.wait_group 0;" ::: "memory")

__device__ __forceinline__ uint32_t pack_h2(float x0, float x1) {
  __half2 h = __floats2half2_rn(x0, x1);
  return *(uint32_t*)&h;
}

// ---------------------------------------------------------------------------
// fp32 -> fp16 (contiguous)
// ---------------------------------------------------------------------------
__global__ __launch_bounds__(256) void convh_kernel(
    const float* __restrict__ src, __half* __restrict__ dst, int n4) {
  int i = blockIdx.x * 256 + threadIdx.x;
  if (i >= n4) return;
  float4 f = ((const float4*)src)[i];
  uint2 u;
  u.x = pack_h2(f.x, f.y);
  u.y = pack_h2(f.z, f.w);
  ((uint2*)dst)[i] = u;
}

// ---------------------------------------------------------------------------
// HMMA GEMM: C[128,128] = A*B^T  (K=768, fp32 acc, fp16 operands)
// 256 threads = 8 warps (2 m x 4 n), warp tile 64x32, BK=32.
// 3-stage cp.async pipeline; ldmatrix fragment loads.
// MODE 0: qkv epilogue (scatter q fp32 + q/k/vt fp16)
// MODE 1: proj epilogue (row-major fp32 out + bias)
// ---------------------------------------------------------------------------
#define SSTR 40                  // smem k-stride in fp16 units (80B, 16B-mult)
#define GEMM_TILE 10240          // 128*SSTR*2 bytes
#define GEMM_BUF (2 * GEMM_TILE) // one stage: A,B
#define GEMM_SMEM (3 * GEMM_BUF)

template <int MODE>
__global__ __launch_bounds__(256) void hmma_gemm_kernel(
    const __half* __restrict__ A, const __half* __restrict__ B,
    const float* __restrict__ bias, float* __restrict__ out) {
  extern __shared__ char dsm[];
  const uint32_t smb = smem_u32(dsm);
  const int tid = threadIdx.x;
  const int wid = tid >> 5, lane = tid & 31;
  const int wm = wid & 1;
  const int wn = wid >> 1;
  const int g = lane >> 2, t = lane & 3;
  const int bn = blockIdx.x, bm = blockIdx.y;
  const int arow0 = bm * 128, brow0 = bn * 128;

  // ldmatrix per-lane offsets (within a stage buffer)
  const uint32_t aoff =
      (uint32_t)(wm * 64 + (lane & 15)) * (SSTR * 2) + (lane >> 4) * 16;
  const uint32_t boff =
      (uint32_t)(wn * 32 + ((lane >> 4) << 3) + (lane & 7)) * (SSTR * 2) +
      ((lane >> 3) & 1) * 16;

  auto prefetch = [&](int kt, int bb) {
    uint32_t sb = smb + bb * GEMM_BUF;
#pragma unroll
    for (int c = tid; c < 512; c += 256) {
      int row = c >> 2, q = c & 3;
      size_t ga = (size_t)(arow0 + row) * 768 + kt * 32 + q * 8;
      size_t gb = (size_t)(brow0 + row) * 768 + kt * 32 + q * 8;
      uint32_t so = row * (SSTR * 2) + q * 16;
      cp16(sb + so, A + ga);
      cp16(sb + GEMM_TILE + so, B + gb);
    }
  };

  float acc[4][4][4];
#pragma unroll
  for (int mi = 0; mi < 4; mi++)
#pragma unroll
    for (int ni = 0; ni < 4; ni++)
#pragma unroll
      for (int r = 0; r < 4; r++) acc[mi][ni][r] = 0.f;

  prefetch(0, 0);
  CP_COMMIT();
  prefetch(1, 1);
  CP_COMMIT();

  for (int kt = 0; kt < 24; ++kt) {
    const int bb = kt % 3;
    if (kt + 2 < 24) {
      prefetch(kt + 2, (kt + 2) % 3);
      CP_COMMIT();
      CP_WAIT2();
    } else if (kt + 1 < 24) {
      CP_WAIT1();
    } else {
      CP_WAIT0();
    }
    __syncthreads();
    const uint32_t sbA = smb + bb * GEMM_BUF;
    const uint32_t sbB = sbA + GEMM_TILE;

#pragma unroll
    for (int ks = 0; ks < 2; ks++) {
      const uint32_t kb = ks * 32;  // 16 halves = 32 bytes
      uint32_t a[4][4];
#pragma unroll
      for (int mi = 0; mi < 4; mi++)
        LDSM4(a[mi], sbA + aoff + mi * (16 * SSTR * 2) + kb);
#pragma unroll
      for (int nip = 0; nip < 2; nip++) {
        uint32_t bfr[4];
        LDSM4(bfr, sbB + boff + nip * (16 * SSTR * 2) + kb);
#pragma unroll
        for (int mi = 0; mi < 4; mi++) {
          mma16816h(acc[mi][2 * nip], a[mi], bfr);
          mma16816h(acc[mi][2 * nip + 1], a[mi], bfr + 2);
        }
      }
    }
    __syncthreads();
  }

  // Epilogue. c0,c1 -> (row g, cols 2t,2t+1); c2,c3 -> row g+8.
#pragma unroll
  for (int mi = 0; mi < 4; mi++) {
#pragma unroll
    for (int ni = 0; ni < 4; ni++) {
      int n = bn * 128 + wn * 32 + ni * 8 + 2 * t;
      float b0 = bias[n], b1 = bias[n + 1];
#pragma unroll
      for (int half = 0; half < 2; half++) {
        int m = bm * 128 + wm * 64 + mi * 16 + g + half * 8;
        float2 v;
        v.x = acc[mi][ni][half * 2 + 0] + b0;
        v.y = acc[mi][ni][half * 2 + 1] + b1;
        if (MODE == 0) {
          int part = n / 768;
          int rem = n - part * 768;
          int head = rem >> 6, d = rem & 63;
          int bb2 = m >> 10, s = m & 1023;
          int bh = bb2 * 12 + head;
          size_t off = ((size_t)bh * 1024 + s) * 64 + d;
          if (part == 0) {
            *(float2*)(g_q + off) = v;
            *(uint32_t*)&g_qh[off] = pack_h2(0.125f * v.x, 0.125f * v.y);
          } else if (part == 1) {
            *(uint32_t*)&g_k[off] = pack_h2(v.x, v.y);
          } else {
            size_t vt0 = ((size_t)bh * 64 + d) * 1024 + s;
            size_t vt1 = ((size_t)bh * 64 + d + 1) * 1024 + s;
            g_vt[vt0] = __float2half_rn(v.x);
            g_vt[vt1] = __float2half_rn(v.y);
          }
        } else {
          *(float2*)(out + (size_t)m * 768 + n) = v;
        }
      }
    }
  }
}

// ---------------------------------------------------------------------------
// Kernel 2: decomposed rel-pos bias tables (fp32, swizzled smem).
// ---------------------------------------------------------------------------
#define RSWZ(r, c4) ((c4) ^ ((((r) >> 2) & 7) << 2))

__global__ __launch_bounds__(256) void relbias_kernel(
    const float* __restrict__ rph, const float* __restrict__ rpw) {
  __shared__ float Qs[32][68];
  __shared__ float Rhs[32][64];
  __shared__ float Rws[63][64];
  const int h = blockIdx.x;
  const int bh = blockIdx.y;
  const int tid = threadIdx.x;

  for (int idx = tid; idx < 32 * 16; idx += 256) {
    int w = idx >> 4, c4 = (idx & 15) << 2;
    *(float4*)&Qs[w][c4] =
        *(const float4*)&g_q[((size_t)bh * 1024 + h * 32 + w) * 64 + c4];
    *(float4*)&Rhs[w][RSWZ(w, c4)] = *(const float4*)&rph[(h + w) * 64 + c4];
  }
  for (int idx = tid; idx < 63 * 16; idx += 256) {
    int r = idx >> 4, c4 = (idx & 15) << 2;
    *(float4*)&Rws[r][RSWZ(r, c4)] = *(const float4*)&rpw[r * 64 + c4];
  }
  __syncthreads();

  const int w = tid >> 3;
  const int k0 = (tid & 7) << 2;
  float ah[4] = {0, 0, 0, 0}, aw[4] = {0, 0, 0, 0};
#pragma unroll
  for (int d4 = 0; d4 < 64; d4 += 4) {
    float4 qv = *(const float4*)&Qs[w][d4];
#pragma unroll
    for (int j = 0; j < 4; j++) {
      int rh_r = 31 - (k0 + j);
      float4 rh = *(const float4*)&Rhs[rh_r][RSWZ(rh_r, d4)];
      ah[j] += qv.x * rh.x + qv.y * rh.y + qv.z * rh.z + qv.w * rh.w;
      int rw_r = w - (k0 + j) + 31;
      float4 rw = *(const float4*)&Rws[rw_r][RSWZ(rw_r, d4)];
      aw[j] += qv.x * rw.x + qv.y * rw.y + qv.z * rw.z + qv.w * rw.w;
    }
  }
  size_t ob = (((size_t)bh * 32 + h) * 32 + w) * 32 + k0;
#pragma unroll
  for (int j = 0; j < 4; j++) {
    g_relh[ob + j] = ah[j];
    g_relw[ob + j] = aw[j];
  }
}

// ---------------------------------------------------------------------------
// Kernel 3: flash attention, single fp16 product, 128x64 q-tile.
// 256 threads = 8 warps; Q frags in registers; ldmatrix K/V fragment loads;
// cp.async double-buffered smem; V pre-transposed [d][seq].
// ---------------------------------------------------------------------------
#define KSTR 72                      // fp16 smem stride (144B, 16B-mult)
#define ATT_TILE (64 * KSTR * 2)     // 9216 B per array
#define ATT_BUF (2 * ATT_TILE)       // K,V one stage
#define ATT_BH_OFF (2 * ATT_BUF)
#define ATT_SMEM (2 * ATT_BUF + 128 * 32 * 4)

__global__ __launch_bounds__(256) void attn_mma_kernel() {
  extern __shared__ char dsm[];
  const uint32_t smb = smem_u32(dsm);
  float* sBh = (float*)(dsm + ATT_BH_OFF);

  const int bh = blockIdx.y;
  const int q0 = blockIdx.x * 128;
  const int tid = threadIdx.x;
  const int w = tid >> 5, lane = tid & 31;
  const int g = lane >> 2, t = lane & 3;
  const int b = bh / 12, head = bh - b * 12;

  // ldmatrix per-lane offset for B-side frags (16-row pair per x4)
  const uint32_t fboff =
      (uint32_t)(((lane >> 4) << 3) + (lane & 7)) * (KSTR * 2) +
      ((lane >> 3) & 1) * 16;

  auto prefetch = [&](int kt, int bb) {
    uint32_t sb = smb + bb * ATT_BUF;
#pragma unroll
    for (int idx = tid; idx < 512; idx += 256) {
      int r = idx >> 3, qc = idx & 7;
      size_t gk = ((size_t)bh * 1024 + kt * 64 + r) * 64 + qc * 8;
      size_t gv = ((size_t)bh * 64 + r) * 1024 + kt * 64 + qc * 8;
      uint32_t so = r * (KSTR * 2) + qc * 16;
      cp16(sb + so, g_k + gk);
      cp16(sb + ATT_TILE + so, g_vt + gv);
    }
  };

  prefetch(0, 0);
  CP_COMMIT();

  // rel_h table for this q-tile (128 rows x 32)
  for (int idx = tid; idx < 128 * 8; idx += 256) {
    int r = idx >> 3, c4 = (idx & 7) << 2;
    int s = q0 + r;
    *(float4*)&sBh[r * 32 + c4] = *(const float4*)
        &g_relh[(((size_t)bh * 32 + (s >> 5)) * 32 + (s & 31)) * 32 + c4];
  }

  // Q fragments in registers (rows w*16+g, +8), pre-scaled
  uint32_t qf[4][4];
  {
    const size_t base = ((size_t)bh * 1024 + q0 + w * 16) * 64;
#pragma unroll
    for (int kc = 0; kc < 4; kc++) {
      int col = kc * 16 + 2 * t;
      qf[kc][0] = *(const uint32_t*)&g_qh[base + (size_t)g * 64 + col];
      qf[kc][1] = *(const uint32_t*)&g_qh[base + (size_t)(g + 8) * 64 + col];
      qf[kc][2] = *(const uint32_t*)&g_qh[base + (size_t)g * 64 + col + 8];
      qf[kc][3] =
          *(const uint32_t*)&g_qh[base + (size_t)(g + 8) * 64 + col + 8];
    }
  }

  // rel_w bias registers: bw[half][ni&3][col01]
  float bw[2][4][2];
#pragma unroll
  for (int hf = 0; hf < 2; hf++) {
    int s = q0 + w * 16 + g + hf * 8;
    const float* src =
        &g_relw[(((size_t)bh * 32 + (s >> 5)) * 32 + (s & 31)) * 32];
#pragma unroll
    for (int nm = 0; nm < 4; nm++) {
      bw[hf][nm][0] = src[nm * 8 + 2 * t];
      bw[hf][nm][1] = src[nm * 8 + 2 * t + 1];
    }
  }

  float m0 = -INFINITY, m1 = -INFINITY, l0 = 0.f, l1 = 0.f;
  float o[8][4];
#pragma unroll
  for (int ni = 0; ni < 8; ni++)
#pragma unroll
    for (int r = 0; r < 4; r++) o[ni][r] = 0.f;

  for (int kt = 0; kt < 16; kt++) {
    const int bb = kt & 1;
    if (kt + 1 < 16) {
      prefetch(kt + 1, bb ^ 1);
      CP_COMMIT();
      CP_WAIT1();
    } else {
      CP_WAIT0();
    }
    __syncthreads();
    const uint32_t sK = smb + bb * ATT_BUF;
    const uint32_t sV = sK + ATT_TILE;

    // ---- S = (scaled Q) K^T ----
    float sc[8][4];
#pragma unroll
    for (int ni = 0; ni < 8; ni++)
#pragma unroll
      for (int r = 0; r < 4; r++) sc[ni][r] = 0.f;
#pragma unroll
    for (int kc = 0; kc < 4; kc++) {
      const uint32_t kb = kc * 32;
#pragma unroll
      for (int nip = 0; nip < 4; nip++) {
        uint32_t bfr[4];
        LDSM4(bfr, sK + fboff + nip * (16 * KSTR * 2) + kb);
        mma16816h(sc[2 * nip], qf[kc], bfr);
        mma16816h(sc[2 * nip + 1], qf[kc], bfr + 2);
      }
    }

    // ---- bias + online softmax (rows g and g+8) ----
    const float bhA0 = sBh[(w * 16 + g) * 32 + 2 * kt];
    const float bhA1 = sBh[(w * 16 + g) * 32 + 2 * kt + 1];
    const float bhB0 = sBh[(w * 16 + g + 8) * 32 + 2 * kt];
    const float bhB1 = sBh[(w * 16 + g + 8) * 32 + 2 * kt + 1];
    float mx0 = -INFINITY, mx1 = -INFINITY;
#pragma unroll
    for (int ni = 0; ni < 8; ni++) {
      const float ba = (ni < 4) ? bhA0 : bhA1;
      const float bb2 = (ni < 4) ? bhB0 : bhB1;
      const int nm = ni & 3;
      sc[ni][0] += ba + bw[0][nm][0];
      sc[ni][1] += ba + bw[0][nm][1];
      sc[ni][2] += bb2 + bw[1][nm][0];
      sc[ni][3] += bb2 + bw[1][nm][1];
      mx0 = fmaxf(mx0, fmaxf(sc[ni][0], sc[ni][1]));
      mx1 = fmaxf(mx1, fmaxf(sc[ni][2], sc[ni][3]));
    }
    mx0 = fmaxf(mx0, __shfl_xor_sync(0xffffffffu, mx0, 1));
    mx0 = fmaxf(mx0, __shfl_xor_sync(0xffffffffu, mx0, 2));
    mx1 = fmaxf(mx1, __shfl_xor_sync(0xffffffffu, mx1, 1));
    mx1 = fmaxf(mx1, __shfl_xor_sync(0xffffffffu, mx1, 2));
    const float mn0 = fmaxf(m0, mx0), mn1 = fmaxf(m1, mx1);
    const float a0 = __expf(m0 - mn0), a1 = __expf(m1 - mn1);
    float sum0 = 0.f, sum1 = 0.f;
#pragma unroll
    for (int ni = 0; ni < 8; ni++) {
      sc[ni][0] = __expf(sc[ni][0] - mn0);
      sc[ni][1] = __expf(sc[ni][1] - mn0);
      sc[ni][2] = __expf(sc[ni][2] - mn1);
      sc[ni][3] = __expf(sc[ni][3] - mn1);
      sum0 += sc[ni][0] + sc[ni][1];
      sum1 += sc[ni][2] + sc[ni][3];
    }
    sum0 += __shfl_xor_sync(0xffffffffu, sum0, 1);
    sum0 += __shfl_xor_sync(0xffffffffu, sum0, 2);
    sum1 += __shfl_xor_sync(0xffffffffu, sum1, 1);
    sum1 += __shfl_xor_sync(0xffffffffu, sum1, 2);
    l0 = l0 * a0 + sum0;
    l1 = l1 * a1 + sum1;
    m0 = mn0;
    m1 = mn1;
#pragma unroll
    for (int ni = 0; ni < 8; ni++) {
      o[ni][0] *= a0;
      o[ni][1] *= a0;
      o[ni][2] *= a1;
      o[ni][3] *= a1;
    }

    // ---- pack P (A-frags reuse S C-frags) ----
    uint32_t ph[4][4];
#pragma unroll
    for (int kc = 0; kc < 4; kc++) {
      const int nA = 2 * kc, nB = 2 * kc + 1;
      ph[kc][0] = pack_h2(sc[nA][0], sc[nA][1]);
      ph[kc][1] = pack_h2(sc[nA][2], sc[nA][3]);
      ph[kc][2] = pack_h2(sc[nB][0], sc[nB][1]);
      ph[kc][3] = pack_h2(sc[nB][2], sc[nB][3]);
    }

    // ---- O += P V ----
#pragma unroll
    for (int kc = 0; kc < 4; kc++) {
      const uint32_t kb = kc * 32;
#pragma unroll
      for (int nip = 0; nip < 4; nip++) {
        uint32_t bfr[4];
        LDSM4(bfr, sV + fboff + nip * (16 * KSTR * 2) + kb);
        mma16816h(o[2 * nip], ph[kc], bfr);
        mma16816h(o[2 * nip + 1], ph[kc], bfr + 2);
      }
    }
    __syncthreads();
  }

  // epilogue: normalize and write fp16 in proj layout [b*1024+s][768]
  const float inv0 = 1.f / l0, inv1 = 1.f / l1;
  const int s0 = q0 + w * 16 + g, s1 = s0 + 8;
  const size_t ob0 = ((size_t)(b * 1024 + s0)) * 768 + head * 64;
  const size_t ob1 = ((size_t)(b * 1024 + s1)) * 768 + head * 64;
#pragma unroll
  for (int ni = 0; ni < 8; ni++) {
    const int d = ni * 8 + 2 * t;
    *(uint32_t*)&g_oh[ob0 + d] = pack_h2(o[ni][0] * inv0, o[ni][1] * inv0);
    *(uint32_t*)&g_oh[ob1 + d] = pack_h2(o[ni][2] * inv1, o[ni][3] * inv1);
  }
}

// ---------------------------------------------------------------------------
extern "C" void kernel_launch(void* const* d_in, const int* in_sizes, int n_in,
                              void* d_out, int out_size) {
  const float* x      = (const float*)d_in[0];
  const float* qkv_w  = (const float*)d_in[1];
  const float* qkv_b  = (const float*)d_in[2];
  const float* proj_w = (const float*)d_in[3];
  const float* proj_b = (const float*)d_in[4];
  const float* rph    = (const float*)d_in[5];
  const float* rpw    = (const float*)d_in[6];
  float* out = (float*)d_out;

  cudaFuncSetAttribute(hmma_gemm_kernel<0>,
                       cudaFuncAttributeMaxDynamicSharedMemorySize, GEMM_SMEM);
  cudaFuncSetAttribute(hmma_gemm_kernel<1>,
                       cudaFuncAttributeMaxDynamicSharedMemorySize, GEMM_SMEM);
  cudaFuncSetAttribute(attn_mma_kernel,
                       cudaFuncAttributeMaxDynamicSharedMemorySize, ATT_SMEM);

  __half *xh, *wq, *oh, *wp;
  cudaGetSymbolAddress((void**)&xh, g_xh);
  cudaGetSymbolAddress((void**)&wq, g_wqkv);
  cudaGetSymbolAddress((void**)&oh, g_oh);
  cudaGetSymbolAddress((void**)&wp, g_wproj);

  convh_kernel<<<8192 * 768 / 4 / 256, 256>>>(x, xh, 8192 * 768 / 4);
  convh_kernel<<<2304 * 768 / 4 / 256, 256>>>(qkv_w, wq, 2304 * 768 / 4);
  convh_kernel<<<768 * 768 / 4 / 256, 256>>>(proj_w, wp, 768 * 768 / 4);
  hmma_gemm_kernel<0><<<dim3(18, 64), 256, GEMM_SMEM>>>(xh, wq, qkv_b,
                                                        nullptr);
  relbias_kernel<<<dim3(32, 96), 256>>>(rph, rpw);
  attn_mma_kernel<<<dim3(8, 96), 256, ATT_SMEM>>>();
  hmma_gemm_kernel<1><<<dim3(6, 64), 256, GEMM_SMEM>>>(oh, wp, proj_b, out);
}

// round 10
// speedup vs baseline: 5.6593x; 1.0097x over previous
#include <cuda_runtime.h>
#include <cuda_fp16.h>
#include <math.h>
#include <cstdint>

// ---------------------------------------------------------------------------
// Problem constants
//   x:(8,32,32,768)  qkv_w:(2304,768)  qkv_b:(2304)
//   proj_w:(768,768) proj_b:(768)  rel_pos_h/w:(63,64)
//   NH=12 HD=64 S=1024 B*NH=96, out:(8,32,32,768) fp32
// ---------------------------------------------------------------------------
namespace {
constexpr int kHD = 64;
constexpr int kS  = 1024;
constexpr int kBH = 96;
}

// Scratch (__device__ globals: allocation-free per harness rules)
__device__ float g_q[kBH * kS * kHD];          // fp32 q (relbias input)
__device__ float g_relh[kBH * 32 * 32 * 32];
__device__ float g_relw[kBH * 32 * 32 * 32];

// fp16 operands
__device__ __half g_xh[8192 * 768];
__device__ __half g_wqkv[2304 * 768];
__device__ __half g_oh[8192 * 768];
__device__ __half g_wproj[768 * 768];
// attention operands (written by qkv epilogue)
__device__ __half g_qh[kBH * kS * kHD];   // pre-scaled by 0.125
__device__ __half g_k[kBH * kS * kHD];
__device__ __half g_vt[kBH * kHD * kS];   // [bh][d][seq] transposed

// ---------------------------------------------------------------------------
// PTX helpers
// ---------------------------------------------------------------------------
__device__ __forceinline__ void mma16816h(float* c, const uint32_t* a,
                                          const uint32_t* b) {
  asm volatile(
      "mma.sync.aligned.m16n8k16.row.col.f32.f16.f16.f32 "
      "{%0,%1,%2,%3}, {%4,%5,%6,%7}, {%8,%9}, {%0,%1,%2,%3};"
      : "+f"(c[0]), "+f"(c[1]), "+f"(c[2]), "+f"(c[3])
      : "r"(a[0]), "r"(a[1]), "r"(a[2]), "r"(a[3]), "r"(b[0]), "r"(b[1]));
}

#define LDSM4(r, addr)                                                  \
  asm volatile(                                                         \
      "ldmatrix.sync.aligned.m8n8.x4.shared.b16 {%0,%1,%2,%3}, [%4];"   \
      : "=r"((r)[0]), "=r"((r)[1]), "=r"((r)[2]), "=r"((r)[3])          \
      : "r"(addr))

__device__ __forceinline__ uint32_t smem_u32(const void* p) {
  uint32_t a;
  asm("{ .reg .u64 t; cvta.to.shared.u64 t, %1; cvt.u32.u64 %0, t; }"
      : "=r"(a) : "l"(p));
  return a;
}
__device__ __forceinline__ void cp16(uint32_t s, const void* g) {
  asm volatile("cp.async.cg.shared.global [%0], [%1], 16;" ::"r"(s), "l"(g)
               : "memory");
}
#define CP_COMMIT() asm volatile("cp.async.commit_group;" ::: "memory")
#define CP_WAIT2() asm volatile("cp.async.wait_group 2;" ::: "memory")
#define CP_WAIT1() asm volatile("cp.async.wait_group 1;" ::: "memory")
#define CP_WAIT0() asm volatile("cp.async.wait_group 0;" ::: "memory")

__device__ __forceinline__ uint32_t pack_h2(float x0, float x1) {
  __half2 h = __floats2half2_rn(x0, x1);
  return *(uint32_t*)&h;
}

// ---------------------------------------------------------------------------
// fp32 -> fp16 (contiguous)
// ---------------------------------------------------------------------------
__global__ __launch_bounds__(256) void convh_kernel(
    const float* __restrict__ src, __half* __restrict__ dst, int n4) {
  int i = blockIdx.x * 256 + threadIdx.x;
  if (i >= n4) return;
  float4 f = ((const float4*)src)[i];
  uint2 u;
  u.x = pack_h2(f.x, f.y);
  u.y = pack_h2(f.z, f.w);
  ((uint2*)dst)[i] = u;
}

// ---------------------------------------------------------------------------
// HMMA GEMM: C[128,128] = A*B^T  (K=768, fp32 acc, fp16 operands)
// 256 threads = 8 warps (2 m x 4 n), warp tile 64x32, BK=32.
// 3-stage cp.async pipeline; ldmatrix + register double-buffered fragments.
// MODE 0: qkv epilogue (scatter q fp32 + q/k/vt fp16)
// MODE 1: proj epilogue (row-major fp32 out + bias)
// ---------------------------------------------------------------------------
#define SSTR 40                  // smem k-stride in fp16 units (80B, 16B-mult)
#define GEMM_TILE 10240          // 128*SSTR*2 bytes
#define GEMM_BUF (2 * GEMM_TILE) // one stage: A,B
#define GEMM_SMEM (3 * GEMM_BUF)

template <int MODE>
__global__ __launch_bounds__(256, 2) void hmma_gemm_kernel(
    const __half* __restrict__ A, const __half* __restrict__ B,
    const float* __restrict__ bias, float* __restrict__ out) {
  extern __shared__ char dsm[];
  const uint32_t smb = smem_u32(dsm);
  const int tid = threadIdx.x;
  const int wid = tid >> 5, lane = tid & 31;
  const int wm = wid & 1;
  const int wn = wid >> 1;
  const int g = lane >> 2, t = lane & 3;
  const int bn = blockIdx.x, bm = blockIdx.y;
  const int arow0 = bm * 128, brow0 = bn * 128;

  // ldmatrix per-lane offsets (within a stage buffer)
  const uint32_t aoff =
      (uint32_t)(wm * 64 + (lane & 15)) * (SSTR * 2) + (lane >> 4) * 16;
  const uint32_t boff =
      (uint32_t)(wn * 32 + ((lane >> 4) << 3) + (lane & 7)) * (SSTR * 2) +
      ((lane >> 3) & 1) * 16;

  auto prefetch = [&](int kt, int bb) {
    uint32_t sb = smb + bb * GEMM_BUF;
#pragma unroll
    for (int c = tid; c < 512; c += 256) {
      int row = c >> 2, q = c & 3;
      size_t ga = (size_t)(arow0 + row) * 768 + kt * 32 + q * 8;
      size_t gb = (size_t)(brow0 + row) * 768 + kt * 32 + q * 8;
      uint32_t so = row * (SSTR * 2) + q * 16;
      cp16(sb + so, A + ga);
      cp16(sb + GEMM_TILE + so, B + gb);
    }
  };

  float acc[4][4][4];
#pragma unroll
  for (int mi = 0; mi < 4; mi++)
#pragma unroll
    for (int ni = 0; ni < 4; ni++)
#pragma unroll
      for (int r = 0; r < 4; r++) acc[mi][ni][r] = 0.f;

  prefetch(0, 0);
  CP_COMMIT();
  prefetch(1, 1);
  CP_COMMIT();

  for (int kt = 0; kt < 24; ++kt) {
    const int bb = kt % 3;
    if (kt + 2 < 24) {
      prefetch(kt + 2, (kt + 2) % 3);
      CP_COMMIT();
      CP_WAIT2();
    } else if (kt + 1 < 24) {
      CP_WAIT1();
    } else {
      CP_WAIT0();
    }
    __syncthreads();
    const uint32_t sbA = smb + bb * GEMM_BUF;
    const uint32_t sbB = sbA + GEMM_TILE;

    // fragment double buffer; preload ks=0, overlap ks=1 loads with mma
    uint32_t a[2][4][4], bf[2][2][4];
#pragma unroll
    for (int mi = 0; mi < 4; mi++)
      LDSM4(a[0][mi], sbA + aoff + mi * (16 * SSTR * 2));
#pragma unroll
    for (int nip = 0; nip < 2; nip++)
      LDSM4(bf[0][nip], sbB + boff + nip * (16 * SSTR * 2));
#pragma unroll
    for (int ks = 0; ks < 2; ks++) {
      const int cur = ks & 1, nxt = cur ^ 1;
      if (ks == 0) {
        const uint32_t kb = 32;  // ks=1 -> +16 halves = +32B
#pragma unroll
        for (int mi = 0; mi < 4; mi++)
          LDSM4(a[nxt][mi], sbA + aoff + mi * (16 * SSTR * 2) + kb);
#pragma unroll
        for (int nip = 0; nip < 2; nip++)
          LDSM4(bf[nxt][nip], sbB + boff + nip * (16 * SSTR * 2) + kb);
      }
#pragma unroll
      for (int nip = 0; nip < 2; nip++)
#pragma unroll
        for (int mi = 0; mi < 4; mi++) {
          mma16816h(acc[mi][2 * nip], a[cur][mi], bf[cur][nip]);
          mma16816h(acc[mi][2 * nip + 1], a[cur][mi], bf[cur][nip] + 2);
        }
    }
    __syncthreads();
  }

  // Epilogue. c0,c1 -> (row g, cols 2t,2t+1); c2,c3 -> row g+8.
#pragma unroll
  for (int mi = 0; mi < 4; mi++) {
#pragma unroll
    for (int ni = 0; ni < 4; ni++) {
      int n = bn * 128 + wn * 32 + ni * 8 + 2 * t;
      float b0 = bias[n], b1 = bias[n + 1];
#pragma unroll
      for (int half = 0; half < 2; half++) {
        int m = bm * 128 + wm * 64 + mi * 16 + g + half * 8;
        float2 v;
        v.x = acc[mi][ni][half * 2 + 0] + b0;
        v.y = acc[mi][ni][half * 2 + 1] + b1;
        if (MODE == 0) {
          int part = n / 768;
          int rem = n - part * 768;
          int head = rem >> 6, d = rem & 63;
          int bb2 = m >> 10, s = m & 1023;
          int bh = bb2 * 12 + head;
          size_t off = ((size_t)bh * 1024 + s) * 64 + d;
          if (part == 0) {
            *(float2*)(g_q + off) = v;
            *(uint32_t*)&g_qh[off] = pack_h2(0.125f * v.x, 0.125f * v.y);
          } else if (part == 1) {
            *(uint32_t*)&g_k[off] = pack_h2(v.x, v.y);
          } else {
            size_t vt0 = ((size_t)bh * 64 + d) * 1024 + s;
            size_t vt1 = ((size_t)bh * 64 + d + 1) * 1024 + s;
            g_vt[vt0] = __float2half_rn(v.x);
            g_vt[vt1] = __float2half_rn(v.y);
          }
        } else {
          *(float2*)(out + (size_t)m * 768 + n) = v;
        }
      }
    }
  }
}

// ---------------------------------------------------------------------------
// Kernel 2: decomposed rel-pos bias tables (fp32, swizzled smem).
// ---------------------------------------------------------------------------
#define RSWZ(r, c4) ((c4) ^ ((((r) >> 2) & 7) << 2))

__global__ __launch_bounds__(256) void relbias_kernel(
    const float* __restrict__ rph, const float* __restrict__ rpw) {
  __shared__ float Qs[32][68];
  __shared__ float Rhs[32][64];
  __shared__ float Rws[63][64];
  const int h = blockIdx.x;
  const int bh = blockIdx.y;
  const int tid = threadIdx.x;

  for (int idx = tid; idx < 32 * 16; idx += 256) {
    int w = idx >> 4, c4 = (idx & 15) << 2;
    *(float4*)&Qs[w][c4] =
        *(const float4*)&g_q[((size_t)bh * 1024 + h * 32 + w) * 64 + c4];
    *(float4*)&Rhs[w][RSWZ(w, c4)] = *(const float4*)&rph[(h + w) * 64 + c4];
  }
  for (int idx = tid; idx < 63 * 16; idx += 256) {
    int r = idx >> 4, c4 = (idx & 15) << 2;
    *(float4*)&Rws[r][RSWZ(r, c4)] = *(const float4*)&rpw[r * 64 + c4];
  }
  __syncthreads();

  const int w = tid >> 3;
  const int k0 = (tid & 7) << 2;
  float ah[4] = {0, 0, 0, 0}, aw[4] = {0, 0, 0, 0};
#pragma unroll
  for (int d4 = 0; d4 < 64; d4 += 4) {
    float4 qv = *(const float4*)&Qs[w][d4];
#pragma unroll
    for (int j = 0; j < 4; j++) {
      int rh_r = 31 - (k0 + j);
      float4 rh = *(const float4*)&Rhs[rh_r][RSWZ(rh_r, d4)];
      ah[j] += qv.x * rh.x + qv.y * rh.y + qv.z * rh.z + qv.w * rh.w;
      int rw_r = w - (k0 + j) + 31;
      float4 rw = *(const float4*)&Rws[rw_r][RSWZ(rw_r, d4)];
      aw[j] += qv.x * rw.x + qv.y * rw.y + qv.z * rw.z + qv.w * rw.w;
    }
  }
  size_t ob = (((size_t)bh * 32 + h) * 32 + w) * 32 + k0;
#pragma unroll
  for (int j = 0; j < 4; j++) {
    g_relh[ob + j] = ah[j];
    g_relw[ob + j] = aw[j];
  }
}

// ---------------------------------------------------------------------------
// Kernel 3: flash attention, single fp16 product, 128x64 q-tile.
// 256 threads = 8 warps; Q frags in registers; batched ldmatrix K/V loads;
// cp.async double-buffered smem; V pre-transposed [d][seq].
// ---------------------------------------------------------------------------
#define KSTR 72                      // fp16 smem stride (144B, 16B-mult)
#define ATT_TILE (64 * KSTR * 2)     // 9216 B per array
#define ATT_BUF (2 * ATT_TILE)       // K,V one stage
#define ATT_BH_OFF (2 * ATT_BUF)
#define ATT_SMEM (2 * ATT_BUF + 128 * 32 * 4)

__global__ __launch_bounds__(256) void attn_mma_kernel() {
  extern __shared__ char dsm[];
  const uint32_t smb = smem_u32(dsm);
  float* sBh = (float*)(dsm + ATT_BH_OFF);

  const int bh = blockIdx.y;
  const int q0 = blockIdx.x * 128;
  const int tid = threadIdx.x;
  const int w = tid >> 5, lane = tid & 31;
  const int g = lane >> 2, t = lane & 3;
  const int b = bh / 12, head = bh - b * 12;

  // ldmatrix per-lane offset for B-side frags (16-row pair per x4)
  const uint32_t fboff =
      (uint32_t)(((lane >> 4) << 3) + (lane & 7)) * (KSTR * 2) +
      ((lane >> 3) & 1) * 16;

  auto prefetch = [&](int kt, int bb) {
    uint32_t sb = smb + bb * ATT_BUF;
#pragma unroll
    for (int idx = tid; idx < 512; idx += 256) {
      int r = idx >> 3, qc = idx & 7;
      size_t gk = ((size_t)bh * 1024 + kt * 64 + r) * 64 + qc * 8;
      size_t gv = ((size_t)bh * 64 + r) * 1024 + kt * 64 + qc * 8;
      uint32_t so = r * (KSTR * 2) + qc * 16;
      cp16(sb + so, g_k + gk);
      cp16(sb + ATT_TILE + so, g_vt + gv);
    }
  };

  prefetch(0, 0);
  CP_COMMIT();

  // rel_h table for this q-tile (128 rows x 32)
  for (int idx = tid; idx < 128 * 8; idx += 256) {
    int r = idx >> 3, c4 = (idx & 7) << 2;
    int s = q0 + r;
    *(float4*)&sBh[r * 32 + c4] = *(const float4*)
        &g_relh[(((size_t)bh * 32 + (s >> 5)) * 32 + (s & 31)) * 32 + c4];
  }

  // Q fragments in registers (rows w*16+g, +8), pre-scaled
  uint32_t qf[4][4];
  {
    const size_t base = ((size_t)bh * 1024 + q0 + w * 16) * 64;
#pragma unroll
    for (int kc = 0; kc < 4; kc++) {
      int col = kc * 16 + 2 * t;
      qf[kc][0] = *(const uint32_t*)&g_qh[base + (size_t)g * 64 + col];
      qf[kc][1] = *(const uint32_t*)&g_qh[base + (size_t)(g + 8) * 64 + col];
      qf[kc][2] = *(const uint32_t*)&g_qh[base + (size_t)g * 64 + col + 8];
      qf[kc][3] =
          *(const uint32_t*)&g_qh[base + (size_t)(g + 8) * 64 + col + 8];
    }
  }

  // rel_w bias registers: bw[half][ni&3][col01]
  float bw[2][4][2];
#pragma unroll
  for (int hf = 0; hf < 2; hf++) {
    int s = q0 + w * 16 + g + hf * 8;
    const float* src =
        &g_relw[(((size_t)bh * 32 + (s >> 5)) * 32 + (s & 31)) * 32];
#pragma unroll
    for (int nm = 0; nm < 4; nm++) {
      bw[hf][nm][0] = src[nm * 8 + 2 * t];
      bw[hf][nm][1] = src[nm * 8 + 2 * t + 1];
    }
  }

  float m0 = -INFINITY, m1 = -INFINITY, l0 = 0.f, l1 = 0.f;
  float o[8][4];
#pragma unroll
  for (int ni = 0; ni < 8; ni++)
#pragma unroll
    for (int r = 0; r < 4; r++) o[ni][r] = 0.f;

  for (int kt = 0; kt < 16; kt++) {
    const int bb = kt & 1;
    if (kt + 1 < 16) {
      prefetch(kt + 1, bb ^ 1);
      CP_COMMIT();
      CP_WAIT1();
    } else {
      CP_WAIT0();
    }
    __syncthreads();
    const uint32_t sK = smb + bb * ATT_BUF;
    const uint32_t sV = sK + ATT_TILE;

    // ---- S = (scaled Q) K^T : batch 4 LDSM per kc, then 8 mma ----
    float sc[8][4];
#pragma unroll
    for (int ni = 0; ni < 8; ni++)
#pragma unroll
      for (int r = 0; r < 4; r++) sc[ni][r] = 0.f;
#pragma unroll
    for (int kc = 0; kc < 4; kc++) {
      const uint32_t kb = kc * 32;
      uint32_t bfr[4][4];
#pragma unroll
      for (int nip = 0; nip < 4; nip++)
        LDSM4(bfr[nip], sK + fboff + nip * (16 * KSTR * 2) + kb);
#pragma unroll
      for (int nip = 0; nip < 4; nip++) {
        mma16816h(sc[2 * nip], qf[kc], bfr[nip]);
        mma16816h(sc[2 * nip + 1], qf[kc], bfr[nip] + 2);
      }
    }

    // ---- bias + online softmax (rows g and g+8) ----
    const float bhA0 = sBh[(w * 16 + g) * 32 + 2 * kt];
    const float bhA1 = sBh[(w * 16 + g) * 32 + 2 * kt + 1];
    const float bhB0 = sBh[(w * 16 + g + 8) * 32 + 2 * kt];
    const float bhB1 = sBh[(w * 16 + g + 8) * 32 + 2 * kt + 1];
    float mx0 = -INFINITY, mx1 = -INFINITY;
#pragma unroll
    for (int ni = 0; ni < 8; ni++) {
      const float ba = (ni < 4) ? bhA0 : bhA1;
      const float bb2 = (ni < 4) ? bhB0 : bhB1;
      const int nm = ni & 3;
      sc[ni][0] += ba + bw[0][nm][0];
      sc[ni][1] += ba + bw[0][nm][1];
      sc[ni][2] += bb2 + bw[1][nm][0];
      sc[ni][3] += bb2 + bw[1][nm][1];
      mx0 = fmaxf(mx0, fmaxf(sc[ni][0], sc[ni][1]));
      mx1 = fmaxf(mx1, fmaxf(sc[ni][2], sc[ni][3]));
    }
    mx0 = fmaxf(mx0, __shfl_xor_sync(0xffffffffu, mx0, 1));
    mx0 = fmaxf(mx0, __shfl_xor_sync(0xffffffffu, mx0, 2));
    mx1 = fmaxf(mx1, __shfl_xor_sync(0xffffffffu, mx1, 1));
    mx1 = fmaxf(mx1, __shfl_xor_sync(0xffffffffu, mx1, 2));
    const float mn0 = fmaxf(m0, mx0), mn1 = fmaxf(m1, mx1);
    const float a0 = __expf(m0 - mn0), a1 = __expf(m1 - mn1);
    float sum0 = 0.f, sum1 = 0.f;
#pragma unroll
    for (int ni = 0; ni < 8; ni++) {
      sc[ni][0] = __expf(sc[ni][0] - mn0);
      sc[ni][1] = __expf(sc[ni][1] - mn0);
      sc[ni][2] = __expf(sc[ni][2] - mn1);
      sc[ni][3] = __expf(sc[ni][3] - mn1);
      sum0 += sc[ni][0] + sc[ni][1];
      sum1 += sc[ni][2] + sc[ni][3];
    }
    sum0 += __shfl_xor_sync(0xffffffffu, sum0, 1);
    sum0 += __shfl_xor_sync(0xffffffffu, sum0, 2);
    sum1 += __shfl_xor_sync(0xffffffffu, sum1, 1);
    sum1 += __shfl_xor_sync(0xffffffffu, sum1, 2);
    l0 = l0 * a0 + sum0;
    l1 = l1 * a1 + sum1;
    m0 = mn0;
    m1 = mn1;
#pragma unroll
    for (int ni = 0; ni < 8; ni++) {
      o[ni][0] *= a0;
      o[ni][1] *= a0;
      o[ni][2] *= a1;
      o[ni][3] *= a1;
    }

    // ---- pack P (A-frags reuse S C-frags) ----
    uint32_t ph[4][4];
#pragma unroll
    for (int kc = 0; kc < 4; kc++) {
      const int nA = 2 * kc, nB = 2 * kc + 1;
      ph[kc][0] = pack_h2(sc[nA][0], sc[nA][1]);
      ph[kc][1] = pack_h2(sc[nA][2], sc[nA][3]);
      ph[kc][2] = pack_h2(sc[nB][0], sc[nB][1]);
      ph[kc][3] = pack_h2(sc[nB][2], sc[nB][3]);
    }

    // ---- O += P V : batch 4 LDSM per kc, then 8 mma ----
#pragma unroll
    for (int kc = 0; kc < 4; kc++) {
      const uint32_t kb = kc * 32;
      uint32_t bfr[4][4];
#pragma unroll
      for (int nip = 0; nip < 4; nip++)
        LDSM4(bfr[nip], sV + fboff + nip * (16 * KSTR * 2) + kb);
#pragma unroll
      for (int nip = 0; nip < 4; nip++) {
        mma16816h(o[2 * nip], ph[kc], bfr[nip]);
        mma16816h(o[2 * nip + 1], ph[kc], bfr[nip] + 2);
      }
    }
    __syncthreads();
  }

  // epilogue: normalize and write fp16 in proj layout [b*1024+s][768]
  const float inv0 = 1.f / l0, inv1 = 1.f / l1;
  const int s0 = q0 + w * 16 + g, s1 = s0 + 8;
  const size_t ob0 = ((size_t)(b * 1024 + s0)) * 768 + head * 64;
  const size_t ob1 = ((size_t)(b * 1024 + s1)) * 768 + head * 64;
#pragma unroll
  for (int ni = 0; ni < 8; ni++) {
    const int d = ni * 8 + 2 * t;
    *(uint32_t*)&g_oh[ob0 + d] = pack_h2(o[ni][0] * inv0, o[ni][1] * inv0);
    *(uint32_t*)&g_oh[ob1 + d] = pack_h2(o[ni][2] * inv1, o[ni][3] * inv1);
  }
}

// ---------------------------------------------------------------------------
extern "C" void kernel_launch(void* const* d_in, const int* in_sizes, int n_in,
                              void* d_out, int out_size) {
  const float* x      = (const float*)d_in[0];
  const float* qkv_w  = (const float*)d_in[1];
  const float* qkv_b  = (const float*)d_in[2];
  const float* proj_w = (const float*)d_in[3];
  const float* proj_b = (const float*)d_in[4];
  const float* rph    = (const float*)d_in[5];
  const float* rpw    = (const float*)d_in[6];
  float* out = (float*)d_out;

  cudaFuncSetAttribute(hmma_gemm_kernel<0>,
                       cudaFuncAttributeMaxDynamicSharedMemorySize, GEMM_SMEM);
  cudaFuncSetAttribute(hmma_gemm_kernel<1>,
                       cudaFuncAttributeMaxDynamicSharedMemorySize, GEMM_SMEM);
  cudaFuncSetAttribute(attn_mma_kernel,
                       cudaFuncAttributeMaxDynamicSharedMemorySize, ATT_SMEM);

  __half *xh, *wq, *oh, *wp;
  cudaGetSymbolAddress((void**)&xh, g_xh);
  cudaGetSymbolAddress((void**)&wq, g_wqkv);
  cudaGetSymbolAddress((void**)&oh, g_oh);
  cudaGetSymbolAddress((void**)&wp, g_wproj);

  convh_kernel<<<8192 * 768 / 4 / 256, 256>>>(x, xh, 8192 * 768 / 4);
  convh_kernel<<<2304 * 768 / 4 / 256, 256>>>(qkv_w, wq, 2304 * 768 / 4);
  convh_kernel<<<768 * 768 / 4 / 256, 256>>>(proj_w, wp, 768 * 768 / 4);
  hmma_gemm_kernel<0><<<dim3(18, 64), 256, GEMM_SMEM>>>(xh, wq, qkv_b,
                                                        nullptr);
  relbias_kernel<<<dim3(32, 96), 256>>>(rph, rpw);
  attn_mma_kernel<<<dim3(8, 96), 256, ATT_SMEM>>>();
  hmma_gemm_kernel<1><<<dim3(6, 64), 256, GEMM_SMEM>>>(oh, wp, proj_b, out);
}

// round 11
// speedup vs baseline: 6.5820x; 1.1630x over previous
#include <cuda_runtime.h>
#include <cuda_fp16.h>
#include <math.h>
#include <cstdint>

// ---------------------------------------------------------------------------
// Problem constants
//   x:(8,32,32,768)  qkv_w:(2304,768)  qkv_b:(2304)
//   proj_w:(768,768) proj_b:(768)  rel_pos_h/w:(63,64)
//   NH=12 HD=64 S=1024 B*NH=96, out:(8,32,32,768) fp32
// ---------------------------------------------------------------------------
namespace {
constexpr int kHD = 64;
constexpr int kS  = 1024;
constexpr int kBH = 96;
}

// Scratch (__device__ globals: allocation-free per harness rules)
__device__ float g_relh[kBH * 32 * 32 * 32];
__device__ float g_relw[kBH * 32 * 32 * 32];

// fp16 operands
__device__ __half g_xh[8192 * 768];
__device__ __half g_wqkv[2304 * 768];
__device__ __half g_oh[8192 * 768];
__device__ __half g_wproj[768 * 768];
// attention operands (written by qkv epilogue)
__device__ __half g_qh[kBH * kS * kHD];   // pre-scaled by 0.125
__device__ __half g_k[kBH * kS * kHD];
__device__ __half g_vt[kBH * kHD * kS];   // [bh][d][seq] transposed
// fp16 rel tables, x8 (compensates q's 0.125), padded to 64 rows (row 63 = 0)
__device__ __half g_rph16[64 * 64];
__device__ __half g_rpw16[64 * 64];

// ---------------------------------------------------------------------------
// PTX helpers
// ---------------------------------------------------------------------------
__device__ __forceinline__ void mma16816h(float* c, const uint32_t* a,
                                          const uint32_t* b) {
  asm volatile(
      "mma.sync.aligned.m16n8k16.row.col.f32.f16.f16.f32 "
      "{%0,%1,%2,%3}, {%4,%5,%6,%7}, {%8,%9}, {%0,%1,%2,%3};"
      : "+f"(c[0]), "+f"(c[1]), "+f"(c[2]), "+f"(c[3])
      : "r"(a[0]), "r"(a[1]), "r"(a[2]), "r"(a[3]), "r"(b[0]), "r"(b[1]));
}

#define LDSM4(r, addr)                                                  \
  asm volatile(                                                         \
      "ldmatrix.sync.aligned.m8n8.x4.shared.b16 {%0,%1,%2,%3}, [%4];"   \
      : "=r"((r)[0]), "=r"((r)[1]), "=r"((r)[2]), "=r"((r)[3])          \
      : "r"(addr))

__device__ __forceinline__ uint32_t smem_u32(const void* p) {
  uint32_t a;
  asm("{ .reg .u64 t; cvta.to.shared.u64 t, %1; cvt.u32.u64 %0, t; }"
      : "=r"(a) : "l"(p));
  return a;
}
__device__ __forceinline__ void cp16(uint32_t s, const void* g) {
  asm volatile("cp.async.cg.shared.global [%0], [%1], 16;" ::"r"(s), "l"(g)
               : "memory");
}
#define CP_COMMIT() asm volatile("cp.async.commit_group;" ::: "memory")
#define CP_WAIT2() asm volatile("cp.async.wait_group 2;" ::: "memory")
#define CP_WAIT1() asm volatile("cp.async.wait_group 1;" ::: "memory")
#define CP_WAIT0() asm volatile("cp.async.wait_group 0;" ::: "memory")

__device__ __forceinline__ uint32_t pack_h2(float x0, float x1) {
  __half2 h = __floats2half2_rn(x0, x1);
  return *(uint32_t*)&h;
}

// ---------------------------------------------------------------------------
// fp32 -> fp16 (contiguous)
// ---------------------------------------------------------------------------
__global__ __launch_bounds__(256) void convh_kernel(
    const float* __restrict__ src, __half* __restrict__ dst, int n4) {
  int i = blockIdx.x * 256 + threadIdx.x;
  if (i >= n4) return;
  float4 f = ((const float4*)src)[i];
  uint2 u;
  u.x = pack_h2(f.x, f.y);
  u.y = pack_h2(f.z, f.w);
  ((uint2*)dst)[i] = u;
}

// rel tables -> fp16 x8, padded to 64 rows (row 63 zeroed)
__global__ __launch_bounds__(256) void conv_rel_kernel(
    const float* __restrict__ rph, const float* __restrict__ rpw) {
  int i = blockIdx.x * 256 + threadIdx.x;  // over 64*64
  if (i >= 64 * 64) return;
  int r = i >> 6, d = i & 63;
  __half hv = __float2half_rn(0.f), wv = __float2half_rn(0.f);
  if (r < 63) {
    hv = __float2half_rn(8.f * rph[r * 64 + d]);
    wv = __float2half_rn(8.f * rpw[r * 64 + d]);
  }
  g_rph16[i] = hv;
  g_rpw16[i] = wv;
}

// ---------------------------------------------------------------------------
// HMMA GEMM: C[128,128] = A*B^T  (K=768, fp32 acc, fp16 operands)
// 256 threads = 8 warps (2 m x 4 n), warp tile 64x32, BK=32.
// 4-stage cp.async ring, ONE __syncthreads per k-iter; ldmatrix frags (R9
// inner loop — fastest measured).
// MODE 0: qkv epilogue (q/k/vt fp16)
// MODE 1: proj epilogue (row-major fp32 out + bias)
// ---------------------------------------------------------------------------
#define SSTR 40                  // smem k-stride in fp16 units (80B)
#define GEMM_TILE 10240          // 128*SSTR*2 bytes
#define GEMM_BUF (2 * GEMM_TILE) // one stage: A,B
#define GEMM_SMEM (4 * GEMM_BUF)

template <int MODE>
__global__ __launch_bounds__(256, 2) void hmma_gemm_kernel(
    const __half* __restrict__ A, const __half* __restrict__ B,
    const float* __restrict__ bias, float* __restrict__ out) {
  extern __shared__ char dsm[];
  const uint32_t smb = smem_u32(dsm);
  const int tid = threadIdx.x;
  const int wid = tid >> 5, lane = tid & 31;
  const int wm = wid & 1;
  const int wn = wid >> 1;
  const int g = lane >> 2, t = lane & 3;
  const int bn = blockIdx.x, bm = blockIdx.y;
  const int arow0 = bm * 128, brow0 = bn * 128;

  const uint32_t aoff =
      (uint32_t)(wm * 64 + (lane & 15)) * (SSTR * 2) + (lane >> 4) * 16;
  const uint32_t boff =
      (uint32_t)(wn * 32 + ((lane >> 4) << 3) + (lane & 7)) * (SSTR * 2) +
      ((lane >> 3) & 1) * 16;

  auto prefetch = [&](int kt, int bb) {
    uint32_t sb = smb + bb * GEMM_BUF;
#pragma unroll
    for (int c = tid; c < 512; c += 256) {
      int row = c >> 2, q = c & 3;
      size_t ga = (size_t)(arow0 + row) * 768 + kt * 32 + q * 8;
      size_t gb = (size_t)(brow0 + row) * 768 + kt * 32 + q * 8;
      uint32_t so = row * (SSTR * 2) + q * 16;
      cp16(sb + so, A + ga);
      cp16(sb + GEMM_TILE + so, B + gb);
    }
  };

  float acc[4][4][4];
#pragma unroll
  for (int mi = 0; mi < 4; mi++)
#pragma unroll
    for (int ni = 0; ni < 4; ni++)
#pragma unroll
      for (int r = 0; r < 4; r++) acc[mi][ni][r] = 0.f;

  prefetch(0, 0);
  CP_COMMIT();
  prefetch(1, 1);
  CP_COMMIT();
  prefetch(2, 2);
  CP_COMMIT();

  for (int kt = 0; kt < 24; ++kt) {
    if (kt + 2 < 24) {
      CP_WAIT2();
    } else if (kt + 1 < 24) {
      CP_WAIT1();
    } else {
      CP_WAIT0();
    }
    __syncthreads();
    const uint32_t sbA = smb + (kt & 3) * GEMM_BUF;
    const uint32_t sbB = sbA + GEMM_TILE;

#pragma unroll
    for (int ks = 0; ks < 2; ks++) {
      const uint32_t kb = ks * 32;  // 16 halves = 32 bytes
      uint32_t a[4][4];
#pragma unroll
      for (int mi = 0; mi < 4; mi++)
        LDSM4(a[mi], sbA + aoff + mi * (16 * SSTR * 2) + kb);
#pragma unroll
      for (int nip = 0; nip < 2; nip++) {
        uint32_t bfr[4];
        LDSM4(bfr, sbB + boff + nip * (16 * SSTR * 2) + kb);
#pragma unroll
        for (int mi = 0; mi < 4; mi++) {
          mma16816h(acc[mi][2 * nip], a[mi], bfr);
          mma16816h(acc[mi][2 * nip + 1], a[mi], bfr + 2);
        }
      }
    }
    if (kt + 3 < 24) {
      prefetch(kt + 3, (kt + 3) & 3);
      CP_COMMIT();
    }
  }

  // Epilogue. c0,c1 -> (row g, cols 2t,2t+1); c2,c3 -> row g+8.
#pragma unroll
  for (int mi = 0; mi < 4; mi++) {
#pragma unroll
    for (int ni = 0; ni < 4; ni++) {
      int n = bn * 128 + wn * 32 + ni * 8 + 2 * t;
      float b0 = bias[n], b1 = bias[n + 1];
#pragma unroll
      for (int half = 0; half < 2; half++) {
        int m = bm * 128 + wm * 64 + mi * 16 + g + half * 8;
        float2 v;
        v.x = acc[mi][ni][half * 2 + 0] + b0;
        v.y = acc[mi][ni][half * 2 + 1] + b1;
        if (MODE == 0) {
          int part = n / 768;
          int rem = n - part * 768;
          int head = rem >> 6, d = rem & 63;
          int bb2 = m >> 10, s = m & 1023;
          int bh = bb2 * 12 + head;
          size_t off = ((size_t)bh * 1024 + s) * 64 + d;
          if (part == 0) {
            *(uint32_t*)&g_qh[off] = pack_h2(0.125f * v.x, 0.125f * v.y);
          } else if (part == 1) {
            *(uint32_t*)&g_k[off] = pack_h2(v.x, v.y);
          } else {
            size_t vt0 = ((size_t)bh * 64 + d) * 1024 + s;
            size_t vt1 = ((size_t)bh * 64 + d + 1) * 1024 + s;
            g_vt[vt0] = __float2half_rn(v.x);
            g_vt[vt1] = __float2half_rn(v.y);
          }
        } else {
          *(float2*)(out + (size_t)m * 768 + n) = v;
        }
      }
    }
  }
}

// ---------------------------------------------------------------------------
// Kernel 2: rel-pos bias via mma + gather.
//   Gh[w,j] = q[h,w] . rph16[h+j]    (j=0..31)  -> rel_h[w,kh] = Gh[w,31-kh]
//   Gw[w,j] = q[h,w] . rpw16[j]      (j=0..62)  -> rel_w[w,kw] = Gw[w,w-kw+31]
// Q from g_qh (x0.125), tables x8 -> scales cancel. Block (h,bh), 128 thr.
// Warps 0/1: Gh rows 0-15/16-31. Warps 2/3: Gw rows 0-15/16-31.
// ---------------------------------------------------------------------------
__global__ __launch_bounds__(128) void relbias_mma_kernel() {
  __shared__ float sGh[32][36];
  __shared__ float sGw[32][68];
  const int h = blockIdx.x, bh = blockIdx.y;
  const int tid = threadIdx.x;
  const int wid = tid >> 5, lane = tid & 31;
  const int g = lane >> 2, t = lane & 3;

  const __half* Qb = g_qh + ((size_t)bh * 1024 + h * 32) * 64;

  if (wid < 2) {
    const int m0 = wid * 16;
    float acc[4][4];
#pragma unroll
    for (int j = 0; j < 4; j++)
#pragma unroll
      for (int r = 0; r < 4; r++) acc[j][r] = 0.f;
#pragma unroll
    for (int kc = 0; kc < 4; kc++) {
      uint32_t a[4];
      const __half* qp = Qb + (size_t)(m0 + g) * 64 + kc * 16 + 2 * t;
      a[0] = *(const uint32_t*)qp;
      a[1] = *(const uint32_t*)(qp + 8 * 64);
      a[2] = *(const uint32_t*)(qp + 8);
      a[3] = *(const uint32_t*)(qp + 8 * 64 + 8);
#pragma unroll
      for (int jn = 0; jn < 4; jn++) {
        uint32_t b[2];
        const __half* bp = g_rph16 + (h + jn * 8 + g) * 64 + kc * 16 + 2 * t;
        b[0] = *(const uint32_t*)bp;
        b[1] = *(const uint32_t*)(bp + 8);
        mma16816h(acc[jn], a, b);
      }
    }
#pragma unroll
    for (int jn = 0; jn < 4; jn++) {
      sGh[m0 + g][jn * 8 + 2 * t] = acc[jn][0];
      sGh[m0 + g][jn * 8 + 2 * t + 1] = acc[jn][1];
      sGh[m0 + g + 8][jn * 8 + 2 * t] = acc[jn][2];
      sGh[m0 + g + 8][jn * 8 + 2 * t + 1] = acc[jn][3];
    }
  } else {
    const int m0 = (wid - 2) * 16;
    float acc[8][4];
#pragma unroll
    for (int j = 0; j < 8; j++)
#pragma unroll
      for (int r = 0; r < 4; r++) acc[j][r] = 0.f;
#pragma unroll
    for (int kc = 0; kc < 4; kc++) {
      uint32_t a[4];
      const __half* qp = Qb + (size_t)(m0 + g) * 64 + kc * 16 + 2 * t;
      a[0] = *(const uint32_t*)qp;
      a[1] = *(const uint32_t*)(qp + 8 * 64);
      a[2] = *(const uint32_t*)(qp + 8);
      a[3] = *(const uint32_t*)(qp + 8 * 64 + 8);
#pragma unroll
      for (int jn = 0; jn < 8; jn++) {
        uint32_t b[2];
        const __half* bp = g_rpw16 + (jn * 8 + g) * 64 + kc * 16 + 2 * t;
        b[0] = *(const uint32_t*)bp;
        b[1] = *(const uint32_t*)(bp + 8);
        mma16816h(acc[jn], a, b);
      }
    }
#pragma unroll
    for (int jn = 0; jn < 8; jn++) {
      sGw[m0 + g][jn * 8 + 2 * t] = acc[jn][0];
      sGw[m0 + g][jn * 8 + 2 * t + 1] = acc[jn][1];
      sGw[m0 + g + 8][jn * 8 + 2 * t] = acc[jn][2];
      sGw[m0 + g + 8][jn * 8 + 2 * t + 1] = acc[jn][3];
    }
  }
  __syncthreads();

  for (int idx = tid; idx < 32 * 32; idx += 128) {
    int wr = idx >> 5, kh = idx & 31;
    size_t ob = (((size_t)bh * 32 + h) * 32 + wr) * 32;
    g_relh[ob + kh] = sGh[wr][31 - kh];
    g_relw[ob + kh] = sGw[wr][wr - kh + 31];
  }
}

// ---------------------------------------------------------------------------
// Kernel 3: flash attention, single fp16 product, 128x64 q-tile.
// 256 threads = 8 warps; Q frags in registers; ldmatrix K/V fragment loads;
// 4-stage cp.async ring with ONE sync per iter; V pre-transposed [d][seq].
// ---------------------------------------------------------------------------
#define KSTR 72                      // fp16 smem stride (144B)
#define ATT_TILE (64 * KSTR * 2)     // 9216 B per array
#define ATT_BUF (2 * ATT_TILE)       // K,V one stage
#define ATT_BH_OFF (4 * ATT_BUF)
#define ATT_SMEM (4 * ATT_BUF + 128 * 32 * 4)

__global__ __launch_bounds__(256) void attn_mma_kernel() {
  extern __shared__ char dsm[];
  const uint32_t smb = smem_u32(dsm);
  float* sBh = (float*)(dsm + ATT_BH_OFF);

  const int bh = blockIdx.y;
  const int q0 = blockIdx.x * 128;
  const int tid = threadIdx.x;
  const int w = tid >> 5, lane = tid & 31;
  const int g = lane >> 2, t = lane & 3;
  const int b = bh / 12, head = bh - b * 12;

  const uint32_t fboff =
      (uint32_t)(((lane >> 4) << 3) + (lane & 7)) * (KSTR * 2) +
      ((lane >> 3) & 1) * 16;

  auto prefetch = [&](int kt, int bb) {
    uint32_t sb = smb + bb * ATT_BUF;
#pragma unroll
    for (int idx = tid; idx < 512; idx += 256) {
      int r = idx >> 3, qc = idx & 7;
      size_t gk = ((size_t)bh * 1024 + kt * 64 + r) * 64 + qc * 8;
      size_t gv = ((size_t)bh * 64 + r) * 1024 + kt * 64 + qc * 8;
      uint32_t so = r * (KSTR * 2) + qc * 16;
      cp16(sb + so, g_k + gk);
      cp16(sb + ATT_TILE + so, g_vt + gv);
    }
  };

  prefetch(0, 0);
  CP_COMMIT();
  prefetch(1, 1);
  CP_COMMIT();
  prefetch(2, 2);
  CP_COMMIT();

  // rel_h table for this q-tile (128 rows x 32)
  for (int idx = tid; idx < 128 * 8; idx += 256) {
    int r = idx >> 3, c4 = (idx & 7) << 2;
    int s = q0 + r;
    *(float4*)&sBh[r * 32 + c4] = *(const float4*)
        &g_relh[(((size_t)bh * 32 + (s >> 5)) * 32 + (s & 31)) * 32 + c4];
  }

  // Q fragments in registers (rows w*16+g, +8), pre-scaled
  uint32_t qf[4][4];
  {
    const size_t base = ((size_t)bh * 1024 + q0 + w * 16) * 64;
#pragma unroll
    for (int kc = 0; kc < 4; kc++) {
      int col = kc * 16 + 2 * t;
      qf[kc][0] = *(const uint32_t*)&g_qh[base + (size_t)g * 64 + col];
      qf[kc][1] = *(const uint32_t*)&g_qh[base + (size_t)(g + 8) * 64 + col];
      qf[kc][2] = *(const uint32_t*)&g_qh[base + (size_t)g * 64 + col + 8];
      qf[kc][3] =
          *(const uint32_t*)&g_qh[base + (size_t)(g + 8) * 64 + col + 8];
    }
  }

  // rel_w bias registers: bw[half][ni&3][col01]
  float bw[2][4][2];
#pragma unroll
  for (int hf = 0; hf < 2; hf++) {
    int s = q0 + w * 16 + g + hf * 8;
    const float* src =
        &g_relw[(((size_t)bh * 32 + (s >> 5)) * 32 + (s & 31)) * 32];
#pragma unroll
    for (int nm = 0; nm < 4; nm++) {
      bw[hf][nm][0] = src[nm * 8 + 2 * t];
      bw[hf][nm][1] = src[nm * 8 + 2 * t + 1];
    }
  }

  float m0 = -INFINITY, m1 = -INFINITY, l0 = 0.f, l1 = 0.f;
  float o[8][4];
#pragma unroll
  for (int ni = 0; ni < 8; ni++)
#pragma unroll
    for (int r = 0; r < 4; r++) o[ni][r] = 0.f;

  for (int kt = 0; kt < 16; kt++) {
    if (kt + 2 < 16) {
      CP_WAIT2();
    } else if (kt + 1 < 16) {
      CP_WAIT1();
    } else {
      CP_WAIT0();
    }
    __syncthreads();
    const uint32_t sK = smb + (kt & 3) * ATT_BUF;
    const uint32_t sV = sK + ATT_TILE;

    // ---- S = (scaled Q) K^T ----
    float sc[8][4];
#pragma unroll
    for (int ni = 0; ni < 8; ni++)
#pragma unroll
      for (int r = 0; r < 4; r++) sc[ni][r] = 0.f;
#pragma unroll
    for (int kc = 0; kc < 4; kc++) {
      const uint32_t kb = kc * 32;
#pragma unroll
      for (int nip = 0; nip < 4; nip++) {
        uint32_t bfr[4];
        LDSM4(bfr, sK + fboff + nip * (16 * KSTR * 2) + kb);
        mma16816h(sc[2 * nip], qf[kc], bfr);
        mma16816h(sc[2 * nip + 1], qf[kc], bfr + 2);
      }
    }

    // ---- bias + online softmax (rows g and g+8) ----
    const float bhA0 = sBh[(w * 16 + g) * 32 + 2 * kt];
    const float bhA1 = sBh[(w * 16 + g) * 32 + 2 * kt + 1];
    const float bhB0 = sBh[(w * 16 + g + 8) * 32 + 2 * kt];
    const float bhB1 = sBh[(w * 16 + g + 8) * 32 + 2 * kt + 1];
    float mx0 = -INFINITY, mx1 = -INFINITY;
#pragma unroll
    for (int ni = 0; ni < 8; ni++) {
      const float ba = (ni < 4) ? bhA0 : bhA1;
      const float bb2 = (ni < 4) ? bhB0 : bhB1;
      const int nm = ni & 3;
      sc[ni][0] += ba + bw[0][nm][0];
      sc[ni][1] += ba + bw[0][nm][1];
      sc[ni][2] += bb2 + bw[1][nm][0];
      sc[ni][3] += bb2 + bw[1][nm][1];
      mx0 = fmaxf(mx0, fmaxf(sc[ni][0], sc[ni][1]));
      mx1 = fmaxf(mx1, fmaxf(sc[ni][2], sc[ni][3]));
    }
    mx0 = fmaxf(mx0, __shfl_xor_sync(0xffffffffu, mx0, 1));
    mx0 = fmaxf(mx0, __shfl_xor_sync(0xffffffffu, mx0, 2));
    mx1 = fmaxf(mx1, __shfl_xor_sync(0xffffffffu, mx1, 1));
    mx1 = fmaxf(mx1, __shfl_xor_sync(0xffffffffu, mx1, 2));
    const float mn0 = fmaxf(m0, mx0), mn1 = fmaxf(m1, mx1);
    const float a0 = __expf(m0 - mn0), a1 = __expf(m1 - mn1);
    float sum0 = 0.f, sum1 = 0.f;
#pragma unroll
    for (int ni = 0; ni < 8; ni++) {
      sc[ni][0] = __expf(sc[ni][0] - mn0);
      sc[ni][1] = __expf(sc[ni][1] - mn0);
      sc[ni][2] = __expf(sc[ni][2] - mn1);
      sc[ni][3] = __expf(sc[ni][3] - mn1);
      sum0 += sc[ni][0] + sc[ni][1];
      sum1 += sc[ni][2] + sc[ni][3];
    }
    sum0 += __shfl_xor_sync(0xffffffffu, sum0, 1);
    sum0 += __shfl_xor_sync(0xffffffffu, sum0, 2);
    sum1 += __shfl_xor_sync(0xffffffffu, sum1, 1);
    sum1 += __shfl_xor_sync(0xffffffffu, sum1, 2);
    l0 = l0 * a0 + sum0;
    l1 = l1 * a1 + sum1;
    m0 = mn0;
    m1 = mn1;
#pragma unroll
    for (int ni = 0; ni < 8; ni++) {
      o[ni][0] *= a0;
      o[ni][1] *= a0;
      o[ni][2] *= a1;
      o[ni][3] *= a1;
    }

    // ---- pack P (A-frags reuse S C-frags) ----
    uint32_t ph[4][4];
#pragma unroll
    for (int kc = 0; kc < 4; kc++) {
      const int nA = 2 * kc, nB = 2 * kc + 1;
      ph[kc][0] = pack_h2(sc[nA][0], sc[nA][1]);
      ph[kc][1] = pack_h2(sc[nA][2], sc[nA][3]);
      ph[kc][2] = pack_h2(sc[nB][0], sc[nB][1]);
      ph[kc][3] = pack_h2(sc[nB][2], sc[nB][3]);
    }

    // ---- O += P V ----
#pragma unroll
    for (int kc = 0; kc < 4; kc++) {
      const uint32_t kb = kc * 32;
#pragma unroll
      for (int nip = 0; nip < 4; nip++) {
        uint32_t bfr[4];
        LDSM4(bfr, sV + fboff + nip * (16 * KSTR * 2) + kb);
        mma16816h(o[2 * nip], ph[kc], bfr);
        mma16816h(o[2 * nip + 1], ph[kc], bfr + 2);
      }
    }
    if (kt + 3 < 16) {
      prefetch(kt + 3, (kt + 3) & 3);
      CP_COMMIT();
    }
  }

  // epilogue: normalize and write fp16 in proj layout [b*1024+s][768]
  const float inv0 = 1.f / l0, inv1 = 1.f / l1;
  const int s0 = q0 + w * 16 + g, s1 = s0 + 8;
  const size_t ob0 = ((size_t)(b * 1024 + s0)) * 768 + head * 64;
  const size_t ob1 = ((size_t)(b * 1024 + s1)) * 768 + head * 64;
#pragma unroll
  for (int ni = 0; ni < 8; ni++) {
    const int d = ni * 8 + 2 * t;
    *(uint32_t*)&g_oh[ob0 + d] = pack_h2(o[ni][0] * inv0, o[ni][1] * inv0);
    *(uint32_t*)&g_oh[ob1 + d] = pack_h2(o[ni][2] * inv1, o[ni][3] * inv1);
  }
}

// ---------------------------------------------------------------------------
extern "C" void kernel_launch(void* const* d_in, const int* in_sizes, int n_in,
                              void* d_out, int out_size) {
  const float* x      = (const float*)d_in[0];
  const float* qkv_w  = (const float*)d_in[1];
  const float* qkv_b  = (const float*)d_in[2];
  const float* proj_w = (const float*)d_in[3];
  const float* proj_b = (const float*)d_in[4];
  const float* rph    = (const float*)d_in[5];
  const float* rpw    = (const float*)d_in[6];
  float* out = (float*)d_out;

  cudaFuncSetAttribute(hmma_gemm_kernel<0>,
                       cudaFuncAttributeMaxDynamicSharedMemorySize, GEMM_SMEM);
  cudaFuncSetAttribute(hmma_gemm_kernel<1>,
                       cudaFuncAttributeMaxDynamicSharedMemorySize, GEMM_SMEM);
  cudaFuncSetAttribute(attn_mma_kernel,
                       cudaFuncAttributeMaxDynamicSharedMemorySize, ATT_SMEM);

  __half *xh, *wq, *oh, *wp;
  cudaGetSymbolAddress((void**)&xh, g_xh);
  cudaGetSymbolAddress((void**)&wq, g_wqkv);
  cudaGetSymbolAddress((void**)&oh, g_oh);
  cudaGetSymbolAddress((void**)&wp, g_wproj);

  convh_kernel<<<8192 * 768 / 4 / 256, 256>>>(x, xh, 8192 * 768 / 4);
  convh_kernel<<<2304 * 768 / 4 / 256, 256>>>(qkv_w, wq, 2304 * 768 / 4);
  convh_kernel<<<768 * 768 / 4 / 256, 256>>>(proj_w, wp, 768 * 768 / 4);
  conv_rel_kernel<<<16, 256>>>(rph, rpw);
  hmma_gemm_kernel<0><<<dim3(18, 64), 256, GEMM_SMEM>>>(xh, wq, qkv_b,
                                                        nullptr);
  relbias_mma_kernel<<<dim3(32, 96), 128>>>();
  attn_mma_kernel<<<dim3(8, 96), 256, ATT_SMEM>>>();
  hmma_gemm_kernel<1><<<dim3(6, 64), 256, GEMM_SMEM>>>(oh, wp, proj_b, out);
}